// round 3
// baseline (speedup 1.0000x reference)
#include <cuda_runtime.h>
#include <cstdint>

#define NNODES 100000
#define NFEAT  512
#define NHID   256
#define NCLASS 40
#define NEDGE_MAX 3200000
#define SCAN_NB ((NNODES + 1023) / 1024)

// ------------- scratch (static device allocations; no runtime alloc) -------------
__device__ int   g_deg[NNODES];
__device__ int   g_off[NNODES + 1];
__device__ int   g_cur[NNODES];
__device__ int   g_csr[NEDGE_MAX];
__device__ float g_dis[NNODES];
__device__ int   g_part[SCAN_NB + 8];
__device__ int   g_is64;
__device__ __align__(16) float g_G1[(size_t)NNODES * NHID];   // dis[row] * (X @ W1)
__device__ __align__(16) float g_H1[(size_t)NNODES * NHID];   // relu(agg + b1)
__device__ __align__(16) float g_P [(size_t)NNODES * NCLASS]; // dis[row] * (H1 @ W2)

// --------------------------- edge dtype detection --------------------------------
// int64 edge data (values < 2^31): every odd 32-bit word is zero.
// int32 edge data: odd words are random node indices, virtually never all zero.
__global__ void k_detect(const unsigned* __restrict__ w, int E) {
    __shared__ int any;
    if (threadIdx.x == 0) any = 0;
    __syncthreads();
    int n = (E < 1024) ? E : 1024;
    for (int i = threadIdx.x; i < n; i += blockDim.x) {
        if (w[2 * i + 1] != 0u) any = 1;   // benign race
    }
    __syncthreads();
    if (threadIdx.x == 0) g_is64 = (any == 0) ? 1 : 0;
}

__device__ __forceinline__ int edge_at(const void* edge, int idx) {
    if (g_is64) return (int)((const long long*)edge)[idx];
    return ((const int*)edge)[idx];
}

// ------------------------------- CSR construction --------------------------------
__global__ void k_zero_deg() {
    int i = blockIdx.x * blockDim.x + threadIdx.x;
    if (i < NNODES) g_deg[i] = 0;
}

__global__ void k_hist(const void* __restrict__ edge, int E) {
    int e = blockIdx.x * blockDim.x + threadIdx.x;
    if (e < E) {
        int d = edge_at(edge, E + e);   // dst half
        if ((unsigned)d < (unsigned)NNODES) atomicAdd(&g_deg[d], 1);
    }
}

// block partial sums over 1024-element chunks
__global__ void k_scan1() {
    __shared__ int s[256];
    int b = blockIdx.x, t = threadIdx.x;
    int base = b * 1024;
    int sum = 0;
    #pragma unroll
    for (int i = t; i < 1024; i += 256) {
        int gi = base + i;
        sum += (gi < NNODES) ? g_deg[gi] : 0;
    }
    s[t] = sum; __syncthreads();
    for (int o = 128; o > 0; o >>= 1) {
        if (t < o) s[t] += s[t + o];
        __syncthreads();
    }
    if (t == 0) g_part[b] = s[0];
}

__global__ void k_scan2(int nb) {
    if (threadIdx.x == 0 && blockIdx.x == 0) {
        int run = 0;
        for (int i = 0; i < nb; i++) { int v = g_part[i]; g_part[i] = run; run += v; }
    }
}

__global__ void k_scan3() {
    __shared__ int s[1024];
    int b = blockIdx.x, t = threadIdx.x;
    int i = b * 1024 + t;
    int v = (i < NNODES) ? g_deg[i] : 0;
    s[t] = v; __syncthreads();
    for (int o = 1; o < 1024; o <<= 1) {
        int x = (t >= o) ? s[t - o] : 0;
        __syncthreads();
        s[t] += x;
        __syncthreads();
    }
    int excl = s[t] - v;
    int off = g_part[b] + excl;
    if (i < NNODES) {
        g_off[i] = off;
        g_cur[i] = off;
        g_dis[i] = rsqrtf((float)(v + 1));   // +1 self-loop
        if (i == NNODES - 1) g_off[NNODES] = off + v;
    }
}

__global__ void k_scatter(const void* __restrict__ edge, int E) {
    int e = blockIdx.x * blockDim.x + threadIdx.x;
    if (e < E) {
        int s = edge_at(edge, e);       // src half
        int d = edge_at(edge, E + e);   // dst half
        if ((unsigned)d < (unsigned)NNODES && (unsigned)s < (unsigned)NNODES) {
            int p = atomicAdd(&g_cur[d], 1);
            g_csr[p] = s;
        }
    }
}

// ------------------------- GEMM1: G1 = dis * (X @ W1) ----------------------------
// 64x64 tile, BK=16, 256 threads, 4x4 microtile
__global__ __launch_bounds__(256) void k_gemm1(const float* __restrict__ X,
                                               const float* __restrict__ W) {
    __shared__ float As[16][64];
    __shared__ float Bs[16][64];
    int t = threadIdx.x;
    int tx = t & 15, ty = t >> 4;
    int rowBase = blockIdx.x * 64;
    int colBase = blockIdx.y * 64;

    float acc[4][4];
    #pragma unroll
    for (int i = 0; i < 4; i++)
        #pragma unroll
        for (int j = 0; j < 4; j++) acc[i][j] = 0.f;

    int aRow = t >> 2;          // 0..63
    int aCol = (t & 3) << 2;    // 0,4,8,12
    int bRow = t >> 4;          // 0..15
    int bCol = (t & 15) << 2;   // 0..60
    int gRow = rowBase + aRow;
    bool aV = gRow < NNODES;
    const float* Xp = X + (size_t)(aV ? gRow : 0) * NFEAT + aCol;
    const float* Wp = W + (size_t)bRow * NHID + colBase + bCol;

    for (int k0 = 0; k0 < NFEAT; k0 += 16) {
        float4 av = aV ? *(const float4*)(Xp + k0) : make_float4(0.f, 0.f, 0.f, 0.f);
        float4 bv = *(const float4*)(Wp + (size_t)k0 * NHID);
        As[aCol + 0][aRow] = av.x;
        As[aCol + 1][aRow] = av.y;
        As[aCol + 2][aRow] = av.z;
        As[aCol + 3][aRow] = av.w;
        *(float4*)&Bs[bRow][bCol] = bv;
        __syncthreads();
        #pragma unroll
        for (int k = 0; k < 16; k++) {
            float4 a = *(const float4*)&As[k][ty << 2];
            float4 b = *(const float4*)&Bs[k][tx << 2];
            acc[0][0] += a.x * b.x; acc[0][1] += a.x * b.y; acc[0][2] += a.x * b.z; acc[0][3] += a.x * b.w;
            acc[1][0] += a.y * b.x; acc[1][1] += a.y * b.y; acc[1][2] += a.y * b.z; acc[1][3] += a.y * b.w;
            acc[2][0] += a.z * b.x; acc[2][1] += a.z * b.y; acc[2][2] += a.z * b.z; acc[2][3] += a.z * b.w;
            acc[3][0] += a.w * b.x; acc[3][1] += a.w * b.y; acc[3][2] += a.w * b.z; acc[3][3] += a.w * b.w;
        }
        __syncthreads();
    }
    #pragma unroll
    for (int i = 0; i < 4; i++) {
        int row = rowBase + (ty << 2) + i;
        if (row < NNODES) {
            float d = g_dis[row];
            float4 o = make_float4(acc[i][0] * d, acc[i][1] * d, acc[i][2] * d, acc[i][3] * d);
            *(float4*)&g_G1[(size_t)row * NHID + colBase + (tx << 2)] = o;
        }
    }
}

// --------------------- Aggregation 1: H1 = relu(dis*(sum)+b1) --------------------
__device__ __forceinline__ void f4add(float4& a, const float4& b) {
    a.x += b.x; a.y += b.y; a.z += b.z; a.w += b.w;
}

__global__ __launch_bounds__(256) void k_agg1(const float* __restrict__ b1) {
    int w = (blockIdx.x * blockDim.x + threadIdx.x) >> 5;
    int lane = threadIdx.x & 31;
    if (w >= NNODES) return;
    const float4* G = (const float4*)g_G1;
    const float4* self = G + (size_t)w * 64;
    float4 a0 = self[lane];
    float4 a1 = self[lane + 32];

    int beg = g_off[w], end = g_off[w + 1];
    int j = beg;
    for (; j + 4 <= end; j += 4) {
        int s0 = g_csr[j], s1 = g_csr[j + 1], s2 = g_csr[j + 2], s3 = g_csr[j + 3];
        const float4* r0 = G + (size_t)s0 * 64;
        const float4* r1 = G + (size_t)s1 * 64;
        const float4* r2 = G + (size_t)s2 * 64;
        const float4* r3 = G + (size_t)s3 * 64;
        float4 x0 = r0[lane], y0 = r0[lane + 32];
        float4 x1 = r1[lane], y1 = r1[lane + 32];
        float4 x2 = r2[lane], y2 = r2[lane + 32];
        float4 x3 = r3[lane], y3 = r3[lane + 32];
        f4add(a0, x0); f4add(a1, y0);
        f4add(a0, x1); f4add(a1, y1);
        f4add(a0, x2); f4add(a1, y2);
        f4add(a0, x3); f4add(a1, y3);
    }
    for (; j < end; ++j) {
        int s = g_csr[j];
        const float4* r = G + (size_t)s * 64;
        f4add(a0, r[lane]);
        f4add(a1, r[lane + 32]);
    }
    float d = g_dis[w];
    int c0 = lane << 2;
    float4 o0, o1;
    o0.x = fmaxf(fmaf(a0.x, d, b1[c0 + 0]), 0.f);
    o0.y = fmaxf(fmaf(a0.y, d, b1[c0 + 1]), 0.f);
    o0.z = fmaxf(fmaf(a0.z, d, b1[c0 + 2]), 0.f);
    o0.w = fmaxf(fmaf(a0.w, d, b1[c0 + 3]), 0.f);
    o1.x = fmaxf(fmaf(a1.x, d, b1[128 + c0 + 0]), 0.f);
    o1.y = fmaxf(fmaf(a1.y, d, b1[128 + c0 + 1]), 0.f);
    o1.z = fmaxf(fmaf(a1.z, d, b1[128 + c0 + 2]), 0.f);
    o1.w = fmaxf(fmaf(a1.w, d, b1[128 + c0 + 3]), 0.f);
    float4* H = (float4*)g_H1 + (size_t)w * 64;
    H[lane] = o0;
    H[lane + 32] = o1;
}

// ----------------------- GEMM2: P = dis * (H1 @ W2) ------------------------------
__global__ __launch_bounds__(256) void k_gemm2(const float* __restrict__ W2) {
    __shared__ float Xs[64][33];
    __shared__ float Ws[32][40];
    int t = threadIdx.x;
    int rBase = blockIdx.x * 64;
    int r2 = t >> 3;     // 0..31 -> rows r2, r2+32
    int cg = t & 7;      // 0..7 -> cols cg*5..cg*5+4
    float acc0[5] = {0.f, 0.f, 0.f, 0.f, 0.f};
    float acc1[5] = {0.f, 0.f, 0.f, 0.f, 0.f};

    for (int k0 = 0; k0 < NHID; k0 += 32) {
        for (int idx = t; idx < 64 * 32; idx += 256) {
            int rr = idx >> 5, kk = idx & 31;
            int row = rBase + rr;
            Xs[rr][kk] = (row < NNODES) ? g_H1[(size_t)row * NHID + k0 + kk] : 0.f;
        }
        for (int idx = t; idx < 32 * 40; idx += 256) {
            int kk = idx / 40, nn = idx - kk * 40;
            Ws[kk][nn] = W2[(size_t)(k0 + kk) * NCLASS + nn];
        }
        __syncthreads();
        #pragma unroll
        for (int k = 0; k < 32; k++) {
            float x0 = Xs[r2][k];
            float x1 = Xs[r2 + 32][k];
            #pragma unroll
            for (int i = 0; i < 5; i++) {
                float wv = Ws[k][cg * 5 + i];
                acc0[i] = fmaf(x0, wv, acc0[i]);
                acc1[i] = fmaf(x1, wv, acc1[i]);
            }
        }
        __syncthreads();
    }
    int row0 = rBase + r2, row1 = row0 + 32;
    if (row0 < NNODES) {
        float d = g_dis[row0];
        #pragma unroll
        for (int i = 0; i < 5; i++) g_P[(size_t)row0 * NCLASS + cg * 5 + i] = acc0[i] * d;
    }
    if (row1 < NNODES) {
        float d = g_dis[row1];
        #pragma unroll
        for (int i = 0; i < 5; i++) g_P[(size_t)row1 * NCLASS + cg * 5 + i] = acc1[i] * d;
    }
}

// ----------- Aggregation 2 + bias + log_softmax, fused, warp per node ------------
__global__ __launch_bounds__(256) void k_agg2(const float* __restrict__ b2,
                                              float* __restrict__ out) {
    int w = (blockIdx.x * blockDim.x + threadIdx.x) >> 5;
    int lane = threadIdx.x & 31;
    if (w >= NNODES) return;
    const float* self = g_P + (size_t)w * NCLASS;
    float aA = self[lane];
    float aB = (lane < 8) ? self[32 + lane] : 0.f;

    int beg = g_off[w], end = g_off[w + 1];
    int j = beg;
    for (; j + 4 <= end; j += 4) {
        int s0 = g_csr[j], s1 = g_csr[j + 1], s2 = g_csr[j + 2], s3 = g_csr[j + 3];
        const float* r0 = g_P + (size_t)s0 * NCLASS;
        const float* r1 = g_P + (size_t)s1 * NCLASS;
        const float* r2 = g_P + (size_t)s2 * NCLASS;
        const float* r3 = g_P + (size_t)s3 * NCLASS;
        float t0 = r0[lane], t1 = r1[lane], t2 = r2[lane], t3 = r3[lane];
        float u0 = 0.f, u1 = 0.f, u2 = 0.f, u3 = 0.f;
        if (lane < 8) {
            u0 = r0[32 + lane]; u1 = r1[32 + lane];
            u2 = r2[32 + lane]; u3 = r3[32 + lane];
        }
        aA += t0 + t1 + t2 + t3;
        aB += u0 + u1 + u2 + u3;
    }
    for (; j < end; ++j) {
        int s = g_csr[j];
        const float* r = g_P + (size_t)s * NCLASS;
        aA += r[lane];
        if (lane < 8) aB += r[32 + lane];
    }
    float d = g_dis[w];
    float vA = fmaf(aA, d, b2[lane]);
    float vB = (lane < 8) ? fmaf(aB, d, b2[32 + lane]) : -1e30f;

    float m = fmaxf(vA, vB);
    #pragma unroll
    for (int o = 16; o > 0; o >>= 1) m = fmaxf(m, __shfl_xor_sync(0xFFFFFFFFu, m, o));
    float e = expf(vA - m) + ((lane < 8) ? expf(vB - m) : 0.f);
    #pragma unroll
    for (int o = 16; o > 0; o >>= 1) e += __shfl_xor_sync(0xFFFFFFFFu, e, o);
    float lz = m + logf(e);

    float* o = out + (size_t)w * NCLASS;
    o[lane] = vA - lz;
    if (lane < 8) o[32 + lane] = vB - lz;
}

// ---------------------------------- launcher -------------------------------------
extern "C" void kernel_launch(void* const* d_in, const int* in_sizes, int n_in,
                              void* d_out, int out_size) {
    // Identify inputs by element count (robust to metadata ordering):
    //   x = 100000*512 = 51,200,000   W1 = 512*256 = 131,072   b1 = 256
    //   W2 = 256*40 = 10,240          b2 = 40                  edge = 2*3,200,000 = 6,400,000
    const float* x = nullptr;
    const float* W1 = nullptr;
    const float* b1 = nullptr;
    const float* W2 = nullptr;
    const float* b2 = nullptr;
    const void* edge = nullptr;
    int edgeElems = 0;
    for (int i = 0; i < n_in; i++) {
        int s = in_sizes[i];
        if      (s == 51200000) x  = (const float*)d_in[i];
        else if (s == 131072)   W1 = (const float*)d_in[i];
        else if (s == 256)      b1 = (const float*)d_in[i];
        else if (s == 10240)    W2 = (const float*)d_in[i];
        else if (s == 40)       b2 = (const float*)d_in[i];
        else if (s == 6400000) { edge = d_in[i]; edgeElems = s; }
    }
    // Positional fallback (setup_inputs dict order) if size matching failed
    if (!x || !W1 || !b1 || !W2 || !b2 || !edge) {
        x  = (const float*)d_in[0];
        W1 = (const float*)d_in[1];
        b1 = (const float*)d_in[2];
        W2 = (const float*)d_in[3];
        b2 = (const float*)d_in[4];
        edge = d_in[5];
        edgeElems = in_sizes[5];
    }
    float* out = (float*)d_out;

    int E = edgeElems / 2;
    if (E > NEDGE_MAX) E = NEDGE_MAX;

    // Edge dtype detection (int32 vs int64) + CSR + normalization
    k_detect<<<1, 256>>>((const unsigned*)edge, E);
    k_zero_deg<<<(NNODES + 255) / 256, 256>>>();
    k_hist<<<(E + 255) / 256, 256>>>(edge, E);
    k_scan1<<<SCAN_NB, 256>>>();
    k_scan2<<<1, 32>>>(SCAN_NB);
    k_scan3<<<SCAN_NB, 1024>>>();
    k_scatter<<<(E + 255) / 256, 256>>>(edge, E);

    // Layer 1
    dim3 g1((NNODES + 63) / 64, NHID / 64);
    k_gemm1<<<g1, 256>>>(x, W1);
    k_agg1<<<(NNODES * 32 + 255) / 256, 256>>>(b1);

    // Layer 2
    k_gemm2<<<(NNODES + 63) / 64, 256>>>(W2);
    k_agg2<<<(NNODES * 32 + 255) / 256, 256>>>(b2, out);
}

// round 5
// speedup vs baseline: 1.4085x; 1.4085x over previous
#include <cuda_runtime.h>
#include <cuda_bf16.h>
#include <cstdint>

#define NNODES 100000
#define NFEAT  512
#define NHID   256
#define NCLASS 40
#define NEDGE_MAX 3200000
#define SCAN_NB ((NNODES + 1023) / 1024)

// ------------- scratch (static device allocations; no runtime alloc) -------------
__device__ int   g_deg[NNODES];
__device__ int   g_off[NNODES + 1];
__device__ int   g_cur[NNODES];
__device__ int   g_csr[NEDGE_MAX];
__device__ float g_dis[NNODES];
__device__ int   g_part[SCAN_NB + 8];
__device__ int   g_is64;
__device__ __align__(16) float g_G1[(size_t)NNODES * NHID];   // dis[row] * (X @ W1)
__device__ __align__(16) float g_H1[(size_t)NNODES * NHID];   // relu(agg + b1)
__device__ __align__(16) float g_P [(size_t)NNODES * NCLASS]; // dis[row] * (H1 @ W2)
// split-bf16 operands for tensor-core GEMM1
__device__ __align__(16) __nv_bfloat16 g_XhiA[(size_t)NNODES * NFEAT];
__device__ __align__(16) __nv_bfloat16 g_XloA[(size_t)NNODES * NFEAT];
__device__ __align__(16) __nv_bfloat16 g_W1tH[(size_t)NHID * NFEAT];   // transposed [n][k]
__device__ __align__(16) __nv_bfloat16 g_W1tL[(size_t)NHID * NFEAT];

// --------------------------- edge dtype detection --------------------------------
__global__ void k_detect(const unsigned* __restrict__ w, int E) {
    __shared__ int any;
    if (threadIdx.x == 0) any = 0;
    __syncthreads();
    int n = (E < 1024) ? E : 1024;
    for (int i = threadIdx.x; i < n; i += blockDim.x)
        if (w[2 * i + 1] != 0u) any = 1;
    __syncthreads();
    if (threadIdx.x == 0) g_is64 = (any == 0) ? 1 : 0;
}

__device__ __forceinline__ int edge_at(const void* edge, int idx) {
    if (g_is64) return (int)((const long long*)edge)[idx];
    return ((const int*)edge)[idx];
}

// ------------------------------- CSR construction --------------------------------
__global__ void k_zero_deg() {
    int i = blockIdx.x * blockDim.x + threadIdx.x;
    if (i < NNODES) g_deg[i] = 0;
}

__global__ void k_hist(const void* __restrict__ edge, int E) {
    int e = blockIdx.x * blockDim.x + threadIdx.x;
    if (e < E) {
        int d = edge_at(edge, E + e);
        if ((unsigned)d < (unsigned)NNODES) atomicAdd(&g_deg[d], 1);
    }
}

__global__ void k_scan1() {
    __shared__ int s[256];
    int b = blockIdx.x, t = threadIdx.x;
    int base = b * 1024;
    int sum = 0;
    #pragma unroll
    for (int i = t; i < 1024; i += 256) {
        int gi = base + i;
        sum += (gi < NNODES) ? g_deg[gi] : 0;
    }
    s[t] = sum; __syncthreads();
    for (int o = 128; o > 0; o >>= 1) {
        if (t < o) s[t] += s[t + o];
        __syncthreads();
    }
    if (t == 0) g_part[b] = s[0];
}

__global__ void k_scan2(int nb) {
    if (threadIdx.x == 0 && blockIdx.x == 0) {
        int run = 0;
        for (int i = 0; i < nb; i++) { int v = g_part[i]; g_part[i] = run; run += v; }
    }
}

__global__ void k_scan3() {
    __shared__ int s[1024];
    int b = blockIdx.x, t = threadIdx.x;
    int i = b * 1024 + t;
    int v = (i < NNODES) ? g_deg[i] : 0;
    s[t] = v; __syncthreads();
    for (int o = 1; o < 1024; o <<= 1) {
        int x = (t >= o) ? s[t - o] : 0;
        __syncthreads();
        s[t] += x;
        __syncthreads();
    }
    int excl = s[t] - v;
    int off = g_part[b] + excl;
    if (i < NNODES) {
        g_off[i] = off;
        g_cur[i] = off;
        g_dis[i] = rsqrtf((float)(v + 1));
        if (i == NNODES - 1) g_off[NNODES] = off + v;
    }
}

__global__ void k_scatter(const void* __restrict__ edge, int E) {
    int e = blockIdx.x * blockDim.x + threadIdx.x;
    if (e < E) {
        int s = edge_at(edge, e);
        int d = edge_at(edge, E + e);
        if ((unsigned)d < (unsigned)NNODES && (unsigned)s < (unsigned)NNODES) {
            int p = atomicAdd(&g_cur[d], 1);
            g_csr[p] = s;
        }
    }
}

// ---------------------- split-bf16 conversions for GEMM1 --------------------------
__global__ void k_convX(const float* __restrict__ x) {
    size_t i = ((size_t)blockIdx.x * 256 + threadIdx.x) * 4;
    if (i >= (size_t)NNODES * NFEAT) return;
    float4 v = *(const float4*)(x + i);
    __nv_bfloat16 h0 = __float2bfloat16_rn(v.x);
    __nv_bfloat16 h1 = __float2bfloat16_rn(v.y);
    __nv_bfloat16 h2 = __float2bfloat16_rn(v.z);
    __nv_bfloat16 h3 = __float2bfloat16_rn(v.w);
    __nv_bfloat16 l0 = __float2bfloat16_rn(v.x - __bfloat162float(h0));
    __nv_bfloat16 l1 = __float2bfloat16_rn(v.y - __bfloat162float(h1));
    __nv_bfloat16 l2 = __float2bfloat16_rn(v.z - __bfloat162float(h2));
    __nv_bfloat16 l3 = __float2bfloat16_rn(v.w - __bfloat162float(h3));
    __nv_bfloat162* ph = (__nv_bfloat162*)(g_XhiA + i);
    __nv_bfloat162* pl = (__nv_bfloat162*)(g_XloA + i);
    ph[0] = __nv_bfloat162(h0, h1); ph[1] = __nv_bfloat162(h2, h3);
    pl[0] = __nv_bfloat162(l0, l1); pl[1] = __nv_bfloat162(l2, l3);
}

__global__ void k_convW1t(const float* __restrict__ W1) {
    int idx = blockIdx.x * 256 + threadIdx.x;
    if (idx < NFEAT * NHID) {
        int k = idx >> 8;      // / NHID
        int n = idx & 255;     // % NHID
        float v = W1[idx];
        __nv_bfloat16 h = __float2bfloat16_rn(v);
        g_W1tH[(size_t)n * NFEAT + k] = h;
        g_W1tL[(size_t)n * NFEAT + k] = __float2bfloat16_rn(v - __bfloat162float(h));
    }
}

// ---------------- GEMM1 (mma.sync bf16 split): G1 = dis * (X @ W1) ----------------
// CTA: 128(M) x 256(N), K chunked by 32. 512 threads = 16 warps (4x4),
// warp tile 32(M) x 64(N) = 2 x 8 m16n8k16 tiles.
// D = Ah@Bh + Ah@Bl + Al@Bh  (fp32 accum)
#define G1_PAD 40   // bf16 elems per smem row (32 data + 8 pad) -> 80B stride
#define G1_SMEM_BYTES ((128 * G1_PAD * 2 + 256 * G1_PAD * 2) * 2)

__device__ __forceinline__ void mma16816(float* c, const uint32_t* a,
                                         uint32_t b0, uint32_t b1) {
    asm volatile(
        "mma.sync.aligned.m16n8k16.row.col.f32.bf16.bf16.f32 "
        "{%0,%1,%2,%3}, {%4,%5,%6,%7}, {%8,%9}, {%0,%1,%2,%3};"
        : "+f"(c[0]), "+f"(c[1]), "+f"(c[2]), "+f"(c[3])
        : "r"(a[0]), "r"(a[1]), "r"(a[2]), "r"(a[3]), "r"(b0), "r"(b1));
}

__global__ __launch_bounds__(512) void k_gemm1_mma() {
    extern __shared__ __nv_bfloat16 sm[];
    __nv_bfloat16* Ah = sm;                      // [128][40]
    __nv_bfloat16* Al = Ah + 128 * G1_PAD;
    __nv_bfloat16* Bh = Al + 128 * G1_PAD;       // [256][40]
    __nv_bfloat16* Bl = Bh + 256 * G1_PAD;

    int tid = threadIdx.x;
    int wid = tid >> 5, lane = tid & 31;
    int wm = wid >> 2, wn = wid & 3;
    int mBase = wm * 32, nBase = wn * 64;
    int rowBase = blockIdx.x * 128;
    int g = lane >> 2, tg = lane & 3;

    float acc[2][8][4];
    #pragma unroll
    for (int i = 0; i < 2; i++)
        #pragma unroll
        for (int j = 0; j < 8; j++)
            #pragma unroll
            for (int r = 0; r < 4; r++) acc[i][j][r] = 0.f;

    // load indices
    int ar = tid >> 2, aseg = tid & 3;
    int gr = rowBase + ar; if (gr >= NNODES) gr = NNODES - 1;
    const __nv_bfloat16* gAh = g_XhiA + (size_t)gr * NFEAT + aseg * 8;
    const __nv_bfloat16* gAl = g_XloA + (size_t)gr * NFEAT + aseg * 8;

    for (int kc = 0; kc < NFEAT / 32; kc++) {
        // A: 128 rows x 32 k, one float4 (8 bf16) per thread per array
        *(float4*)(Ah + ar * G1_PAD + aseg * 8) = *(const float4*)(gAh + kc * 32);
        *(float4*)(Al + ar * G1_PAD + aseg * 8) = *(const float4*)(gAl + kc * 32);
        // B: 256 rows x 32 k, two float4 per thread per array
        #pragma unroll
        for (int b = 0; b < 2; b++) {
            int i = tid + b * 512;
            int n = i >> 2, bseg = i & 3;
            size_t bo = (size_t)n * NFEAT + kc * 32 + bseg * 8;
            *(float4*)(Bh + n * G1_PAD + bseg * 8) = *(const float4*)(g_W1tH + bo);
            *(float4*)(Bl + n * G1_PAD + bseg * 8) = *(const float4*)(g_W1tL + bo);
        }
        __syncthreads();

        #pragma unroll
        for (int ks = 0; ks < 2; ks++) {
            int k0 = ks * 16;
            uint32_t afh[2][4], afl[2][4];
            #pragma unroll
            for (int i = 0; i < 2; i++) {
                const __nv_bfloat16* bh = Ah + (mBase + i * 16 + g) * G1_PAD + k0;
                const __nv_bfloat16* bl = Al + (mBase + i * 16 + g) * G1_PAD + k0;
                afh[i][0] = *(const uint32_t*)(bh + 2 * tg);
                afh[i][1] = *(const uint32_t*)(bh + 8 * G1_PAD + 2 * tg);
                afh[i][2] = *(const uint32_t*)(bh + 2 * tg + 8);
                afh[i][3] = *(const uint32_t*)(bh + 8 * G1_PAD + 2 * tg + 8);
                afl[i][0] = *(const uint32_t*)(bl + 2 * tg);
                afl[i][1] = *(const uint32_t*)(bl + 8 * G1_PAD + 2 * tg);
                afl[i][2] = *(const uint32_t*)(bl + 2 * tg + 8);
                afl[i][3] = *(const uint32_t*)(bl + 8 * G1_PAD + 2 * tg + 8);
            }
            #pragma unroll
            for (int j = 0; j < 8; j++) {
                const __nv_bfloat16* pbh = Bh + (nBase + j * 8 + g) * G1_PAD + k0;
                const __nv_bfloat16* pbl = Bl + (nBase + j * 8 + g) * G1_PAD + k0;
                uint32_t bh0 = *(const uint32_t*)(pbh + 2 * tg);
                uint32_t bh1 = *(const uint32_t*)(pbh + 2 * tg + 8);
                uint32_t bl0 = *(const uint32_t*)(pbl + 2 * tg);
                uint32_t bl1 = *(const uint32_t*)(pbl + 2 * tg + 8);
                #pragma unroll
                for (int i = 0; i < 2; i++) {
                    mma16816(acc[i][j], afh[i], bh0, bh1);
                    mma16816(acc[i][j], afh[i], bl0, bl1);
                    mma16816(acc[i][j], afl[i], bh0, bh1);
                }
            }
        }
        __syncthreads();
    }

    // epilogue: scale by dis[row], store
    #pragma unroll
    for (int i = 0; i < 2; i++) {
        int r0 = rowBase + mBase + i * 16 + g;
        int r1 = r0 + 8;
        float d0 = (r0 < NNODES) ? g_dis[r0] : 0.f;
        float d1 = (r1 < NNODES) ? g_dis[r1] : 0.f;
        #pragma unroll
        for (int j = 0; j < 8; j++) {
            int col = nBase + j * 8 + 2 * tg;
            if (r0 < NNODES) {
                float2 v = make_float2(acc[i][j][0] * d0, acc[i][j][1] * d0);
                *(float2*)(g_G1 + (size_t)r0 * NHID + col) = v;
            }
            if (r1 < NNODES) {
                float2 v = make_float2(acc[i][j][2] * d1, acc[i][j][3] * d1);
                *(float2*)(g_G1 + (size_t)r1 * NHID + col) = v;
            }
        }
    }
}

// --------------------- Aggregation 1: H1 = relu(dis*(sum)+b1) --------------------
__device__ __forceinline__ void f4add(float4& a, const float4& b) {
    a.x += b.x; a.y += b.y; a.z += b.z; a.w += b.w;
}

__global__ __launch_bounds__(256) void k_agg1(const float* __restrict__ b1) {
    int w = (blockIdx.x * blockDim.x + threadIdx.x) >> 5;
    int lane = threadIdx.x & 31;
    if (w >= NNODES) return;
    const float4* G = (const float4*)g_G1;
    const float4* self = G + (size_t)w * 64;
    float4 a0 = self[lane];
    float4 a1 = self[lane + 32];

    int beg = g_off[w], end = g_off[w + 1];
    int j = beg;
    for (; j + 4 <= end; j += 4) {
        int s0 = g_csr[j], s1 = g_csr[j + 1], s2 = g_csr[j + 2], s3 = g_csr[j + 3];
        const float4* r0 = G + (size_t)s0 * 64;
        const float4* r1 = G + (size_t)s1 * 64;
        const float4* r2 = G + (size_t)s2 * 64;
        const float4* r3 = G + (size_t)s3 * 64;
        float4 x0 = r0[lane], y0 = r0[lane + 32];
        float4 x1 = r1[lane], y1 = r1[lane + 32];
        float4 x2 = r2[lane], y2 = r2[lane + 32];
        float4 x3 = r3[lane], y3 = r3[lane + 32];
        f4add(a0, x0); f4add(a1, y0);
        f4add(a0, x1); f4add(a1, y1);
        f4add(a0, x2); f4add(a1, y2);
        f4add(a0, x3); f4add(a1, y3);
    }
    for (; j < end; ++j) {
        int s = g_csr[j];
        const float4* r = G + (size_t)s * 64;
        f4add(a0, r[lane]);
        f4add(a1, r[lane + 32]);
    }
    float d = g_dis[w];
    int c0 = lane << 2;
    float4 o0, o1;
    o0.x = fmaxf(fmaf(a0.x, d, b1[c0 + 0]), 0.f);
    o0.y = fmaxf(fmaf(a0.y, d, b1[c0 + 1]), 0.f);
    o0.z = fmaxf(fmaf(a0.z, d, b1[c0 + 2]), 0.f);
    o0.w = fmaxf(fmaf(a0.w, d, b1[c0 + 3]), 0.f);
    o1.x = fmaxf(fmaf(a1.x, d, b1[128 + c0 + 0]), 0.f);
    o1.y = fmaxf(fmaf(a1.y, d, b1[128 + c0 + 1]), 0.f);
    o1.z = fmaxf(fmaf(a1.z, d, b1[128 + c0 + 2]), 0.f);
    o1.w = fmaxf(fmaf(a1.w, d, b1[128 + c0 + 3]), 0.f);
    float4* H = (float4*)g_H1 + (size_t)w * 64;
    H[lane] = o0;
    H[lane + 32] = o1;
}

// ----------------------- GEMM2: P = dis * (H1 @ W2) ------------------------------
__global__ __launch_bounds__(256) void k_gemm2(const float* __restrict__ W2) {
    __shared__ float Xs[64][33];
    __shared__ float Ws[32][40];
    int t = threadIdx.x;
    int rBase = blockIdx.x * 64;
    int r2 = t >> 3;
    int cg = t & 7;
    float acc0[5] = {0.f, 0.f, 0.f, 0.f, 0.f};
    float acc1[5] = {0.f, 0.f, 0.f, 0.f, 0.f};

    for (int k0 = 0; k0 < NHID; k0 += 32) {
        for (int idx = t; idx < 64 * 32; idx += 256) {
            int rr = idx >> 5, kk = idx & 31;
            int row = rBase + rr;
            Xs[rr][kk] = (row < NNODES) ? g_H1[(size_t)row * NHID + k0 + kk] : 0.f;
        }
        for (int idx = t; idx < 32 * 40; idx += 256) {
            int kk = idx / 40, nn = idx - kk * 40;
            Ws[kk][nn] = W2[(size_t)(k0 + kk) * NCLASS + nn];
        }
        __syncthreads();
        #pragma unroll
        for (int k = 0; k < 32; k++) {
            float x0 = Xs[r2][k];
            float x1 = Xs[r2 + 32][k];
            #pragma unroll
            for (int i = 0; i < 5; i++) {
                float wv = Ws[k][cg * 5 + i];
                acc0[i] = fmaf(x0, wv, acc0[i]);
                acc1[i] = fmaf(x1, wv, acc1[i]);
            }
        }
        __syncthreads();
    }
    int row0 = rBase + r2, row1 = row0 + 32;
    if (row0 < NNODES) {
        float d = g_dis[row0];
        #pragma unroll
        for (int i = 0; i < 5; i++) g_P[(size_t)row0 * NCLASS + cg * 5 + i] = acc0[i] * d;
    }
    if (row1 < NNODES) {
        float d = g_dis[row1];
        #pragma unroll
        for (int i = 0; i < 5; i++) g_P[(size_t)row1 * NCLASS + cg * 5 + i] = acc1[i] * d;
    }
}

// ----------- Aggregation 2 + bias + log_softmax, fused, warp per node ------------
__global__ __launch_bounds__(256) void k_agg2(const float* __restrict__ b2,
                                              float* __restrict__ out) {
    int w = (blockIdx.x * blockDim.x + threadIdx.x) >> 5;
    int lane = threadIdx.x & 31;
    if (w >= NNODES) return;
    const float* self = g_P + (size_t)w * NCLASS;
    float aA = self[lane];
    float aB = (lane < 8) ? self[32 + lane] : 0.f;

    int beg = g_off[w], end = g_off[w + 1];
    int j = beg;
    for (; j + 4 <= end; j += 4) {
        int s0 = g_csr[j], s1 = g_csr[j + 1], s2 = g_csr[j + 2], s3 = g_csr[j + 3];
        const float* r0 = g_P + (size_t)s0 * NCLASS;
        const float* r1 = g_P + (size_t)s1 * NCLASS;
        const float* r2 = g_P + (size_t)s2 * NCLASS;
        const float* r3 = g_P + (size_t)s3 * NCLASS;
        float t0 = r0[lane], t1 = r1[lane], t2 = r2[lane], t3 = r3[lane];
        float u0 = 0.f, u1 = 0.f, u2 = 0.f, u3 = 0.f;
        if (lane < 8) {
            u0 = r0[32 + lane]; u1 = r1[32 + lane];
            u2 = r2[32 + lane]; u3 = r3[32 + lane];
        }
        aA += t0 + t1 + t2 + t3;
        aB += u0 + u1 + u2 + u3;
    }
    for (; j < end; ++j) {
        int s = g_csr[j];
        const float* r = g_P + (size_t)s * NCLASS;
        aA += r[lane];
        if (lane < 8) aB += r[32 + lane];
    }
    float d = g_dis[w];
    float vA = fmaf(aA, d, b2[lane]);
    float vB = (lane < 8) ? fmaf(aB, d, b2[32 + lane]) : -1e30f;

    float m = fmaxf(vA, vB);
    #pragma unroll
    for (int o = 16; o > 0; o >>= 1) m = fmaxf(m, __shfl_xor_sync(0xFFFFFFFFu, m, o));
    float e = expf(vA - m) + ((lane < 8) ? expf(vB - m) : 0.f);
    #pragma unroll
    for (int o = 16; o > 0; o >>= 1) e += __shfl_xor_sync(0xFFFFFFFFu, e, o);
    float lz = m + logf(e);

    float* o = out + (size_t)w * NCLASS;
    o[lane] = vA - lz;
    if (lane < 8) o[32 + lane] = vB - lz;
}

// ---------------------------------- launcher -------------------------------------
extern "C" void kernel_launch(void* const* d_in, const int* in_sizes, int n_in,
                              void* d_out, int out_size) {
    const float* x = nullptr;
    const float* W1 = nullptr;
    const float* b1 = nullptr;
    const float* W2 = nullptr;
    const float* b2 = nullptr;
    const void* edge = nullptr;
    int edgeElems = 0;
    for (int i = 0; i < n_in; i++) {
        int s = in_sizes[i];
        if      (s == 51200000) x  = (const float*)d_in[i];
        else if (s == 131072)   W1 = (const float*)d_in[i];
        else if (s == 256)      b1 = (const float*)d_in[i];
        else if (s == 10240)    W2 = (const float*)d_in[i];
        else if (s == 40)       b2 = (const float*)d_in[i];
        else if (s == 6400000) { edge = d_in[i]; edgeElems = s; }
    }
    if (!x || !W1 || !b1 || !W2 || !b2 || !edge) {
        x  = (const float*)d_in[0];
        W1 = (const float*)d_in[1];
        b1 = (const float*)d_in[2];
        W2 = (const float*)d_in[3];
        b2 = (const float*)d_in[4];
        edge = d_in[5];
        edgeElems = in_sizes[5];
    }
    float* out = (float*)d_out;

    int E = edgeElems / 2;
    if (E > NEDGE_MAX) E = NEDGE_MAX;

    // edge dtype detection + CSR + norm
    k_detect<<<1, 256>>>((const unsigned*)edge, E);
    k_zero_deg<<<(NNODES + 255) / 256, 256>>>();
    k_hist<<<(E + 255) / 256, 256>>>(edge, E);
    k_scan1<<<SCAN_NB, 256>>>();
    k_scan2<<<1, 32>>>(SCAN_NB);
    k_scan3<<<SCAN_NB, 1024>>>();
    k_scatter<<<(E + 255) / 256, 256>>>(edge, E);

    // split-bf16 operand prep
    k_convX<<<(int)(((size_t)NNODES * NFEAT / 4 + 255) / 256), 256>>>(x);
    k_convW1t<<<(NFEAT * NHID + 255) / 256, 256>>>(W1);

    // Layer 1: HMMA GEMM + CSR aggregation
    static int smemSet = 0;
    if (!smemSet) {
        cudaFuncSetAttribute(k_gemm1_mma, cudaFuncAttributeMaxDynamicSharedMemorySize,
                             G1_SMEM_BYTES);
        smemSet = 1;
    }
    k_gemm1_mma<<<(NNODES + 127) / 128, 512, G1_SMEM_BYTES>>>();
    k_agg1<<<(NNODES * 32 + 255) / 256, 256>>>(b1);

    // Layer 2
    k_gemm2<<<(NNODES + 63) / 64, 256>>>(W2);
    k_agg2<<<(NNODES * 32 + 255) / 256, 256>>>(b2, out);
}

// round 6
// speedup vs baseline: 1.5956x; 1.1328x over previous
#include <cuda_runtime.h>
#include <cuda_bf16.h>
#include <cuda_fp16.h>
#include <cstdint>

#define NNODES 100000
#define NFEAT  512
#define NHID   256
#define NCLASS 40
#define NEDGE_MAX 3200000
#define SCAN_NB ((NNODES + 1023) / 1024)

// ------------- scratch (static device allocations; no runtime alloc) -------------
__device__ int   g_deg[NNODES];
__device__ int   g_off[NNODES + 1];
__device__ int   g_cur[NNODES];
__device__ int   g_csr[NEDGE_MAX];
__device__ float g_dis[NNODES];
__device__ int   g_part[SCAN_NB + 8];
__device__ int   g_is64;
__device__ __align__(16) __half g_G1h[(size_t)NNODES * NHID];  // fp16: dis[row]*(X@W1)
__device__ __align__(16) float g_H1[(size_t)NNODES * NHID];    // relu(agg + b1)
__device__ __align__(16) float g_P [(size_t)NNODES * NCLASS];  // dis[row] * (H1 @ W2)
// split-bf16 operands for tensor-core GEMM1
__device__ __align__(16) __nv_bfloat16 g_XhiA[(size_t)NNODES * NFEAT];
__device__ __align__(16) __nv_bfloat16 g_XloA[(size_t)NNODES * NFEAT];
__device__ __align__(16) __nv_bfloat16 g_W1tH[(size_t)NHID * NFEAT];   // transposed [n][k]
__device__ __align__(16) __nv_bfloat16 g_W1tL[(size_t)NHID * NFEAT];

// --------------------------- edge dtype detection --------------------------------
__global__ void k_detect(const unsigned* __restrict__ w, int E) {
    __shared__ int any;
    if (threadIdx.x == 0) any = 0;
    __syncthreads();
    int n = (E < 1024) ? E : 1024;
    for (int i = threadIdx.x; i < n; i += blockDim.x)
        if (w[2 * i + 1] != 0u) any = 1;
    __syncthreads();
    if (threadIdx.x == 0) g_is64 = (any == 0) ? 1 : 0;
}

__device__ __forceinline__ int edge_at(const void* edge, int idx) {
    if (g_is64) return (int)((const long long*)edge)[idx];
    return ((const int*)edge)[idx];
}

// ------------------------------- CSR construction --------------------------------
__global__ void k_zero_deg() {
    int i = blockIdx.x * blockDim.x + threadIdx.x;
    if (i < NNODES) g_deg[i] = 0;
}

__global__ void k_hist(const void* __restrict__ edge, int E) {
    int e = blockIdx.x * blockDim.x + threadIdx.x;
    if (e < E) {
        int d = edge_at(edge, E + e);
        if ((unsigned)d < (unsigned)NNODES) atomicAdd(&g_deg[d], 1);
    }
}

__global__ void k_scan1() {
    __shared__ int s[256];
    int b = blockIdx.x, t = threadIdx.x;
    int base = b * 1024;
    int sum = 0;
    #pragma unroll
    for (int i = t; i < 1024; i += 256) {
        int gi = base + i;
        sum += (gi < NNODES) ? g_deg[gi] : 0;
    }
    s[t] = sum; __syncthreads();
    for (int o = 128; o > 0; o >>= 1) {
        if (t < o) s[t] += s[t + o];
        __syncthreads();
    }
    if (t == 0) g_part[b] = s[0];
}

__global__ void k_scan2(int nb) {
    if (threadIdx.x == 0 && blockIdx.x == 0) {
        int run = 0;
        for (int i = 0; i < nb; i++) { int v = g_part[i]; g_part[i] = run; run += v; }
    }
}

__global__ void k_scan3() {
    __shared__ int s[1024];
    int b = blockIdx.x, t = threadIdx.x;
    int i = b * 1024 + t;
    int v = (i < NNODES) ? g_deg[i] : 0;
    s[t] = v; __syncthreads();
    for (int o = 1; o < 1024; o <<= 1) {
        int x = (t >= o) ? s[t - o] : 0;
        __syncthreads();
        s[t] += x;
        __syncthreads();
    }
    int excl = s[t] - v;
    int off = g_part[b] + excl;
    if (i < NNODES) {
        g_off[i] = off;
        g_cur[i] = off;
        g_dis[i] = rsqrtf((float)(v + 1));
        if (i == NNODES - 1) g_off[NNODES] = off + v;
    }
}

__global__ void k_scatter(const void* __restrict__ edge, int E) {
    int e = blockIdx.x * blockDim.x + threadIdx.x;
    if (e < E) {
        int s = edge_at(edge, e);
        int d = edge_at(edge, E + e);
        if ((unsigned)d < (unsigned)NNODES && (unsigned)s < (unsigned)NNODES) {
            int p = atomicAdd(&g_cur[d], 1);
            g_csr[p] = s;
        }
    }
}

// ---------------------- split-bf16 conversions for GEMM1 --------------------------
__global__ void k_convX(const float* __restrict__ x) {
    size_t i = ((size_t)blockIdx.x * 256 + threadIdx.x) * 4;
    if (i >= (size_t)NNODES * NFEAT) return;
    float4 v = *(const float4*)(x + i);
    __nv_bfloat16 h0 = __float2bfloat16_rn(v.x);
    __nv_bfloat16 h1 = __float2bfloat16_rn(v.y);
    __nv_bfloat16 h2 = __float2bfloat16_rn(v.z);
    __nv_bfloat16 h3 = __float2bfloat16_rn(v.w);
    __nv_bfloat16 l0 = __float2bfloat16_rn(v.x - __bfloat162float(h0));
    __nv_bfloat16 l1 = __float2bfloat16_rn(v.y - __bfloat162float(h1));
    __nv_bfloat16 l2 = __float2bfloat16_rn(v.z - __bfloat162float(h2));
    __nv_bfloat16 l3 = __float2bfloat16_rn(v.w - __bfloat162float(h3));
    __nv_bfloat162* ph = (__nv_bfloat162*)(g_XhiA + i);
    __nv_bfloat162* pl = (__nv_bfloat162*)(g_XloA + i);
    ph[0] = __nv_bfloat162(h0, h1); ph[1] = __nv_bfloat162(h2, h3);
    pl[0] = __nv_bfloat162(l0, l1); pl[1] = __nv_bfloat162(l2, l3);
}

__global__ void k_convW1t(const float* __restrict__ W1) {
    int idx = blockIdx.x * 256 + threadIdx.x;
    if (idx < NFEAT * NHID) {
        int k = idx >> 8;      // / NHID
        int n = idx & 255;     // % NHID
        float v = W1[idx];
        __nv_bfloat16 h = __float2bfloat16_rn(v);
        g_W1tH[(size_t)n * NFEAT + k] = h;
        g_W1tL[(size_t)n * NFEAT + k] = __float2bfloat16_rn(v - __bfloat162float(h));
    }
}

// ---------------- GEMM1 (mma.sync bf16 split): G1 = dis * (X @ W1) ----------------
#define G1_PAD 40   // bf16 elems per smem row (32 data + 8 pad) -> 80B stride
#define G1_SMEM_BYTES ((128 * G1_PAD * 2 + 256 * G1_PAD * 2) * 2)

__device__ __forceinline__ void mma16816(float* c, const uint32_t* a,
                                         uint32_t b0, uint32_t b1) {
    asm volatile(
        "mma.sync.aligned.m16n8k16.row.col.f32.bf16.bf16.f32 "
        "{%0,%1,%2,%3}, {%4,%5,%6,%7}, {%8,%9}, {%0,%1,%2,%3};"
        : "+f"(c[0]), "+f"(c[1]), "+f"(c[2]), "+f"(c[3])
        : "r"(a[0]), "r"(a[1]), "r"(a[2]), "r"(a[3]), "r"(b0), "r"(b1));
}

__global__ __launch_bounds__(512) void k_gemm1_mma() {
    extern __shared__ __nv_bfloat16 sm[];
    __nv_bfloat16* Ah = sm;                      // [128][40]
    __nv_bfloat16* Al = Ah + 128 * G1_PAD;
    __nv_bfloat16* Bh = Al + 128 * G1_PAD;       // [256][40]
    __nv_bfloat16* Bl = Bh + 256 * G1_PAD;

    int tid = threadIdx.x;
    int wid = tid >> 5, lane = tid & 31;
    int wm = wid >> 2, wn = wid & 3;
    int mBase = wm * 32, nBase = wn * 64;
    int rowBase = blockIdx.x * 128;
    int g = lane >> 2, tg = lane & 3;

    float acc[2][8][4];
    #pragma unroll
    for (int i = 0; i < 2; i++)
        #pragma unroll
        for (int j = 0; j < 8; j++)
            #pragma unroll
            for (int r = 0; r < 4; r++) acc[i][j][r] = 0.f;

    int ar = tid >> 2, aseg = tid & 3;
    int gr = rowBase + ar; if (gr >= NNODES) gr = NNODES - 1;
    const __nv_bfloat16* gAh = g_XhiA + (size_t)gr * NFEAT + aseg * 8;
    const __nv_bfloat16* gAl = g_XloA + (size_t)gr * NFEAT + aseg * 8;

    for (int kc = 0; kc < NFEAT / 32; kc++) {
        *(float4*)(Ah + ar * G1_PAD + aseg * 8) = *(const float4*)(gAh + kc * 32);
        *(float4*)(Al + ar * G1_PAD + aseg * 8) = *(const float4*)(gAl + kc * 32);
        #pragma unroll
        for (int b = 0; b < 2; b++) {
            int i = tid + b * 512;
            int n = i >> 2, bseg = i & 3;
            size_t bo = (size_t)n * NFEAT + kc * 32 + bseg * 8;
            *(float4*)(Bh + n * G1_PAD + bseg * 8) = *(const float4*)(g_W1tH + bo);
            *(float4*)(Bl + n * G1_PAD + bseg * 8) = *(const float4*)(g_W1tL + bo);
        }
        __syncthreads();

        #pragma unroll
        for (int ks = 0; ks < 2; ks++) {
            int k0 = ks * 16;
            uint32_t afh[2][4], afl[2][4];
            #pragma unroll
            for (int i = 0; i < 2; i++) {
                const __nv_bfloat16* bh = Ah + (mBase + i * 16 + g) * G1_PAD + k0;
                const __nv_bfloat16* bl = Al + (mBase + i * 16 + g) * G1_PAD + k0;
                afh[i][0] = *(const uint32_t*)(bh + 2 * tg);
                afh[i][1] = *(const uint32_t*)(bh + 8 * G1_PAD + 2 * tg);
                afh[i][2] = *(const uint32_t*)(bh + 2 * tg + 8);
                afh[i][3] = *(const uint32_t*)(bh + 8 * G1_PAD + 2 * tg + 8);
                afl[i][0] = *(const uint32_t*)(bl + 2 * tg);
                afl[i][1] = *(const uint32_t*)(bl + 8 * G1_PAD + 2 * tg);
                afl[i][2] = *(const uint32_t*)(bl + 2 * tg + 8);
                afl[i][3] = *(const uint32_t*)(bl + 8 * G1_PAD + 2 * tg + 8);
            }
            #pragma unroll
            for (int j = 0; j < 8; j++) {
                const __nv_bfloat16* pbh = Bh + (nBase + j * 8 + g) * G1_PAD + k0;
                const __nv_bfloat16* pbl = Bl + (nBase + j * 8 + g) * G1_PAD + k0;
                uint32_t bh0 = *(const uint32_t*)(pbh + 2 * tg);
                uint32_t bh1 = *(const uint32_t*)(pbh + 2 * tg + 8);
                uint32_t bl0 = *(const uint32_t*)(pbl + 2 * tg);
                uint32_t bl1 = *(const uint32_t*)(pbl + 2 * tg + 8);
                #pragma unroll
                for (int i = 0; i < 2; i++) {
                    mma16816(acc[i][j], afh[i], bh0, bh1);
                    mma16816(acc[i][j], afh[i], bl0, bl1);
                    mma16816(acc[i][j], afl[i], bh0, bh1);
                }
            }
        }
        __syncthreads();
    }

    // epilogue: scale by dis[row], store as fp16 (half2 per thread pair)
    #pragma unroll
    for (int i = 0; i < 2; i++) {
        int r0 = rowBase + mBase + i * 16 + g;
        int r1 = r0 + 8;
        float d0 = (r0 < NNODES) ? g_dis[r0] : 0.f;
        float d1 = (r1 < NNODES) ? g_dis[r1] : 0.f;
        #pragma unroll
        for (int j = 0; j < 8; j++) {
            int col = nBase + j * 8 + 2 * tg;
            if (r0 < NNODES) {
                __half2 v = __floats2half2_rn(acc[i][j][0] * d0, acc[i][j][1] * d0);
                *(__half2*)(g_G1h + (size_t)r0 * NHID + col) = v;
            }
            if (r1 < NNODES) {
                __half2 v = __floats2half2_rn(acc[i][j][2] * d1, acc[i][j][3] * d1);
                *(__half2*)(g_G1h + (size_t)r1 * NHID + col) = v;
            }
        }
    }
}

// --------------------- Aggregation 1: H1 = relu(dis*(sum)+b1) --------------------
// fp16 G1 rows: 256 halves = 32 float4 per row -> exactly 1 float4 per lane.
__device__ __forceinline__ void h8acc(float* a, float4 v) {
    const __half2* h = (const __half2*)&v;
    #pragma unroll
    for (int q = 0; q < 4; q++) {
        float2 f = __half22float2(h[q]);
        a[2 * q + 0] += f.x;
        a[2 * q + 1] += f.y;
    }
}

__global__ __launch_bounds__(256) void k_agg1(const float* __restrict__ b1) {
    int w = (blockIdx.x * blockDim.x + threadIdx.x) >> 5;
    int lane = threadIdx.x & 31;
    if (w >= NNODES) return;
    const float4* G = (const float4*)g_G1h;   // 32 float4 per row

    float a[8] = {0.f, 0.f, 0.f, 0.f, 0.f, 0.f, 0.f, 0.f};
    h8acc(a, G[(size_t)w * 32 + lane]);       // self

    int beg = g_off[w], end = g_off[w + 1];
    int j = beg;
    for (; j + 4 <= end; j += 4) {
        int s0 = g_csr[j], s1 = g_csr[j + 1], s2 = g_csr[j + 2], s3 = g_csr[j + 3];
        float4 v0 = G[(size_t)s0 * 32 + lane];
        float4 v1 = G[(size_t)s1 * 32 + lane];
        float4 v2 = G[(size_t)s2 * 32 + lane];
        float4 v3 = G[(size_t)s3 * 32 + lane];
        h8acc(a, v0); h8acc(a, v1); h8acc(a, v2); h8acc(a, v3);
    }
    for (; j < end; ++j)
        h8acc(a, G[(size_t)g_csr[j] * 32 + lane]);

    float d = g_dis[w];
    int c0 = lane << 3;
    float4 bb0 = *(const float4*)(b1 + c0);
    float4 bb1 = *(const float4*)(b1 + c0 + 4);
    float4 o0, o1;
    o0.x = fmaxf(fmaf(a[0], d, bb0.x), 0.f);
    o0.y = fmaxf(fmaf(a[1], d, bb0.y), 0.f);
    o0.z = fmaxf(fmaf(a[2], d, bb0.z), 0.f);
    o0.w = fmaxf(fmaf(a[3], d, bb0.w), 0.f);
    o1.x = fmaxf(fmaf(a[4], d, bb1.x), 0.f);
    o1.y = fmaxf(fmaf(a[5], d, bb1.y), 0.f);
    o1.z = fmaxf(fmaf(a[6], d, bb1.z), 0.f);
    o1.w = fmaxf(fmaf(a[7], d, bb1.w), 0.f);
    float* H = g_H1 + (size_t)w * NHID + c0;
    *(float4*)(H + 0) = o0;
    *(float4*)(H + 4) = o1;
}

// ----------------------- GEMM2: P = dis * (H1 @ W2) ------------------------------
__global__ __launch_bounds__(256) void k_gemm2(const float* __restrict__ W2) {
    __shared__ float Xs[64][33];
    __shared__ float Ws[32][40];
    int t = threadIdx.x;
    int rBase = blockIdx.x * 64;
    int r2 = t >> 3;
    int cg = t & 7;
    float acc0[5] = {0.f, 0.f, 0.f, 0.f, 0.f};
    float acc1[5] = {0.f, 0.f, 0.f, 0.f, 0.f};

    for (int k0 = 0; k0 < NHID; k0 += 32) {
        for (int idx = t; idx < 64 * 32; idx += 256) {
            int rr = idx >> 5, kk = idx & 31;
            int row = rBase + rr;
            Xs[rr][kk] = (row < NNODES) ? g_H1[(size_t)row * NHID + k0 + kk] : 0.f;
        }
        for (int idx = t; idx < 32 * 40; idx += 256) {
            int kk = idx / 40, nn = idx - kk * 40;
            Ws[kk][nn] = W2[(size_t)(k0 + kk) * NCLASS + nn];
        }
        __syncthreads();
        #pragma unroll
        for (int k = 0; k < 32; k++) {
            float x0 = Xs[r2][k];
            float x1 = Xs[r2 + 32][k];
            #pragma unroll
            for (int i = 0; i < 5; i++) {
                float wv = Ws[k][cg * 5 + i];
                acc0[i] = fmaf(x0, wv, acc0[i]);
                acc1[i] = fmaf(x1, wv, acc1[i]);
            }
        }
        __syncthreads();
    }
    int row0 = rBase + r2, row1 = row0 + 32;
    if (row0 < NNODES) {
        float d = g_dis[row0];
        #pragma unroll
        for (int i = 0; i < 5; i++) g_P[(size_t)row0 * NCLASS + cg * 5 + i] = acc0[i] * d;
    }
    if (row1 < NNODES) {
        float d = g_dis[row1];
        #pragma unroll
        for (int i = 0; i < 5; i++) g_P[(size_t)row1 * NCLASS + cg * 5 + i] = acc1[i] * d;
    }
}

// ----------- Aggregation 2 + bias + log_softmax, fused, warp per node ------------
__global__ __launch_bounds__(256) void k_agg2(const float* __restrict__ b2,
                                              float* __restrict__ out) {
    int w = (blockIdx.x * blockDim.x + threadIdx.x) >> 5;
    int lane = threadIdx.x & 31;
    if (w >= NNODES) return;
    const float* self = g_P + (size_t)w * NCLASS;
    float aA = self[lane];
    float aB = (lane < 8) ? self[32 + lane] : 0.f;

    int beg = g_off[w], end = g_off[w + 1];
    int j = beg;
    for (; j + 4 <= end; j += 4) {
        int s0 = g_csr[j], s1 = g_csr[j + 1], s2 = g_csr[j + 2], s3 = g_csr[j + 3];
        const float* r0 = g_P + (size_t)s0 * NCLASS;
        const float* r1 = g_P + (size_t)s1 * NCLASS;
        const float* r2 = g_P + (size_t)s2 * NCLASS;
        const float* r3 = g_P + (size_t)s3 * NCLASS;
        float t0 = r0[lane], t1 = r1[lane], t2 = r2[lane], t3 = r3[lane];
        float u0 = 0.f, u1 = 0.f, u2 = 0.f, u3 = 0.f;
        if (lane < 8) {
            u0 = r0[32 + lane]; u1 = r1[32 + lane];
            u2 = r2[32 + lane]; u3 = r3[32 + lane];
        }
        aA += t0 + t1 + t2 + t3;
        aB += u0 + u1 + u2 + u3;
    }
    for (; j < end; ++j) {
        int s = g_csr[j];
        const float* r = g_P + (size_t)s * NCLASS;
        aA += r[lane];
        if (lane < 8) aB += r[32 + lane];
    }
    float d = g_dis[w];
    float vA = fmaf(aA, d, b2[lane]);
    float vB = (lane < 8) ? fmaf(aB, d, b2[32 + lane]) : -1e30f;

    float m = fmaxf(vA, vB);
    #pragma unroll
    for (int o = 16; o > 0; o >>= 1) m = fmaxf(m, __shfl_xor_sync(0xFFFFFFFFu, m, o));
    float e = expf(vA - m) + ((lane < 8) ? expf(vB - m) : 0.f);
    #pragma unroll
    for (int o = 16; o > 0; o >>= 1) e += __shfl_xor_sync(0xFFFFFFFFu, e, o);
    float lz = m + logf(e);

    float* o = out + (size_t)w * NCLASS;
    o[lane] = vA - lz;
    if (lane < 8) o[32 + lane] = vB - lz;
}

// ---------------------------------- launcher -------------------------------------
extern "C" void kernel_launch(void* const* d_in, const int* in_sizes, int n_in,
                              void* d_out, int out_size) {
    const float* x = nullptr;
    const float* W1 = nullptr;
    const float* b1 = nullptr;
    const float* W2 = nullptr;
    const float* b2 = nullptr;
    const void* edge = nullptr;
    int edgeElems = 0;
    for (int i = 0; i < n_in; i++) {
        int s = in_sizes[i];
        if      (s == 51200000) x  = (const float*)d_in[i];
        else if (s == 131072)   W1 = (const float*)d_in[i];
        else if (s == 256)      b1 = (const float*)d_in[i];
        else if (s == 10240)    W2 = (const float*)d_in[i];
        else if (s == 40)       b2 = (const float*)d_in[i];
        else if (s == 6400000) { edge = d_in[i]; edgeElems = s; }
    }
    if (!x || !W1 || !b1 || !W2 || !b2 || !edge) {
        x  = (const float*)d_in[0];
        W1 = (const float*)d_in[1];
        b1 = (const float*)d_in[2];
        W2 = (const float*)d_in[3];
        b2 = (const float*)d_in[4];
        edge = d_in[5];
        edgeElems = in_sizes[5];
    }
    float* out = (float*)d_out;

    int E = edgeElems / 2;
    if (E > NEDGE_MAX) E = NEDGE_MAX;

    // edge dtype detection + CSR + norm
    k_detect<<<1, 256>>>((const unsigned*)edge, E);
    k_zero_deg<<<(NNODES + 255) / 256, 256>>>();
    k_hist<<<(E + 255) / 256, 256>>>(edge, E);
    k_scan1<<<SCAN_NB, 256>>>();
    k_scan2<<<1, 32>>>(SCAN_NB);
    k_scan3<<<SCAN_NB, 1024>>>();
    k_scatter<<<(E + 255) / 256, 256>>>(edge, E);

    // split-bf16 operand prep
    k_convX<<<(int)(((size_t)NNODES * NFEAT / 4 + 255) / 256), 256>>>(x);
    k_convW1t<<<(NFEAT * NHID + 255) / 256, 256>>>(W1);

    // Layer 1: HMMA GEMM + CSR aggregation
    static int smemSet = 0;
    if (!smemSet) {
        cudaFuncSetAttribute(k_gemm1_mma, cudaFuncAttributeMaxDynamicSharedMemorySize,
                             G1_SMEM_BYTES);
        smemSet = 1;
    }
    k_gemm1_mma<<<(NNODES + 127) / 128, 512, G1_SMEM_BYTES>>>();
    k_agg1<<<(NNODES * 32 + 255) / 256, 256>>>(b1);

    // Layer 2
    k_gemm2<<<(NNODES + 63) / 64, 256>>>(W2);
    k_agg2<<<(NNODES * 32 + 255) / 256, 256>>>(b2, out);
}

// round 7
// speedup vs baseline: 1.6609x; 1.0409x over previous
#include <cuda_runtime.h>
#include <cuda_bf16.h>
#include <cuda_fp16.h>
#include <cstdint>

#define NNODES 100000
#define NFEAT  512
#define NHID   256
#define NCLASS 40
#define NEDGE_MAX 3200000
#define SCAN_NB ((NNODES + 1023) / 1024)

// ------------- scratch (static device allocations; no runtime alloc) -------------
__device__ int   g_deg[NNODES];
__device__ int   g_off[NNODES + 1];
__device__ int   g_cur[NNODES];
__device__ int   g_csr[NEDGE_MAX];
__device__ float g_dis[NNODES];
__device__ int   g_part[SCAN_NB + 8];
__device__ int   g_is64;
__device__ __align__(16) __half g_G1h[(size_t)NNODES * NHID];  // fp16: dis[row]*(X@W1)
__device__ __align__(16) float g_H1[(size_t)NNODES * NHID];    // relu(agg + b1)
__device__ __align__(16) float g_P [(size_t)NNODES * NCLASS];  // dis[row] * (H1 @ W2)
// split-bf16 W1 (transposed) for tensor-core GEMM1
__device__ __align__(16) __nv_bfloat16 g_W1tH[(size_t)NHID * NFEAT];   // [n][k]
__device__ __align__(16) __nv_bfloat16 g_W1tL[(size_t)NHID * NFEAT];

// --------------------------- edge dtype detection --------------------------------
__global__ void k_detect(const unsigned* __restrict__ w, int E) {
    __shared__ int any;
    if (threadIdx.x == 0) any = 0;
    __syncthreads();
    int n = (E < 1024) ? E : 1024;
    for (int i = threadIdx.x; i < n; i += blockDim.x)
        if (w[2 * i + 1] != 0u) any = 1;
    __syncthreads();
    if (threadIdx.x == 0) g_is64 = (any == 0) ? 1 : 0;
}

__device__ __forceinline__ int edge_at(const void* edge, int idx) {
    if (g_is64) return (int)((const long long*)edge)[idx];
    return ((const int*)edge)[idx];
}

// ------------------------------- CSR construction --------------------------------
__global__ void k_zero_deg() {
    int i = blockIdx.x * blockDim.x + threadIdx.x;
    if (i < NNODES) g_deg[i] = 0;
}

__global__ void k_hist(const void* __restrict__ edge, int E) {
    int e = blockIdx.x * blockDim.x + threadIdx.x;
    if (e < E) {
        int d = edge_at(edge, E + e);
        if ((unsigned)d < (unsigned)NNODES) atomicAdd(&g_deg[d], 1);
    }
}

__global__ void k_scan1() {
    __shared__ int s[256];
    int b = blockIdx.x, t = threadIdx.x;
    int base = b * 1024;
    int sum = 0;
    #pragma unroll
    for (int i = t; i < 1024; i += 256) {
        int gi = base + i;
        sum += (gi < NNODES) ? g_deg[gi] : 0;
    }
    s[t] = sum; __syncthreads();
    for (int o = 128; o > 0; o >>= 1) {
        if (t < o) s[t] += s[t + o];
        __syncthreads();
    }
    if (t == 0) g_part[b] = s[0];
}

__global__ void k_scan2(int nb) {
    if (threadIdx.x == 0 && blockIdx.x == 0) {
        int run = 0;
        for (int i = 0; i < nb; i++) { int v = g_part[i]; g_part[i] = run; run += v; }
    }
}

__global__ void k_scan3() {
    __shared__ int s[1024];
    int b = blockIdx.x, t = threadIdx.x;
    int i = b * 1024 + t;
    int v = (i < NNODES) ? g_deg[i] : 0;
    s[t] = v; __syncthreads();
    for (int o = 1; o < 1024; o <<= 1) {
        int x = (t >= o) ? s[t - o] : 0;
        __syncthreads();
        s[t] += x;
        __syncthreads();
    }
    int excl = s[t] - v;
    int off = g_part[b] + excl;
    if (i < NNODES) {
        g_off[i] = off;
        g_cur[i] = off;
        g_dis[i] = rsqrtf((float)(v + 1));
        if (i == NNODES - 1) g_off[NNODES] = off + v;
    }
}

__global__ void k_scatter(const void* __restrict__ edge, int E) {
    int e = blockIdx.x * blockDim.x + threadIdx.x;
    if (e < E) {
        int s = edge_at(edge, e);
        int d = edge_at(edge, E + e);
        if ((unsigned)d < (unsigned)NNODES && (unsigned)s < (unsigned)NNODES) {
            int p = atomicAdd(&g_cur[d], 1);
            g_csr[p] = s;
        }
    }
}

// ---------------------- split-bf16 W1 conversion (transposed) ---------------------
__global__ void k_convW1t(const float* __restrict__ W1) {
    int idx = blockIdx.x * 256 + threadIdx.x;
    if (idx < NFEAT * NHID) {
        int k = idx >> 8;      // / NHID
        int n = idx & 255;     // % NHID
        float v = W1[idx];
        __nv_bfloat16 h = __float2bfloat16_rn(v);
        g_W1tH[(size_t)n * NFEAT + k] = h;
        g_W1tL[(size_t)n * NFEAT + k] = __float2bfloat16_rn(v - __bfloat162float(h));
    }
}

// ---------------- GEMM1 (mma.sync bf16 split): G1 = dis * (X @ W1) ----------------
// X converted to split-bf16 inline during the A-tile smem fill (X read exactly once).
#define G1_PAD 40   // bf16 elems per smem row (32 data + 8 pad) -> 80B stride
#define G1_SMEM_BYTES ((128 * G1_PAD * 2 + 256 * G1_PAD * 2) * 2)

__device__ __forceinline__ void mma16816(float* c, const uint32_t* a,
                                         uint32_t b0, uint32_t b1) {
    asm volatile(
        "mma.sync.aligned.m16n8k16.row.col.f32.bf16.bf16.f32 "
        "{%0,%1,%2,%3}, {%4,%5,%6,%7}, {%8,%9}, {%0,%1,%2,%3};"
        : "+f"(c[0]), "+f"(c[1]), "+f"(c[2]), "+f"(c[3])
        : "r"(a[0]), "r"(a[1]), "r"(a[2]), "r"(a[3]), "r"(b0), "r"(b1));
}

__global__ __launch_bounds__(512) void k_gemm1_mma(const float* __restrict__ X) {
    extern __shared__ __nv_bfloat16 sm[];
    __nv_bfloat16* Ah = sm;                      // [128][40]
    __nv_bfloat16* Al = Ah + 128 * G1_PAD;
    __nv_bfloat16* Bh = Al + 128 * G1_PAD;       // [256][40]
    __nv_bfloat16* Bl = Bh + 256 * G1_PAD;

    int tid = threadIdx.x;
    int wid = tid >> 5, lane = tid & 31;
    int wm = wid >> 2, wn = wid & 3;
    int mBase = wm * 32, nBase = wn * 64;
    int rowBase = blockIdx.x * 128;
    int g = lane >> 2, tg = lane & 3;

    float acc[2][8][4];
    #pragma unroll
    for (int i = 0; i < 2; i++)
        #pragma unroll
        for (int j = 0; j < 8; j++)
            #pragma unroll
            for (int r = 0; r < 4; r++) acc[i][j][r] = 0.f;

    int ar = tid >> 2, aseg = tid & 3;
    int gr = rowBase + ar; if (gr >= NNODES) gr = NNODES - 1;
    const float* gX = X + (size_t)gr * NFEAT + aseg * 8;

    for (int kc = 0; kc < NFEAT / 32; kc++) {
        // A: load 8 fp32, split to bf16 hi/lo inline
        {
            float4 v0 = *(const float4*)(gX + kc * 32);
            float4 v1 = *(const float4*)(gX + kc * 32 + 4);
            float f[8] = {v0.x, v0.y, v0.z, v0.w, v1.x, v1.y, v1.z, v1.w};
            __nv_bfloat162 hp[4], lp[4];
            #pragma unroll
            for (int q = 0; q < 4; q++) {
                __nv_bfloat16 h0 = __float2bfloat16_rn(f[2 * q]);
                __nv_bfloat16 h1 = __float2bfloat16_rn(f[2 * q + 1]);
                hp[q] = __nv_bfloat162(h0, h1);
                lp[q] = __nv_bfloat162(
                    __float2bfloat16_rn(f[2 * q] - __bfloat162float(h0)),
                    __float2bfloat16_rn(f[2 * q + 1] - __bfloat162float(h1)));
            }
            *(uint4*)(Ah + ar * G1_PAD + aseg * 8) = *(uint4*)hp;
            *(uint4*)(Al + ar * G1_PAD + aseg * 8) = *(uint4*)lp;
        }
        // B: 256 rows x 32 k, two float4 per thread per array
        #pragma unroll
        for (int b = 0; b < 2; b++) {
            int i = tid + b * 512;
            int n = i >> 2, bseg = i & 3;
            size_t bo = (size_t)n * NFEAT + kc * 32 + bseg * 8;
            *(float4*)(Bh + n * G1_PAD + bseg * 8) = *(const float4*)(g_W1tH + bo);
            *(float4*)(Bl + n * G1_PAD + bseg * 8) = *(const float4*)(g_W1tL + bo);
        }
        __syncthreads();

        #pragma unroll
        for (int ks = 0; ks < 2; ks++) {
            int k0 = ks * 16;
            uint32_t afh[2][4], afl[2][4];
            #pragma unroll
            for (int i = 0; i < 2; i++) {
                const __nv_bfloat16* bh = Ah + (mBase + i * 16 + g) * G1_PAD + k0;
                const __nv_bfloat16* bl = Al + (mBase + i * 16 + g) * G1_PAD + k0;
                afh[i][0] = *(const uint32_t*)(bh + 2 * tg);
                afh[i][1] = *(const uint32_t*)(bh + 8 * G1_PAD + 2 * tg);
                afh[i][2] = *(const uint32_t*)(bh + 2 * tg + 8);
                afh[i][3] = *(const uint32_t*)(bh + 8 * G1_PAD + 2 * tg + 8);
                afl[i][0] = *(const uint32_t*)(bl + 2 * tg);
                afl[i][1] = *(const uint32_t*)(bl + 8 * G1_PAD + 2 * tg);
                afl[i][2] = *(const uint32_t*)(bl + 2 * tg + 8);
                afl[i][3] = *(const uint32_t*)(bl + 8 * G1_PAD + 2 * tg + 8);
            }
            #pragma unroll
            for (int j = 0; j < 8; j++) {
                const __nv_bfloat16* pbh = Bh + (nBase + j * 8 + g) * G1_PAD + k0;
                const __nv_bfloat16* pbl = Bl + (nBase + j * 8 + g) * G1_PAD + k0;
                uint32_t bh0 = *(const uint32_t*)(pbh + 2 * tg);
                uint32_t bh1 = *(const uint32_t*)(pbh + 2 * tg + 8);
                uint32_t bl0 = *(const uint32_t*)(pbl + 2 * tg);
                uint32_t bl1 = *(const uint32_t*)(pbl + 2 * tg + 8);
                #pragma unroll
                for (int i = 0; i < 2; i++) {
                    mma16816(acc[i][j], afh[i], bh0, bh1);
                    mma16816(acc[i][j], afh[i], bl0, bl1);
                    mma16816(acc[i][j], afl[i], bh0, bh1);
                }
            }
        }
        __syncthreads();
    }

    // epilogue: scale by dis[row], store as fp16
    #pragma unroll
    for (int i = 0; i < 2; i++) {
        int r0 = rowBase + mBase + i * 16 + g;
        int r1 = r0 + 8;
        float d0 = (r0 < NNODES) ? g_dis[r0] : 0.f;
        float d1 = (r1 < NNODES) ? g_dis[r1] : 0.f;
        #pragma unroll
        for (int j = 0; j < 8; j++) {
            int col = nBase + j * 8 + 2 * tg;
            if (r0 < NNODES) {
                __half2 v = __floats2half2_rn(acc[i][j][0] * d0, acc[i][j][1] * d0);
                *(__half2*)(g_G1h + (size_t)r0 * NHID + col) = v;
            }
            if (r1 < NNODES) {
                __half2 v = __floats2half2_rn(acc[i][j][2] * d1, acc[i][j][3] * d1);
                *(__half2*)(g_G1h + (size_t)r1 * NHID + col) = v;
            }
        }
    }
}

// --------------------- Aggregation 1: H1 = relu(dis*(sum)+b1) --------------------
__device__ __forceinline__ void h8acc(float* a, float4 v) {
    const __half2* h = (const __half2*)&v;
    #pragma unroll
    for (int q = 0; q < 4; q++) {
        float2 f = __half22float2(h[q]);
        a[2 * q + 0] += f.x;
        a[2 * q + 1] += f.y;
    }
}

__global__ __launch_bounds__(256) void k_agg1(const float* __restrict__ b1) {
    int w = (blockIdx.x * blockDim.x + threadIdx.x) >> 5;
    int lane = threadIdx.x & 31;
    if (w >= NNODES) return;
    const float4* G = (const float4*)g_G1h;   // 32 float4 per row

    float a[8] = {0.f, 0.f, 0.f, 0.f, 0.f, 0.f, 0.f, 0.f};
    h8acc(a, G[(size_t)w * 32 + lane]);       // self

    int beg = g_off[w], end = g_off[w + 1];
    int j = beg;
    for (; j + 4 <= end; j += 4) {
        int s0 = g_csr[j], s1 = g_csr[j + 1], s2 = g_csr[j + 2], s3 = g_csr[j + 3];
        float4 v0 = G[(size_t)s0 * 32 + lane];
        float4 v1 = G[(size_t)s1 * 32 + lane];
        float4 v2 = G[(size_t)s2 * 32 + lane];
        float4 v3 = G[(size_t)s3 * 32 + lane];
        h8acc(a, v0); h8acc(a, v1); h8acc(a, v2); h8acc(a, v3);
    }
    for (; j < end; ++j)
        h8acc(a, G[(size_t)g_csr[j] * 32 + lane]);

    float d = g_dis[w];
    int c0 = lane << 3;
    float4 bb0 = *(const float4*)(b1 + c0);
    float4 bb1 = *(const float4*)(b1 + c0 + 4);
    float4 o0, o1;
    o0.x = fmaxf(fmaf(a[0], d, bb0.x), 0.f);
    o0.y = fmaxf(fmaf(a[1], d, bb0.y), 0.f);
    o0.z = fmaxf(fmaf(a[2], d, bb0.z), 0.f);
    o0.w = fmaxf(fmaf(a[3], d, bb0.w), 0.f);
    o1.x = fmaxf(fmaf(a[4], d, bb1.x), 0.f);
    o1.y = fmaxf(fmaf(a[5], d, bb1.y), 0.f);
    o1.z = fmaxf(fmaf(a[6], d, bb1.z), 0.f);
    o1.w = fmaxf(fmaf(a[7], d, bb1.w), 0.f);
    float* H = g_H1 + (size_t)w * NHID + c0;
    *(float4*)(H + 0) = o0;
    *(float4*)(H + 4) = o1;
}

// ----------------------- GEMM2: P = dis * (H1 @ W2) ------------------------------
__global__ __launch_bounds__(256) void k_gemm2(const float* __restrict__ W2) {
    __shared__ float Xs[64][33];
    __shared__ float Ws[32][40];
    int t = threadIdx.x;
    int rBase = blockIdx.x * 64;
    int r2 = t >> 3;
    int cg = t & 7;
    float acc0[5] = {0.f, 0.f, 0.f, 0.f, 0.f};
    float acc1[5] = {0.f, 0.f, 0.f, 0.f, 0.f};

    for (int k0 = 0; k0 < NHID; k0 += 32) {
        for (int idx = t; idx < 64 * 32; idx += 256) {
            int rr = idx >> 5, kk = idx & 31;
            int row = rBase + rr;
            Xs[rr][kk] = (row < NNODES) ? g_H1[(size_t)row * NHID + k0 + kk] : 0.f;
        }
        for (int idx = t; idx < 32 * 40; idx += 256) {
            int kk = idx / 40, nn = idx - kk * 40;
            Ws[kk][nn] = W2[(size_t)(k0 + kk) * NCLASS + nn];
        }
        __syncthreads();
        #pragma unroll
        for (int k = 0; k < 32; k++) {
            float x0 = Xs[r2][k];
            float x1 = Xs[r2 + 32][k];
            #pragma unroll
            for (int i = 0; i < 5; i++) {
                float wv = Ws[k][cg * 5 + i];
                acc0[i] = fmaf(x0, wv, acc0[i]);
                acc1[i] = fmaf(x1, wv, acc1[i]);
            }
        }
        __syncthreads();
    }
    int row0 = rBase + r2, row1 = row0 + 32;
    if (row0 < NNODES) {
        float d = g_dis[row0];
        #pragma unroll
        for (int i = 0; i < 5; i++) g_P[(size_t)row0 * NCLASS + cg * 5 + i] = acc0[i] * d;
    }
    if (row1 < NNODES) {
        float d = g_dis[row1];
        #pragma unroll
        for (int i = 0; i < 5; i++) g_P[(size_t)row1 * NCLASS + cg * 5 + i] = acc1[i] * d;
    }
}

// ----------- Aggregation 2 + bias + log_softmax, fused, warp per node ------------
// P rows are 40 floats = 10 float4; lanes 0-9 each own one float4 (4 classes).
__global__ __launch_bounds__(256) void k_agg2(const float* __restrict__ b2,
                                              float* __restrict__ out) {
    int w = (blockIdx.x * blockDim.x + threadIdx.x) >> 5;
    int lane = threadIdx.x & 31;
    if (w >= NNODES) return;
    const float4* Pv = (const float4*)g_P;   // 10 float4 per row
    bool act = lane < 10;
    int li = act ? lane : 0;

    float4 a = act ? Pv[(size_t)w * 10 + li] : make_float4(0.f, 0.f, 0.f, 0.f);

    int beg = g_off[w], end = g_off[w + 1];
    int j = beg;
    for (; j + 4 <= end; j += 4) {
        int s0 = g_csr[j], s1 = g_csr[j + 1], s2 = g_csr[j + 2], s3 = g_csr[j + 3];
        if (act) {
            float4 v0 = Pv[(size_t)s0 * 10 + li];
            float4 v1 = Pv[(size_t)s1 * 10 + li];
            float4 v2 = Pv[(size_t)s2 * 10 + li];
            float4 v3 = Pv[(size_t)s3 * 10 + li];
            a.x += v0.x + v1.x + v2.x + v3.x;
            a.y += v0.y + v1.y + v2.y + v3.y;
            a.z += v0.z + v1.z + v2.z + v3.z;
            a.w += v0.w + v1.w + v2.w + v3.w;
        }
    }
    for (; j < end; ++j) {
        if (act) {
            float4 v = Pv[(size_t)g_csr[j] * 10 + li];
            a.x += v.x; a.y += v.y; a.z += v.z; a.w += v.w;
        }
    }

    float d = g_dis[w];
    float v0 = -1e30f, v1 = -1e30f, v2 = -1e30f, v3 = -1e30f;
    if (act) {
        float4 bb = *(const float4*)(b2 + li * 4);
        v0 = fmaf(a.x, d, bb.x);
        v1 = fmaf(a.y, d, bb.y);
        v2 = fmaf(a.z, d, bb.z);
        v3 = fmaf(a.w, d, bb.w);
    }
    float m = fmaxf(fmaxf(v0, v1), fmaxf(v2, v3));
    #pragma unroll
    for (int o = 16; o > 0; o >>= 1) m = fmaxf(m, __shfl_xor_sync(0xFFFFFFFFu, m, o));
    float e = act ? (expf(v0 - m) + expf(v1 - m) + expf(v2 - m) + expf(v3 - m)) : 0.f;
    #pragma unroll
    for (int o = 16; o > 0; o >>= 1) e += __shfl_xor_sync(0xFFFFFFFFu, e, o);
    float lz = m + logf(e);

    if (act) {
        float4 o4 = make_float4(v0 - lz, v1 - lz, v2 - lz, v3 - lz);
        *(float4*)(out + (size_t)w * NCLASS + li * 4) = o4;
    }
}

// ---------------------------------- launcher -------------------------------------
extern "C" void kernel_launch(void* const* d_in, const int* in_sizes, int n_in,
                              void* d_out, int out_size) {
    const float* x = nullptr;
    const float* W1 = nullptr;
    const float* b1 = nullptr;
    const float* W2 = nullptr;
    const float* b2 = nullptr;
    const void* edge = nullptr;
    int edgeElems = 0;
    for (int i = 0; i < n_in; i++) {
        int s = in_sizes[i];
        if      (s == 51200000) x  = (const float*)d_in[i];
        else if (s == 131072)   W1 = (const float*)d_in[i];
        else if (s == 256)      b1 = (const float*)d_in[i];
        else if (s == 10240)    W2 = (const float*)d_in[i];
        else if (s == 40)       b2 = (const float*)d_in[i];
        else if (s == 6400000) { edge = d_in[i]; edgeElems = s; }
    }
    if (!x || !W1 || !b1 || !W2 || !b2 || !edge) {
        x  = (const float*)d_in[0];
        W1 = (const float*)d_in[1];
        b1 = (const float*)d_in[2];
        W2 = (const float*)d_in[3];
        b2 = (const float*)d_in[4];
        edge = d_in[5];
        edgeElems = in_sizes[5];
    }
    float* out = (float*)d_out;

    int E = edgeElems / 2;
    if (E > NEDGE_MAX) E = NEDGE_MAX;

    // edge dtype detection + CSR + norm
    k_detect<<<1, 256>>>((const unsigned*)edge, E);
    k_zero_deg<<<(NNODES + 255) / 256, 256>>>();
    k_hist<<<(E + 255) / 256, 256>>>(edge, E);
    k_scan1<<<SCAN_NB, 256>>>();
    k_scan2<<<1, 32>>>(SCAN_NB);
    k_scan3<<<SCAN_NB, 1024>>>();
    k_scatter<<<(E + 255) / 256, 256>>>(edge, E);

    // split-bf16 W1 prep (X converted inline in GEMM1)
    k_convW1t<<<(NFEAT * NHID + 255) / 256, 256>>>(W1);

    // Layer 1: HMMA GEMM (fused X conversion) + CSR aggregation
    static int smemSet = 0;
    if (!smemSet) {
        cudaFuncSetAttribute(k_gemm1_mma, cudaFuncAttributeMaxDynamicSharedMemorySize,
                             G1_SMEM_BYTES);
        smemSet = 1;
    }
    k_gemm1_mma<<<(NNODES + 127) / 128, 512, G1_SMEM_BYTES>>>(x);
    k_agg1<<<(NNODES * 32 + 255) / 256, 256>>>(b1);

    // Layer 2
    k_gemm2<<<(NNODES + 63) / 64, 256>>>(W2);
    k_agg2<<<(NNODES * 32 + 255) / 256, 256>>>(b2, out);
}

// round 8
// speedup vs baseline: 1.7470x; 1.0518x over previous
#include <cuda_runtime.h>
#include <cuda_bf16.h>
#include <cuda_fp16.h>
#include <cstdint>

#define NNODES 100000
#define NFEAT  512
#define NHID   256
#define NCLASS 40
#define NEDGE_MAX 3200000
#define SCAN_NB ((NNODES + 1023) / 1024)

// ------------- scratch (static device allocations; no runtime alloc) -------------
__device__ int   g_deg[NNODES];
__device__ int   g_off[NNODES + 1];
__device__ int   g_cur[NNODES];
__device__ int   g_csr[NEDGE_MAX];
__device__ float g_dis[NNODES];
__device__ int   g_part[SCAN_NB + 8];
__device__ int   g_is64;
__device__ __align__(16) __half g_G1h[(size_t)NNODES * NHID];  // fp16: dis[row]*(X@W1)
__device__ __align__(16) float g_H1[(size_t)NNODES * NHID];    // relu(agg + b1)
__device__ __align__(16) __half g_Ph[(size_t)NNODES * NCLASS]; // fp16: dis[row]*(H1@W2)
// split-bf16 weights (transposed [n][k])
__device__ __align__(16) __nv_bfloat16 g_W1tH[(size_t)NHID * NFEAT];
__device__ __align__(16) __nv_bfloat16 g_W1tL[(size_t)NHID * NFEAT];
__device__ __align__(16) __nv_bfloat16 g_W2tH[(size_t)NCLASS * NHID];
__device__ __align__(16) __nv_bfloat16 g_W2tL[(size_t)NCLASS * NHID];

// --------------------------- edge dtype detection --------------------------------
__global__ void k_detect(const unsigned* __restrict__ w, int E) {
    __shared__ int any;
    if (threadIdx.x == 0) any = 0;
    __syncthreads();
    int n = (E < 1024) ? E : 1024;
    for (int i = threadIdx.x; i < n; i += blockDim.x)
        if (w[2 * i + 1] != 0u) any = 1;
    __syncthreads();
    if (threadIdx.x == 0) g_is64 = (any == 0) ? 1 : 0;
}

__device__ __forceinline__ int edge_at(const void* edge, int idx) {
    if (g_is64) return (int)((const long long*)edge)[idx];
    return ((const int*)edge)[idx];
}

// ------------------------------- CSR construction --------------------------------
__global__ void k_zero_deg() {
    int i = blockIdx.x * blockDim.x + threadIdx.x;
    if (i < NNODES) g_deg[i] = 0;
}

__global__ void k_hist(const void* __restrict__ edge, int E) {
    int e = blockIdx.x * blockDim.x + threadIdx.x;
    if (e < E) {
        int d = edge_at(edge, E + e);
        if ((unsigned)d < (unsigned)NNODES) atomicAdd(&g_deg[d], 1);
    }
}

__global__ void k_scan1() {
    __shared__ int s[256];
    int b = blockIdx.x, t = threadIdx.x;
    int base = b * 1024;
    int sum = 0;
    #pragma unroll
    for (int i = t; i < 1024; i += 256) {
        int gi = base + i;
        sum += (gi < NNODES) ? g_deg[gi] : 0;
    }
    s[t] = sum; __syncthreads();
    for (int o = 128; o > 0; o >>= 1) {
        if (t < o) s[t] += s[t + o];
        __syncthreads();
    }
    if (t == 0) g_part[b] = s[0];
}

__global__ void k_scan2(int nb) {
    if (threadIdx.x == 0 && blockIdx.x == 0) {
        int run = 0;
        for (int i = 0; i < nb; i++) { int v = g_part[i]; g_part[i] = run; run += v; }
    }
}

__global__ void k_scan3() {
    __shared__ int s[1024];
    int b = blockIdx.x, t = threadIdx.x;
    int i = b * 1024 + t;
    int v = (i < NNODES) ? g_deg[i] : 0;
    s[t] = v; __syncthreads();
    for (int o = 1; o < 1024; o <<= 1) {
        int x = (t >= o) ? s[t - o] : 0;
        __syncthreads();
        s[t] += x;
        __syncthreads();
    }
    int excl = s[t] - v;
    int off = g_part[b] + excl;
    if (i < NNODES) {
        g_off[i] = off;
        g_cur[i] = off;
        g_dis[i] = rsqrtf((float)(v + 1));
        if (i == NNODES - 1) g_off[NNODES] = off + v;
    }
}

__global__ void k_scatter(const void* __restrict__ edge, int E) {
    int e = blockIdx.x * blockDim.x + threadIdx.x;
    if (e < E) {
        int s = edge_at(edge, e);
        int d = edge_at(edge, E + e);
        if ((unsigned)d < (unsigned)NNODES && (unsigned)s < (unsigned)NNODES) {
            int p = atomicAdd(&g_cur[d], 1);
            g_csr[p] = s;
        }
    }
}

// ---------------------- split-bf16 weight conversions -----------------------------
__global__ void k_convW1t(const float* __restrict__ W1) {
    int idx = blockIdx.x * 256 + threadIdx.x;
    if (idx < NFEAT * NHID) {
        int k = idx >> 8;      // / NHID
        int n = idx & 255;     // % NHID
        float v = W1[idx];
        __nv_bfloat16 h = __float2bfloat16_rn(v);
        g_W1tH[(size_t)n * NFEAT + k] = h;
        g_W1tL[(size_t)n * NFEAT + k] = __float2bfloat16_rn(v - __bfloat162float(h));
    }
}

__global__ void k_convW2t(const float* __restrict__ W2) {
    int idx = blockIdx.x * 256 + threadIdx.x;
    if (idx < NHID * NCLASS) {
        int k = idx / NCLASS;
        int n = idx - k * NCLASS;
        float v = W2[idx];
        __nv_bfloat16 h = __float2bfloat16_rn(v);
        g_W2tH[(size_t)n * NHID + k] = h;
        g_W2tL[(size_t)n * NHID + k] = __float2bfloat16_rn(v - __bfloat162float(h));
    }
}

// ---------------- GEMM1 (mma.sync bf16 split): G1 = dis * (X @ W1) ----------------
#define G1_PAD 40   // bf16 elems per smem row (32 data + 8 pad) -> 80B stride
#define G1_SMEM_BYTES ((128 * G1_PAD * 2 + 256 * G1_PAD * 2) * 2)

__device__ __forceinline__ void mma16816(float* c, const uint32_t* a,
                                         uint32_t b0, uint32_t b1) {
    asm volatile(
        "mma.sync.aligned.m16n8k16.row.col.f32.bf16.bf16.f32 "
        "{%0,%1,%2,%3}, {%4,%5,%6,%7}, {%8,%9}, {%0,%1,%2,%3};"
        : "+f"(c[0]), "+f"(c[1]), "+f"(c[2]), "+f"(c[3])
        : "r"(a[0]), "r"(a[1]), "r"(a[2]), "r"(a[3]), "r"(b0), "r"(b1));
}

__device__ __forceinline__ void splitpack(const float* f, __nv_bfloat162* hp,
                                          __nv_bfloat162* lp) {
    #pragma unroll
    for (int q = 0; q < 4; q++) {
        __nv_bfloat16 h0 = __float2bfloat16_rn(f[2 * q]);
        __nv_bfloat16 h1 = __float2bfloat16_rn(f[2 * q + 1]);
        hp[q] = __nv_bfloat162(h0, h1);
        lp[q] = __nv_bfloat162(
            __float2bfloat16_rn(f[2 * q] - __bfloat162float(h0)),
            __float2bfloat16_rn(f[2 * q + 1] - __bfloat162float(h1)));
    }
}

__global__ __launch_bounds__(512) void k_gemm1_mma(const float* __restrict__ X) {
    extern __shared__ __nv_bfloat16 sm[];
    __nv_bfloat16* Ah = sm;                      // [128][40]
    __nv_bfloat16* Al = Ah + 128 * G1_PAD;
    __nv_bfloat16* Bh = Al + 128 * G1_PAD;       // [256][40]
    __nv_bfloat16* Bl = Bh + 256 * G1_PAD;

    int tid = threadIdx.x;
    int wid = tid >> 5, lane = tid & 31;
    int wm = wid >> 2, wn = wid & 3;
    int mBase = wm * 32, nBase = wn * 64;
    int rowBase = blockIdx.x * 128;
    int g = lane >> 2, tg = lane & 3;

    float acc[2][8][4];
    #pragma unroll
    for (int i = 0; i < 2; i++)
        #pragma unroll
        for (int j = 0; j < 8; j++)
            #pragma unroll
            for (int r = 0; r < 4; r++) acc[i][j][r] = 0.f;

    int ar = tid >> 2, aseg = tid & 3;
    int gr = rowBase + ar; if (gr >= NNODES) gr = NNODES - 1;
    const float* gX = X + (size_t)gr * NFEAT + aseg * 8;

    // prefetch first A chunk (fp32)
    float4 pv0 = *(const float4*)(gX);
    float4 pv1 = *(const float4*)(gX + 4);

    for (int kc = 0; kc < NFEAT / 32; kc++) {
        // A: convert prefetched fp32 -> split bf16, store to smem
        {
            float f[8] = {pv0.x, pv0.y, pv0.z, pv0.w, pv1.x, pv1.y, pv1.z, pv1.w};
            __nv_bfloat162 hp[4], lp[4];
            splitpack(f, hp, lp);
            *(uint4*)(Ah + ar * G1_PAD + aseg * 8) = *(uint4*)hp;
            *(uint4*)(Al + ar * G1_PAD + aseg * 8) = *(uint4*)lp;
        }
        // B: 256 rows x 32 k, two float4 per thread per array (L2-resident)
        #pragma unroll
        for (int b = 0; b < 2; b++) {
            int i = tid + b * 512;
            int n = i >> 2, bseg = i & 3;
            size_t bo = (size_t)n * NFEAT + kc * 32 + bseg * 8;
            *(float4*)(Bh + n * G1_PAD + bseg * 8) = *(const float4*)(g_W1tH + bo);
            *(float4*)(Bl + n * G1_PAD + bseg * 8) = *(const float4*)(g_W1tL + bo);
        }
        __syncthreads();

        // prefetch next A chunk while computing
        if (kc + 1 < NFEAT / 32) {
            pv0 = *(const float4*)(gX + (kc + 1) * 32);
            pv1 = *(const float4*)(gX + (kc + 1) * 32 + 4);
        }

        #pragma unroll
        for (int ks = 0; ks < 2; ks++) {
            int k0 = ks * 16;
            uint32_t afh[2][4], afl[2][4];
            #pragma unroll
            for (int i = 0; i < 2; i++) {
                const __nv_bfloat16* bh = Ah + (mBase + i * 16 + g) * G1_PAD + k0;
                const __nv_bfloat16* bl = Al + (mBase + i * 16 + g) * G1_PAD + k0;
                afh[i][0] = *(const uint32_t*)(bh + 2 * tg);
                afh[i][1] = *(const uint32_t*)(bh + 8 * G1_PAD + 2 * tg);
                afh[i][2] = *(const uint32_t*)(bh + 2 * tg + 8);
                afh[i][3] = *(const uint32_t*)(bh + 8 * G1_PAD + 2 * tg + 8);
                afl[i][0] = *(const uint32_t*)(bl + 2 * tg);
                afl[i][1] = *(const uint32_t*)(bl + 8 * G1_PAD + 2 * tg);
                afl[i][2] = *(const uint32_t*)(bl + 2 * tg + 8);
                afl[i][3] = *(const uint32_t*)(bl + 8 * G1_PAD + 2 * tg + 8);
            }
            #pragma unroll
            for (int j = 0; j < 8; j++) {
                const __nv_bfloat16* pbh = Bh + (nBase + j * 8 + g) * G1_PAD + k0;
                const __nv_bfloat16* pbl = Bl + (nBase + j * 8 + g) * G1_PAD + k0;
                uint32_t bh0 = *(const uint32_t*)(pbh + 2 * tg);
                uint32_t bh1 = *(const uint32_t*)(pbh + 2 * tg + 8);
                uint32_t bl0 = *(const uint32_t*)(pbl + 2 * tg);
                uint32_t bl1 = *(const uint32_t*)(pbl + 2 * tg + 8);
                #pragma unroll
                for (int i = 0; i < 2; i++) {
                    mma16816(acc[i][j], afh[i], bh0, bh1);
                    mma16816(acc[i][j], afh[i], bl0, bl1);
                    mma16816(acc[i][j], afl[i], bh0, bh1);
                }
            }
        }
        __syncthreads();
    }

    // epilogue: scale by dis[row], store as fp16
    #pragma unroll
    for (int i = 0; i < 2; i++) {
        int r0 = rowBase + mBase + i * 16 + g;
        int r1 = r0 + 8;
        float d0 = (r0 < NNODES) ? g_dis[r0] : 0.f;
        float d1 = (r1 < NNODES) ? g_dis[r1] : 0.f;
        #pragma unroll
        for (int j = 0; j < 8; j++) {
            int col = nBase + j * 8 + 2 * tg;
            if (r0 < NNODES) {
                __half2 v = __floats2half2_rn(acc[i][j][0] * d0, acc[i][j][1] * d0);
                *(__half2*)(g_G1h + (size_t)r0 * NHID + col) = v;
            }
            if (r1 < NNODES) {
                __half2 v = __floats2half2_rn(acc[i][j][2] * d1, acc[i][j][3] * d1);
                *(__half2*)(g_G1h + (size_t)r1 * NHID + col) = v;
            }
        }
    }
}

// --------------------- Aggregation 1: H1 = relu(dis*(sum)+b1) --------------------
__device__ __forceinline__ void h8acc(float* a, float4 v) {
    const __half2* h = (const __half2*)&v;
    #pragma unroll
    for (int q = 0; q < 4; q++) {
        float2 f = __half22float2(h[q]);
        a[2 * q + 0] += f.x;
        a[2 * q + 1] += f.y;
    }
}

__global__ __launch_bounds__(256) void k_agg1(const float* __restrict__ b1) {
    int w = (blockIdx.x * blockDim.x + threadIdx.x) >> 5;
    int lane = threadIdx.x & 31;
    if (w >= NNODES) return;
    const float4* G = (const float4*)g_G1h;   // 32 float4 per row

    float a[8] = {0.f, 0.f, 0.f, 0.f, 0.f, 0.f, 0.f, 0.f};
    h8acc(a, G[(size_t)w * 32 + lane]);       // self

    int beg = g_off[w], end = g_off[w + 1];
    int j = beg;
    for (; j + 4 <= end; j += 4) {
        int s0 = g_csr[j], s1 = g_csr[j + 1], s2 = g_csr[j + 2], s3 = g_csr[j + 3];
        float4 v0 = G[(size_t)s0 * 32 + lane];
        float4 v1 = G[(size_t)s1 * 32 + lane];
        float4 v2 = G[(size_t)s2 * 32 + lane];
        float4 v3 = G[(size_t)s3 * 32 + lane];
        h8acc(a, v0); h8acc(a, v1); h8acc(a, v2); h8acc(a, v3);
    }
    for (; j < end; ++j)
        h8acc(a, G[(size_t)g_csr[j] * 32 + lane]);

    float d = g_dis[w];
    int c0 = lane << 3;
    float4 bb0 = *(const float4*)(b1 + c0);
    float4 bb1 = *(const float4*)(b1 + c0 + 4);
    float4 o0, o1;
    o0.x = fmaxf(fmaf(a[0], d, bb0.x), 0.f);
    o0.y = fmaxf(fmaf(a[1], d, bb0.y), 0.f);
    o0.z = fmaxf(fmaf(a[2], d, bb0.z), 0.f);
    o0.w = fmaxf(fmaf(a[3], d, bb0.w), 0.f);
    o1.x = fmaxf(fmaf(a[4], d, bb1.x), 0.f);
    o1.y = fmaxf(fmaf(a[5], d, bb1.y), 0.f);
    o1.z = fmaxf(fmaf(a[6], d, bb1.z), 0.f);
    o1.w = fmaxf(fmaf(a[7], d, bb1.w), 0.f);
    float* H = g_H1 + (size_t)w * NHID + c0;
    *(float4*)(H + 0) = o0;
    *(float4*)(H + 4) = o1;
}

// ------------- GEMM2 (mma.sync bf16 split): Ph = fp16(dis * (H1 @ W2)) -----------
// 256 threads = 8 warps; each warp: 16 rows x 40 cols, K=256.
// A (H1 fp32) loaded + split inline per fragment; B from L1-resident g_W2t.
__global__ __launch_bounds__(256) void k_gemm2_mma() {
    int tid = threadIdx.x;
    int wid = tid >> 5, lane = tid & 31;
    int g = lane >> 2, tg = lane & 3;
    int wBase = blockIdx.x * 128 + wid * 16;

    int r0 = wBase + g, r1 = r0 + 8;
    int cr0 = (r0 < NNODES) ? r0 : NNODES - 1;
    int cr1 = (r1 < NNODES) ? r1 : NNODES - 1;
    const float* A0 = g_H1 + (size_t)cr0 * NHID;
    const float* A1 = g_H1 + (size_t)cr1 * NHID;

    float acc[5][4];
    #pragma unroll
    for (int n = 0; n < 5; n++)
        #pragma unroll
        for (int r = 0; r < 4; r++) acc[n][r] = 0.f;

    for (int kc = 0; kc < NHID / 16; kc++) {
        int kk = kc * 16 + tg * 2;
        // A fragment: 8 fp32 -> split bf16 (row pattern of m16n8k16 A)
        float f[8];
        float2 t0 = *(const float2*)(A0 + kk);
        float2 t1 = *(const float2*)(A1 + kk);
        float2 t2 = *(const float2*)(A0 + kk + 8);
        float2 t3 = *(const float2*)(A1 + kk + 8);
        f[0] = t0.x; f[1] = t0.y; f[2] = t1.x; f[3] = t1.y;
        f[4] = t2.x; f[5] = t2.y; f[6] = t3.x; f[7] = t3.y;
        __nv_bfloat162 hp[4], lp[4];
        splitpack(f, hp, lp);
        uint32_t ah[4] = {*(uint32_t*)&hp[0], *(uint32_t*)&hp[1],
                          *(uint32_t*)&hp[2], *(uint32_t*)&hp[3]};
        uint32_t al[4] = {*(uint32_t*)&lp[0], *(uint32_t*)&lp[1],
                          *(uint32_t*)&lp[2], *(uint32_t*)&lp[3]};
        #pragma unroll
        for (int nt = 0; nt < 5; nt++) {
            const __nv_bfloat16* bh = g_W2tH + (size_t)(nt * 8 + g) * NHID + kc * 16;
            const __nv_bfloat16* bl = g_W2tL + (size_t)(nt * 8 + g) * NHID + kc * 16;
            uint32_t bh0 = *(const uint32_t*)(bh + 2 * tg);
            uint32_t bh1 = *(const uint32_t*)(bh + 2 * tg + 8);
            uint32_t bl0 = *(const uint32_t*)(bl + 2 * tg);
            uint32_t bl1 = *(const uint32_t*)(bl + 2 * tg + 8);
            mma16816(acc[nt], ah, bh0, bh1);
            mma16816(acc[nt], ah, bl0, bl1);
            mma16816(acc[nt], al, bh0, bh1);
        }
    }

    float d0 = (r0 < NNODES) ? g_dis[r0] : 0.f;
    float d1 = (r1 < NNODES) ? g_dis[r1] : 0.f;
    #pragma unroll
    for (int nt = 0; nt < 5; nt++) {
        int col = nt * 8 + 2 * tg;
        if (r0 < NNODES)
            *(__half2*)(g_Ph + (size_t)r0 * NCLASS + col) =
                __floats2half2_rn(acc[nt][0] * d0, acc[nt][1] * d0);
        if (r1 < NNODES)
            *(__half2*)(g_Ph + (size_t)r1 * NCLASS + col) =
                __floats2half2_rn(acc[nt][2] * d1, acc[nt][3] * d1);
    }
}

// ----------- Aggregation 2 + bias + log_softmax, fused, warp per node ------------
// fp16 P rows = 40 halves = 10 uint2; lanes 0-9 each own one uint2 (4 classes).
__global__ __launch_bounds__(256) void k_agg2(const float* __restrict__ b2,
                                              float* __restrict__ out) {
    int w = (blockIdx.x * blockDim.x + threadIdx.x) >> 5;
    int lane = threadIdx.x & 31;
    if (w >= NNODES) return;
    const uint2* Pv = (const uint2*)g_Ph;   // 10 uint2 per row
    bool act = lane < 10;
    int li = act ? lane : 0;

    float a0 = 0.f, a1 = 0.f, a2 = 0.f, a3 = 0.f;
    if (act) {
        uint2 v = Pv[(size_t)w * 10 + li];
        float2 x = __half22float2(*(__half2*)&v.x);
        float2 y = __half22float2(*(__half2*)&v.y);
        a0 = x.x; a1 = x.y; a2 = y.x; a3 = y.y;
    }

    int beg = g_off[w], end = g_off[w + 1];
    int j = beg;
    for (; j + 4 <= end; j += 4) {
        int s0 = g_csr[j], s1 = g_csr[j + 1], s2 = g_csr[j + 2], s3 = g_csr[j + 3];
        if (act) {
            uint2 u0 = Pv[(size_t)s0 * 10 + li];
            uint2 u1 = Pv[(size_t)s1 * 10 + li];
            uint2 u2 = Pv[(size_t)s2 * 10 + li];
            uint2 u3 = Pv[(size_t)s3 * 10 + li];
            #pragma unroll
            for (int q = 0; q < 4; q++) {
                uint2 u = (q == 0) ? u0 : (q == 1) ? u1 : (q == 2) ? u2 : u3;
                float2 x = __half22float2(*(__half2*)&u.x);
                float2 y = __half22float2(*(__half2*)&u.y);
                a0 += x.x; a1 += x.y; a2 += y.x; a3 += y.y;
            }
        }
    }
    for (; j < end; ++j) {
        if (act) {
            uint2 u = Pv[(size_t)g_csr[j] * 10 + li];
            float2 x = __half22float2(*(__half2*)&u.x);
            float2 y = __half22float2(*(__half2*)&u.y);
            a0 += x.x; a1 += x.y; a2 += y.x; a3 += y.y;
        }
    }

    float d = g_dis[w];
    float v0 = -1e30f, v1 = -1e30f, v2 = -1e30f, v3 = -1e30f;
    if (act) {
        float4 bb = *(const float4*)(b2 + li * 4);
        v0 = fmaf(a0, d, bb.x);
        v1 = fmaf(a1, d, bb.y);
        v2 = fmaf(a2, d, bb.z);
        v3 = fmaf(a3, d, bb.w);
    }
    float m = fmaxf(fmaxf(v0, v1), fmaxf(v2, v3));
    #pragma unroll
    for (int o = 16; o > 0; o >>= 1) m = fmaxf(m, __shfl_xor_sync(0xFFFFFFFFu, m, o));
    float e = act ? (expf(v0 - m) + expf(v1 - m) + expf(v2 - m) + expf(v3 - m)) : 0.f;
    #pragma unroll
    for (int o = 16; o > 0; o >>= 1) e += __shfl_xor_sync(0xFFFFFFFFu, e, o);
    float lz = m + logf(e);

    if (act) {
        float4 o4 = make_float4(v0 - lz, v1 - lz, v2 - lz, v3 - lz);
        *(float4*)(out + (size_t)w * NCLASS + li * 4) = o4;
    }
}

// ---------------------------------- launcher -------------------------------------
extern "C" void kernel_launch(void* const* d_in, const int* in_sizes, int n_in,
                              void* d_out, int out_size) {
    const float* x = nullptr;
    const float* W1 = nullptr;
    const float* b1 = nullptr;
    const float* W2 = nullptr;
    const float* b2 = nullptr;
    const void* edge = nullptr;
    int edgeElems = 0;
    for (int i = 0; i < n_in; i++) {
        int s = in_sizes[i];
        if      (s == 51200000) x  = (const float*)d_in[i];
        else if (s == 131072)   W1 = (const float*)d_in[i];
        else if (s == 256)      b1 = (const float*)d_in[i];
        else if (s == 10240)    W2 = (const float*)d_in[i];
        else if (s == 40)       b2 = (const float*)d_in[i];
        else if (s == 6400000) { edge = d_in[i]; edgeElems = s; }
    }
    if (!x || !W1 || !b1 || !W2 || !b2 || !edge) {
        x  = (const float*)d_in[0];
        W1 = (const float*)d_in[1];
        b1 = (const float*)d_in[2];
        W2 = (const float*)d_in[3];
        b2 = (const float*)d_in[4];
        edge = d_in[5];
        edgeElems = in_sizes[5];
    }
    float* out = (float*)d_out;

    int E = edgeElems / 2;
    if (E > NEDGE_MAX) E = NEDGE_MAX;

    // edge dtype detection + CSR + norm
    k_detect<<<1, 256>>>((const unsigned*)edge, E);
    k_zero_deg<<<(NNODES + 255) / 256, 256>>>();
    k_hist<<<(E + 255) / 256, 256>>>(edge, E);
    k_scan1<<<SCAN_NB, 256>>>();
    k_scan2<<<1, 32>>>(SCAN_NB);
    k_scan3<<<SCAN_NB, 1024>>>();
    k_scatter<<<(E + 255) / 256, 256>>>(edge, E);

    // split-bf16 weight prep
    k_convW1t<<<(NFEAT * NHID + 255) / 256, 256>>>(W1);
    k_convW2t<<<(NHID * NCLASS + 255) / 256, 256>>>(W2);

    // Layer 1: HMMA GEMM (fused X conversion, A-prefetch) + CSR aggregation
    static int smemSet = 0;
    if (!smemSet) {
        cudaFuncSetAttribute(k_gemm1_mma, cudaFuncAttributeMaxDynamicSharedMemorySize,
                             G1_SMEM_BYTES);
        smemSet = 1;
    }
    k_gemm1_mma<<<(NNODES + 127) / 128, 512, G1_SMEM_BYTES>>>(x);
    k_agg1<<<(NNODES * 32 + 255) / 256, 256>>>(b1);

    // Layer 2: HMMA GEMM + fused aggregation/log-softmax
    k_gemm2_mma<<<(NNODES + 127) / 128, 256>>>();
    k_agg2<<<(NNODES * 32 + 255) / 256, 256>>>(b2, out);
}

// round 9
// speedup vs baseline: 1.8142x; 1.0385x over previous
#include <cuda_runtime.h>
#include <cuda_bf16.h>
#include <cuda_fp16.h>
#include <cstdint>

#define NNODES 100000
#define NFEAT  512
#define NHID   256
#define NCLASS 40
#define NEDGE_MAX 3200000
#define SCAN_NB ((NNODES + 1023) / 1024)

// ------------- scratch (static device allocations; no runtime alloc) -------------
__device__ int   g_deg[NNODES];
__device__ int   g_off[NNODES + 1];
__device__ int   g_cur[NNODES];
__device__ int   g_csr[NEDGE_MAX];
__device__ float g_dis[NNODES];
__device__ float g_disB[NNODES];      // copy computed on stream B (avoids cross-stream dep)
__device__ int   g_part[SCAN_NB + 8];
__device__ int   g_is64;
__device__ __align__(16) __half g_G1h[(size_t)NNODES * NHID];  // fp16: dis[row]*(X@W1)
__device__ __align__(16) float g_H1[(size_t)NNODES * NHID];    // relu(agg + b1)
__device__ __align__(16) __half g_Ph[(size_t)NNODES * NCLASS]; // fp16: dis[row]*(H1@W2)
// split-bf16 weights (transposed [n][k])
__device__ __align__(16) __nv_bfloat16 g_W1tH[(size_t)NHID * NFEAT];
__device__ __align__(16) __nv_bfloat16 g_W1tL[(size_t)NHID * NFEAT];
__device__ __align__(16) __nv_bfloat16 g_W2tH[(size_t)NCLASS * NHID];
__device__ __align__(16) __nv_bfloat16 g_W2tL[(size_t)NCLASS * NHID];

// --------------------------- edge dtype detection --------------------------------
__global__ void k_detect(const unsigned* __restrict__ w, int E) {
    __shared__ int any;
    if (threadIdx.x == 0) any = 0;
    __syncthreads();
    int n = (E < 1024) ? E : 1024;
    for (int i = threadIdx.x; i < n; i += blockDim.x)
        if (w[2 * i + 1] != 0u) any = 1;
    __syncthreads();
    if (threadIdx.x == 0) g_is64 = (any == 0) ? 1 : 0;
}

__device__ __forceinline__ int edge_at(const void* edge, int idx) {
    if (g_is64) return (int)((const long long*)edge)[idx];
    return ((const int*)edge)[idx];
}

// ----------------- degree computation on stream B (for GEMM1 epilogue) ------------
// GEMM1 needs dis[] but runs on stream B concurrently with the CSR chain on stream A.
// Recompute degrees independently into g_disB to keep the streams fully decoupled.
__global__ void k_degB(const void* __restrict__ edge, int E) {
    int i = blockIdx.x * blockDim.x + threadIdx.x;
    if (i < NNODES) ((int*)g_disB)[i] = 0;   // reuse as int accumulator first
}
__global__ void k_histB(const void* __restrict__ edge, int E) {
    int e = blockIdx.x * blockDim.x + threadIdx.x;
    if (e < E) {
        int d = edge_at(edge, E + e);
        if ((unsigned)d < (unsigned)NNODES) atomicAdd(&((int*)g_disB)[d], 1);
    }
}
__global__ void k_finB() {
    int i = blockIdx.x * blockDim.x + threadIdx.x;
    if (i < NNODES) {
        int v = ((int*)g_disB)[i];
        g_disB[i] = rsqrtf((float)(v + 1));
    }
}

// ------------------------------- CSR construction (stream A) ----------------------
__global__ void k_zero_deg() {
    int i = blockIdx.x * blockDim.x + threadIdx.x;
    if (i < NNODES) g_deg[i] = 0;
}

__global__ void k_hist(const void* __restrict__ edge, int E) {
    int e = blockIdx.x * blockDim.x + threadIdx.x;
    if (e < E) {
        int d = edge_at(edge, E + e);
        if ((unsigned)d < (unsigned)NNODES) atomicAdd(&g_deg[d], 1);
    }
}

__global__ void k_scan1() {
    __shared__ int s[256];
    int b = blockIdx.x, t = threadIdx.x;
    int base = b * 1024;
    int sum = 0;
    #pragma unroll
    for (int i = t; i < 1024; i += 256) {
        int gi = base + i;
        sum += (gi < NNODES) ? g_deg[gi] : 0;
    }
    s[t] = sum; __syncthreads();
    for (int o = 128; o > 0; o >>= 1) {
        if (t < o) s[t] += s[t + o];
        __syncthreads();
    }
    if (t == 0) g_part[b] = s[0];
}

// parallel exclusive scan over SCAN_NB (=98) partials, one 128-thread block
__global__ void k_scan2(int nb) {
    __shared__ int s[128];
    int t = threadIdx.x;
    int v = (t < nb) ? g_part[t] : 0;
    s[t] = v; __syncthreads();
    #pragma unroll
    for (int o = 1; o < 128; o <<= 1) {
        int x = (t >= o) ? s[t - o] : 0;
        __syncthreads();
        s[t] += x;
        __syncthreads();
    }
    if (t < nb) g_part[t] = s[t] - v;
}

__global__ void k_scan3() {
    __shared__ int s[1024];
    int b = blockIdx.x, t = threadIdx.x;
    int i = b * 1024 + t;
    int v = (i < NNODES) ? g_deg[i] : 0;
    s[t] = v; __syncthreads();
    for (int o = 1; o < 1024; o <<= 1) {
        int x = (t >= o) ? s[t - o] : 0;
        __syncthreads();
        s[t] += x;
        __syncthreads();
    }
    int excl = s[t] - v;
    int off = g_part[b] + excl;
    if (i < NNODES) {
        g_off[i] = off;
        g_cur[i] = off;
        g_dis[i] = rsqrtf((float)(v + 1));
        if (i == NNODES - 1) g_off[NNODES] = off + v;
    }
}

__global__ void k_scatter(const void* __restrict__ edge, int E) {
    int e = blockIdx.x * blockDim.x + threadIdx.x;
    if (e < E) {
        int s = edge_at(edge, e);
        int d = edge_at(edge, E + e);
        if ((unsigned)d < (unsigned)NNODES && (unsigned)s < (unsigned)NNODES) {
            int p = atomicAdd(&g_cur[d], 1);
            g_csr[p] = s;
        }
    }
}

// ---------------------- split-bf16 weight conversions -----------------------------
__global__ void k_convW1t(const float* __restrict__ W1) {
    int idx = blockIdx.x * 256 + threadIdx.x;
    if (idx < NFEAT * NHID) {
        int k = idx >> 8;      // / NHID
        int n = idx & 255;     // % NHID
        float v = W1[idx];
        __nv_bfloat16 h = __float2bfloat16_rn(v);
        g_W1tH[(size_t)n * NFEAT + k] = h;
        g_W1tL[(size_t)n * NFEAT + k] = __float2bfloat16_rn(v - __bfloat162float(h));
    }
}

__global__ void k_convW2t(const float* __restrict__ W2) {
    int idx = blockIdx.x * 256 + threadIdx.x;
    if (idx < NHID * NCLASS) {
        int k = idx / NCLASS;
        int n = idx - k * NCLASS;
        float v = W2[idx];
        __nv_bfloat16 h = __float2bfloat16_rn(v);
        g_W2tH[(size_t)n * NHID + k] = h;
        g_W2tL[(size_t)n * NHID + k] = __float2bfloat16_rn(v - __bfloat162float(h));
    }
}

// ---------------- GEMM1 (mma.sync bf16 split): G1 = disB * (X @ W1) ---------------
#define G1_PAD 40   // bf16 elems per smem row (32 data + 8 pad) -> 80B stride
#define G1_SMEM_BYTES ((128 * G1_PAD * 2 + 256 * G1_PAD * 2) * 2)

__device__ __forceinline__ void mma16816(float* c, const uint32_t* a,
                                         uint32_t b0, uint32_t b1) {
    asm volatile(
        "mma.sync.aligned.m16n8k16.row.col.f32.bf16.bf16.f32 "
        "{%0,%1,%2,%3}, {%4,%5,%6,%7}, {%8,%9}, {%0,%1,%2,%3};"
        : "+f"(c[0]), "+f"(c[1]), "+f"(c[2]), "+f"(c[3])
        : "r"(a[0]), "r"(a[1]), "r"(a[2]), "r"(a[3]), "r"(b0), "r"(b1));
}

__device__ __forceinline__ void splitpack(const float* f, __nv_bfloat162* hp,
                                          __nv_bfloat162* lp) {
    #pragma unroll
    for (int q = 0; q < 4; q++) {
        __nv_bfloat16 h0 = __float2bfloat16_rn(f[2 * q]);
        __nv_bfloat16 h1 = __float2bfloat16_rn(f[2 * q + 1]);
        hp[q] = __nv_bfloat162(h0, h1);
        lp[q] = __nv_bfloat162(
            __float2bfloat16_rn(f[2 * q] - __bfloat162float(h0)),
            __float2bfloat16_rn(f[2 * q + 1] - __bfloat162float(h1)));
    }
}

__global__ __launch_bounds__(512) void k_gemm1_mma(const float* __restrict__ X) {
    extern __shared__ __nv_bfloat16 sm[];
    __nv_bfloat16* Ah = sm;                      // [128][40]
    __nv_bfloat16* Al = Ah + 128 * G1_PAD;
    __nv_bfloat16* Bh = Al + 128 * G1_PAD;       // [256][40]
    __nv_bfloat16* Bl = Bh + 256 * G1_PAD;

    int tid = threadIdx.x;
    int wid = tid >> 5, lane = tid & 31;
    int wm = wid >> 2, wn = wid & 3;
    int mBase = wm * 32, nBase = wn * 64;
    int rowBase = blockIdx.x * 128;
    int g = lane >> 2, tg = lane & 3;

    float acc[2][8][4];
    #pragma unroll
    for (int i = 0; i < 2; i++)
        #pragma unroll
        for (int j = 0; j < 8; j++)
            #pragma unroll
            for (int r = 0; r < 4; r++) acc[i][j][r] = 0.f;

    int ar = tid >> 2, aseg = tid & 3;
    int gr = rowBase + ar; if (gr >= NNODES) gr = NNODES - 1;
    const float* gX = X + (size_t)gr * NFEAT + aseg * 8;

    float4 pv0 = *(const float4*)(gX);
    float4 pv1 = *(const float4*)(gX + 4);

    for (int kc = 0; kc < NFEAT / 32; kc++) {
        {
            float f[8] = {pv0.x, pv0.y, pv0.z, pv0.w, pv1.x, pv1.y, pv1.z, pv1.w};
            __nv_bfloat162 hp[4], lp[4];
            splitpack(f, hp, lp);
            *(uint4*)(Ah + ar * G1_PAD + aseg * 8) = *(uint4*)hp;
            *(uint4*)(Al + ar * G1_PAD + aseg * 8) = *(uint4*)lp;
        }
        #pragma unroll
        for (int b = 0; b < 2; b++) {
            int i = tid + b * 512;
            int n = i >> 2, bseg = i & 3;
            size_t bo = (size_t)n * NFEAT + kc * 32 + bseg * 8;
            *(float4*)(Bh + n * G1_PAD + bseg * 8) = *(const float4*)(g_W1tH + bo);
            *(float4*)(Bl + n * G1_PAD + bseg * 8) = *(const float4*)(g_W1tL + bo);
        }
        __syncthreads();

        if (kc + 1 < NFEAT / 32) {
            pv0 = *(const float4*)(gX + (kc + 1) * 32);
            pv1 = *(const float4*)(gX + (kc + 1) * 32 + 4);
        }

        #pragma unroll
        for (int ks = 0; ks < 2; ks++) {
            int k0 = ks * 16;
            uint32_t afh[2][4], afl[2][4];
            #pragma unroll
            for (int i = 0; i < 2; i++) {
                const __nv_bfloat16* bh = Ah + (mBase + i * 16 + g) * G1_PAD + k0;
                const __nv_bfloat16* bl = Al + (mBase + i * 16 + g) * G1_PAD + k0;
                afh[i][0] = *(const uint32_t*)(bh + 2 * tg);
                afh[i][1] = *(const uint32_t*)(bh + 8 * G1_PAD + 2 * tg);
                afh[i][2] = *(const uint32_t*)(bh + 2 * tg + 8);
                afh[i][3] = *(const uint32_t*)(bh + 8 * G1_PAD + 2 * tg + 8);
                afl[i][0] = *(const uint32_t*)(bl + 2 * tg);
                afl[i][1] = *(const uint32_t*)(bl + 8 * G1_PAD + 2 * tg);
                afl[i][2] = *(const uint32_t*)(bl + 2 * tg + 8);
                afl[i][3] = *(const uint32_t*)(bl + 8 * G1_PAD + 2 * tg + 8);
            }
            #pragma unroll
            for (int j = 0; j < 8; j++) {
                const __nv_bfloat16* pbh = Bh + (nBase + j * 8 + g) * G1_PAD + k0;
                const __nv_bfloat16* pbl = Bl + (nBase + j * 8 + g) * G1_PAD + k0;
                uint32_t bh0 = *(const uint32_t*)(pbh + 2 * tg);
                uint32_t bh1 = *(const uint32_t*)(pbh + 2 * tg + 8);
                uint32_t bl0 = *(const uint32_t*)(pbl + 2 * tg);
                uint32_t bl1 = *(const uint32_t*)(pbl + 2 * tg + 8);
                #pragma unroll
                for (int i = 0; i < 2; i++) {
                    mma16816(acc[i][j], afh[i], bh0, bh1);
                    mma16816(acc[i][j], afh[i], bl0, bl1);
                    mma16816(acc[i][j], afl[i], bh0, bh1);
                }
            }
        }
        __syncthreads();
    }

    // epilogue: scale by disB[row] (stream-B copy), store as fp16
    #pragma unroll
    for (int i = 0; i < 2; i++) {
        int r0 = rowBase + mBase + i * 16 + g;
        int r1 = r0 + 8;
        float d0 = (r0 < NNODES) ? g_disB[r0] : 0.f;
        float d1 = (r1 < NNODES) ? g_disB[r1] : 0.f;
        #pragma unroll
        for (int j = 0; j < 8; j++) {
            int col = nBase + j * 8 + 2 * tg;
            if (r0 < NNODES) {
                __half2 v = __floats2half2_rn(acc[i][j][0] * d0, acc[i][j][1] * d0);
                *(__half2*)(g_G1h + (size_t)r0 * NHID + col) = v;
            }
            if (r1 < NNODES) {
                __half2 v = __floats2half2_rn(acc[i][j][2] * d1, acc[i][j][3] * d1);
                *(__half2*)(g_G1h + (size_t)r1 * NHID + col) = v;
            }
        }
    }
}

// --------------------- Aggregation 1: H1 = relu(dis*(sum)+b1) --------------------
__device__ __forceinline__ void h8acc(float* a, float4 v) {
    const __half2* h = (const __half2*)&v;
    #pragma unroll
    for (int q = 0; q < 4; q++) {
        float2 f = __half22float2(h[q]);
        a[2 * q + 0] += f.x;
        a[2 * q + 1] += f.y;
    }
}

__global__ __launch_bounds__(256) void k_agg1(const float* __restrict__ b1) {
    int w = (blockIdx.x * blockDim.x + threadIdx.x) >> 5;
    int lane = threadIdx.x & 31;
    if (w >= NNODES) return;
    const float4* G = (const float4*)g_G1h;   // 32 float4 per row

    float a[8] = {0.f, 0.f, 0.f, 0.f, 0.f, 0.f, 0.f, 0.f};
    h8acc(a, G[(size_t)w * 32 + lane]);       // self

    int beg = g_off[w], end = g_off[w + 1];
    int j = beg;
    for (; j + 4 <= end; j += 4) {
        int s0 = g_csr[j], s1 = g_csr[j + 1], s2 = g_csr[j + 2], s3 = g_csr[j + 3];
        float4 v0 = G[(size_t)s0 * 32 + lane];
        float4 v1 = G[(size_t)s1 * 32 + lane];
        float4 v2 = G[(size_t)s2 * 32 + lane];
        float4 v3 = G[(size_t)s3 * 32 + lane];
        h8acc(a, v0); h8acc(a, v1); h8acc(a, v2); h8acc(a, v3);
    }
    for (; j < end; ++j)
        h8acc(a, G[(size_t)g_csr[j] * 32 + lane]);

    float d = g_dis[w];
    int c0 = lane << 3;
    float4 bb0 = *(const float4*)(b1 + c0);
    float4 bb1 = *(const float4*)(b1 + c0 + 4);
    float4 o0, o1;
    o0.x = fmaxf(fmaf(a[0], d, bb0.x), 0.f);
    o0.y = fmaxf(fmaf(a[1], d, bb0.y), 0.f);
    o0.z = fmaxf(fmaf(a[2], d, bb0.z), 0.f);
    o0.w = fmaxf(fmaf(a[3], d, bb0.w), 0.f);
    o1.x = fmaxf(fmaf(a[4], d, bb1.x), 0.f);
    o1.y = fmaxf(fmaf(a[5], d, bb1.y), 0.f);
    o1.z = fmaxf(fmaf(a[6], d, bb1.z), 0.f);
    o1.w = fmaxf(fmaf(a[7], d, bb1.w), 0.f);
    float* H = g_H1 + (size_t)w * NHID + c0;
    *(float4*)(H + 0) = o0;
    *(float4*)(H + 4) = o1;
}

// ------------- GEMM2 (mma.sync bf16 split): Ph = fp16(dis * (H1 @ W2)) -----------
__global__ __launch_bounds__(256) void k_gemm2_mma() {
    int tid = threadIdx.x;
    int wid = tid >> 5, lane = tid & 31;
    int g = lane >> 2, tg = lane & 3;
    int wBase = blockIdx.x * 128 + wid * 16;

    int r0 = wBase + g, r1 = r0 + 8;
    int cr0 = (r0 < NNODES) ? r0 : NNODES - 1;
    int cr1 = (r1 < NNODES) ? r1 : NNODES - 1;
    const float* A0 = g_H1 + (size_t)cr0 * NHID;
    const float* A1 = g_H1 + (size_t)cr1 * NHID;

    float acc[5][4];
    #pragma unroll
    for (int n = 0; n < 5; n++)
        #pragma unroll
        for (int r = 0; r < 4; r++) acc[n][r] = 0.f;

    for (int kc = 0; kc < NHID / 16; kc++) {
        int kk = kc * 16 + tg * 2;
        float f[8];
        float2 t0 = *(const float2*)(A0 + kk);
        float2 t1 = *(const float2*)(A1 + kk);
        float2 t2 = *(const float2*)(A0 + kk + 8);
        float2 t3 = *(const float2*)(A1 + kk + 8);
        f[0] = t0.x; f[1] = t0.y; f[2] = t1.x; f[3] = t1.y;
        f[4] = t2.x; f[5] = t2.y; f[6] = t3.x; f[7] = t3.y;
        __nv_bfloat162 hp[4], lp[4];
        splitpack(f, hp, lp);
        uint32_t ah[4] = {*(uint32_t*)&hp[0], *(uint32_t*)&hp[1],
                          *(uint32_t*)&hp[2], *(uint32_t*)&hp[3]};
        uint32_t al[4] = {*(uint32_t*)&lp[0], *(uint32_t*)&lp[1],
                          *(uint32_t*)&lp[2], *(uint32_t*)&lp[3]};
        #pragma unroll
        for (int nt = 0; nt < 5; nt++) {
            const __nv_bfloat16* bh = g_W2tH + (size_t)(nt * 8 + g) * NHID + kc * 16;
            const __nv_bfloat16* bl = g_W2tL + (size_t)(nt * 8 + g) * NHID + kc * 16;
            uint32_t bh0 = *(const uint32_t*)(bh + 2 * tg);
            uint32_t bh1 = *(const uint32_t*)(bh + 2 * tg + 8);
            uint32_t bl0 = *(const uint32_t*)(bl + 2 * tg);
            uint32_t bl1 = *(const uint32_t*)(bl + 2 * tg + 8);
            mma16816(acc[nt], ah, bh0, bh1);
            mma16816(acc[nt], ah, bl0, bl1);
            mma16816(acc[nt], al, bh0, bh1);
        }
    }

    float d0 = (r0 < NNODES) ? g_dis[r0] : 0.f;
    float d1 = (r1 < NNODES) ? g_dis[r1] : 0.f;
    #pragma unroll
    for (int nt = 0; nt < 5; nt++) {
        int col = nt * 8 + 2 * tg;
        if (r0 < NNODES)
            *(__half2*)(g_Ph + (size_t)r0 * NCLASS + col) =
                __floats2half2_rn(acc[nt][0] * d0, acc[nt][1] * d0);
        if (r1 < NNODES)
            *(__half2*)(g_Ph + (size_t)r1 * NCLASS + col) =
                __floats2half2_rn(acc[nt][2] * d1, acc[nt][3] * d1);
    }
}

// ----------- Aggregation 2 + bias + log_softmax, fused, warp per node ------------
__global__ __launch_bounds__(256) void k_agg2(const float* __restrict__ b2,
                                              float* __restrict__ out) {
    int w = (blockIdx.x * blockDim.x + threadIdx.x) >> 5;
    int lane = threadIdx.x & 31;
    if (w >= NNODES) return;
    const uint2* Pv = (const uint2*)g_Ph;   // 10 uint2 per row
    bool act = lane < 10;
    int li = act ? lane : 0;

    float a0 = 0.f, a1 = 0.f, a2 = 0.f, a3 = 0.f;
    if (act) {
        uint2 v = Pv[(size_t)w * 10 + li];
        float2 x = __half22float2(*(__half2*)&v.x);
        float2 y = __half22float2(*(__half2*)&v.y);
        a0 = x.x; a1 = x.y; a2 = y.x; a3 = y.y;
    }

    int beg = g_off[w], end = g_off[w + 1];
    int j = beg;
    for (; j + 4 <= end; j += 4) {
        int s0 = g_csr[j], s1 = g_csr[j + 1], s2 = g_csr[j + 2], s3 = g_csr[j + 3];
        if (act) {
            uint2 u0 = Pv[(size_t)s0 * 10 + li];
            uint2 u1 = Pv[(size_t)s1 * 10 + li];
            uint2 u2 = Pv[(size_t)s2 * 10 + li];
            uint2 u3 = Pv[(size_t)s3 * 10 + li];
            #pragma unroll
            for (int q = 0; q < 4; q++) {
                uint2 u = (q == 0) ? u0 : (q == 1) ? u1 : (q == 2) ? u2 : u3;
                float2 x = __half22float2(*(__half2*)&u.x);
                float2 y = __half22float2(*(__half2*)&u.y);
                a0 += x.x; a1 += x.y; a2 += y.x; a3 += y.y;
            }
        }
    }
    for (; j < end; ++j) {
        if (act) {
            uint2 u = Pv[(size_t)g_csr[j] * 10 + li];
            float2 x = __half22float2(*(__half2*)&u.x);
            float2 y = __half22float2(*(__half2*)&u.y);
            a0 += x.x; a1 += x.y; a2 += y.x; a3 += y.y;
        }
    }

    float d = g_dis[w];
    float v0 = -1e30f, v1 = -1e30f, v2 = -1e30f, v3 = -1e30f;
    if (act) {
        float4 bb = *(const float4*)(b2 + li * 4);
        v0 = fmaf(a0, d, bb.x);
        v1 = fmaf(a1, d, bb.y);
        v2 = fmaf(a2, d, bb.z);
        v3 = fmaf(a3, d, bb.w);
    }
    float m = fmaxf(fmaxf(v0, v1), fmaxf(v2, v3));
    #pragma unroll
    for (int o = 16; o > 0; o >>= 1) m = fmaxf(m, __shfl_xor_sync(0xFFFFFFFFu, m, o));
    float e = act ? (expf(v0 - m) + expf(v1 - m) + expf(v2 - m) + expf(v3 - m)) : 0.f;
    #pragma unroll
    for (int o = 16; o > 0; o >>= 1) e += __shfl_xor_sync(0xFFFFFFFFu, e, o);
    float lz = m + logf(e);

    if (act) {
        float4 o4 = make_float4(v0 - lz, v1 - lz, v2 - lz, v3 - lz);
        *(float4*)(out + (size_t)w * NCLASS + li * 4) = o4;
    }
}

// ---------------------------------- launcher -------------------------------------
extern "C" void kernel_launch(void* const* d_in, const int* in_sizes, int n_in,
                              void* d_out, int out_size) {
    const float* x = nullptr;
    const float* W1 = nullptr;
    const float* b1 = nullptr;
    const float* W2 = nullptr;
    const float* b2 = nullptr;
    const void* edge = nullptr;
    int edgeElems = 0;
    for (int i = 0; i < n_in; i++) {
        int s = in_sizes[i];
        if      (s == 51200000) x  = (const float*)d_in[i];
        else if (s == 131072)   W1 = (const float*)d_in[i];
        else if (s == 256)      b1 = (const float*)d_in[i];
        else if (s == 10240)    W2 = (const float*)d_in[i];
        else if (s == 40)       b2 = (const float*)d_in[i];
        else if (s == 6400000) { edge = d_in[i]; edgeElems = s; }
    }
    if (!x || !W1 || !b1 || !W2 || !b2 || !edge) {
        x  = (const float*)d_in[0];
        W1 = (const float*)d_in[1];
        b1 = (const float*)d_in[2];
        W2 = (const float*)d_in[3];
        b2 = (const float*)d_in[4];
        edge = d_in[5];
        edgeElems = in_sizes[5];
    }
    float* out = (float*)d_out;

    int E = edgeElems / 2;
    if (E > NEDGE_MAX) E = NEDGE_MAX;

    // one-time resource setup (handles only; no device memory)
    static cudaStream_t sB = nullptr;
    static cudaEvent_t evFork = nullptr, evB = nullptr;
    if (!sB) {
        cudaStreamCreateWithFlags(&sB, cudaStreamNonBlocking);
        cudaEventCreateWithFlags(&evFork, cudaEventDisableTiming);
        cudaEventCreateWithFlags(&evB, cudaEventDisableTiming);
        cudaFuncSetAttribute(k_gemm1_mma, cudaFuncAttributeMaxDynamicSharedMemorySize,
                             G1_SMEM_BYTES);
    }

    // dtype detection first (both branches need g_is64)
    k_detect<<<1, 256>>>((const unsigned*)edge, E);

    // ---- fork: stream B = weights conv + degB + GEMM1 ----
    cudaEventRecord(evFork, 0);
    cudaStreamWaitEvent(sB, evFork, 0);

    k_convW1t<<<(NFEAT * NHID + 255) / 256, 256, 0, sB>>>(W1);
    k_convW2t<<<(NHID * NCLASS + 255) / 256, 256, 0, sB>>>(W2);
    k_degB<<<(NNODES + 255) / 256, 256, 0, sB>>>(edge, E);
    k_histB<<<(E + 255) / 256, 256, 0, sB>>>(edge, E);
    k_finB<<<(NNODES + 255) / 256, 256, 0, sB>>>();
    k_gemm1_mma<<<(NNODES + 127) / 128, 512, G1_SMEM_BYTES, sB>>>(x);
    cudaEventRecord(evB, sB);

    // ---- stream A (default): CSR chain ----
    k_zero_deg<<<(NNODES + 255) / 256, 256>>>();
    k_hist<<<(E + 255) / 256, 256>>>(edge, E);
    k_scan1<<<SCAN_NB, 256>>>();
    k_scan2<<<1, 128>>>(SCAN_NB);
    k_scan3<<<SCAN_NB, 1024>>>();
    k_scatter<<<(E + 255) / 256, 256>>>(edge, E);

    // ---- join: agg1 needs CSR (stream A) + G1 (stream B) ----
    cudaStreamWaitEvent(0, evB, 0);
    k_agg1<<<(NNODES * 32 + 255) / 256, 256>>>(b1);

    // Layer 2
    k_gemm2_mma<<<(NNODES + 127) / 128, 256>>>();
    k_agg2<<<(NNODES * 32 + 255) / 256, 256>>>(b2, out);
}

// round 10
// speedup vs baseline: 2.0974x; 1.1561x over previous
#include <cuda_runtime.h>
#include <cuda_bf16.h>
#include <cuda_fp16.h>
#include <cstdint>

#define NNODES 100000
#define NFEAT  512
#define NHID   256
#define NCLASS 40
#define NEDGE_MAX 3200000
#define SCAN_NB ((NNODES + 1023) / 1024)

// ------------- scratch (static device allocations; no runtime alloc) -------------
__device__ int   g_deg[NNODES];
__device__ int   g_off[NNODES + 1];
__device__ int   g_cur[NNODES];
__device__ int   g_csr[NEDGE_MAX];
__device__ float g_dis[NNODES];
__device__ float g_disB[NNODES];
__device__ int   g_part[SCAN_NB + 8];
__device__ int   g_is64;
__device__ __align__(16) __half g_G1h[(size_t)NNODES * NHID];  // fp16: dis[row]*(X@W1)
__device__ __align__(16) __half g_H1h[(size_t)NNODES * NHID];  // fp16: relu(agg + b1)
__device__ __align__(16) __half g_Ph[(size_t)NNODES * NCLASS]; // fp16: dis[row]*(H1@W2)
// bf16 weights (transposed [n][k]); W1 hi only, W2 split hi/lo
__device__ __align__(16) __nv_bfloat16 g_W1tH[(size_t)NHID * NFEAT];
__device__ __align__(16) __nv_bfloat16 g_W2tH[(size_t)NCLASS * NHID];
__device__ __align__(16) __nv_bfloat16 g_W2tL[(size_t)NCLASS * NHID];

// --------------------------- edge dtype detection --------------------------------
__global__ void k_detect(const unsigned* __restrict__ w, int E) {
    __shared__ int any;
    if (threadIdx.x == 0) any = 0;
    __syncthreads();
    int n = (E < 1024) ? E : 1024;
    for (int i = threadIdx.x; i < n; i += blockDim.x)
        if (w[2 * i + 1] != 0u) any = 1;
    __syncthreads();
    if (threadIdx.x == 0) g_is64 = (any == 0) ? 1 : 0;
}

__device__ __forceinline__ int edge_at(const void* edge, int idx) {
    if (g_is64) return (int)((const long long*)edge)[idx];
    return ((const int*)edge)[idx];
}

// ----------------- degree computation on stream B (for GEMM1 epilogue) ------------
__global__ void k_degB(const void* __restrict__ edge, int E) {
    int i = blockIdx.x * blockDim.x + threadIdx.x;
    if (i < NNODES) ((int*)g_disB)[i] = 0;
}
__global__ void k_histB(const void* __restrict__ edge, int E) {
    int e = blockIdx.x * blockDim.x + threadIdx.x;
    if (e < E) {
        int d = edge_at(edge, E + e);
        if ((unsigned)d < (unsigned)NNODES) atomicAdd(&((int*)g_disB)[d], 1);
    }
}
__global__ void k_finB() {
    int i = blockIdx.x * blockDim.x + threadIdx.x;
    if (i < NNODES) {
        int v = ((int*)g_disB)[i];
        g_disB[i] = rsqrtf((float)(v + 1));
    }
}

// ------------------------------- CSR construction (stream A) ----------------------
__global__ void k_zero_deg() {
    int i = blockIdx.x * blockDim.x + threadIdx.x;
    if (i < NNODES) g_deg[i] = 0;
}

__global__ void k_hist(const void* __restrict__ edge, int E) {
    int e = blockIdx.x * blockDim.x + threadIdx.x;
    if (e < E) {
        int d = edge_at(edge, E + e);
        if ((unsigned)d < (unsigned)NNODES) atomicAdd(&g_deg[d], 1);
    }
}

__global__ void k_scan1() {
    __shared__ int s[256];
    int b = blockIdx.x, t = threadIdx.x;
    int base = b * 1024;
    int sum = 0;
    #pragma unroll
    for (int i = t; i < 1024; i += 256) {
        int gi = base + i;
        sum += (gi < NNODES) ? g_deg[gi] : 0;
    }
    s[t] = sum; __syncthreads();
    for (int o = 128; o > 0; o >>= 1) {
        if (t < o) s[t] += s[t + o];
        __syncthreads();
    }
    if (t == 0) g_part[b] = s[0];
}

__global__ void k_scan2(int nb) {
    __shared__ int s[128];
    int t = threadIdx.x;
    int v = (t < nb) ? g_part[t] : 0;
    s[t] = v; __syncthreads();
    #pragma unroll
    for (int o = 1; o < 128; o <<= 1) {
        int x = (t >= o) ? s[t - o] : 0;
        __syncthreads();
        s[t] += x;
        __syncthreads();
    }
    if (t < nb) g_part[t] = s[t] - v;
}

__global__ void k_scan3() {
    __shared__ int s[1024];
    int b = blockIdx.x, t = threadIdx.x;
    int i = b * 1024 + t;
    int v = (i < NNODES) ? g_deg[i] : 0;
    s[t] = v; __syncthreads();
    for (int o = 1; o < 1024; o <<= 1) {
        int x = (t >= o) ? s[t - o] : 0;
        __syncthreads();
        s[t] += x;
        __syncthreads();
    }
    int excl = s[t] - v;
    int off = g_part[b] + excl;
    if (i < NNODES) {
        g_off[i] = off;
        g_cur[i] = off;
        g_dis[i] = rsqrtf((float)(v + 1));
        if (i == NNODES - 1) g_off[NNODES] = off + v;
    }
}

__global__ void k_scatter(const void* __restrict__ edge, int E) {
    int e = blockIdx.x * blockDim.x + threadIdx.x;
    if (e < E) {
        int s = edge_at(edge, e);
        int d = edge_at(edge, E + e);
        if ((unsigned)d < (unsigned)NNODES && (unsigned)s < (unsigned)NNODES) {
            int p = atomicAdd(&g_cur[d], 1);
            g_csr[p] = s;
        }
    }
}

// ---------------------- bf16 weight conversions ------------------------------------
__global__ void k_convW1t(const float* __restrict__ W1) {
    int idx = blockIdx.x * 256 + threadIdx.x;
    if (idx < NFEAT * NHID) {
        int k = idx >> 8;      // / NHID
        int n = idx & 255;     // % NHID
        g_W1tH[(size_t)n * NFEAT + k] = __float2bfloat16_rn(W1[idx]);
    }
}

__global__ void k_convW2t(const float* __restrict__ W2) {
    int idx = blockIdx.x * 256 + threadIdx.x;
    if (idx < NHID * NCLASS) {
        int k = idx / NCLASS;
        int n = idx - k * NCLASS;
        float v = W2[idx];
        __nv_bfloat16 h = __float2bfloat16_rn(v);
        g_W2tH[(size_t)n * NHID + k] = h;
        g_W2tL[(size_t)n * NHID + k] = __float2bfloat16_rn(v - __bfloat162float(h));
    }
}

// ---------------- GEMM1 (mma.sync bf16 split-A): G1 = disB * (X @ W1) -------------
// D = Ah@Bh + Al@Bh (A split-bf16 for fp32-grade X; W1 plain bf16)
#define G1_PAD 40   // bf16 elems per smem row (32 data + 8 pad) -> 80B stride
#define G1_SMEM_BYTES ((128 * G1_PAD * 2 + 256 * G1_PAD) * 2)

__device__ __forceinline__ void mma16816(float* c, const uint32_t* a,
                                         uint32_t b0, uint32_t b1) {
    asm volatile(
        "mma.sync.aligned.m16n8k16.row.col.f32.bf16.bf16.f32 "
        "{%0,%1,%2,%3}, {%4,%5,%6,%7}, {%8,%9}, {%0,%1,%2,%3};"
        : "+f"(c[0]), "+f"(c[1]), "+f"(c[2]), "+f"(c[3])
        : "r"(a[0]), "r"(a[1]), "r"(a[2]), "r"(a[3]), "r"(b0), "r"(b1));
}

__device__ __forceinline__ void splitpack(const float* f, __nv_bfloat162* hp,
                                          __nv_bfloat162* lp) {
    #pragma unroll
    for (int q = 0; q < 4; q++) {
        __nv_bfloat16 h0 = __float2bfloat16_rn(f[2 * q]);
        __nv_bfloat16 h1 = __float2bfloat16_rn(f[2 * q + 1]);
        hp[q] = __nv_bfloat162(h0, h1);
        lp[q] = __nv_bfloat162(
            __float2bfloat16_rn(f[2 * q] - __bfloat162float(h0)),
            __float2bfloat16_rn(f[2 * q + 1] - __bfloat162float(h1)));
    }
}

__global__ __launch_bounds__(512) void k_gemm1_mma(const float* __restrict__ X) {
    extern __shared__ __nv_bfloat16 sm[];
    __nv_bfloat16* Ah = sm;                      // [128][40]
    __nv_bfloat16* Al = Ah + 128 * G1_PAD;
    __nv_bfloat16* Bh = Al + 128 * G1_PAD;       // [256][40]

    int tid = threadIdx.x;
    int wid = tid >> 5, lane = tid & 31;
    int wm = wid >> 2, wn = wid & 3;
    int mBase = wm * 32, nBase = wn * 64;
    int rowBase = blockIdx.x * 128;
    int g = lane >> 2, tg = lane & 3;

    float acc[2][8][4];
    #pragma unroll
    for (int i = 0; i < 2; i++)
        #pragma unroll
        for (int j = 0; j < 8; j++)
            #pragma unroll
            for (int r = 0; r < 4; r++) acc[i][j][r] = 0.f;

    int ar = tid >> 2, aseg = tid & 3;
    int gr = rowBase + ar; if (gr >= NNODES) gr = NNODES - 1;
    const float* gX = X + (size_t)gr * NFEAT + aseg * 8;

    float4 pv0 = *(const float4*)(gX);
    float4 pv1 = *(const float4*)(gX + 4);

    for (int kc = 0; kc < NFEAT / 32; kc++) {
        {
            float f[8] = {pv0.x, pv0.y, pv0.z, pv0.w, pv1.x, pv1.y, pv1.z, pv1.w};
            __nv_bfloat162 hp[4], lp[4];
            splitpack(f, hp, lp);
            *(uint4*)(Ah + ar * G1_PAD + aseg * 8) = *(uint4*)hp;
            *(uint4*)(Al + ar * G1_PAD + aseg * 8) = *(uint4*)lp;
        }
        // B (hi only): 256 rows x 32 k, two float4 per thread
        #pragma unroll
        for (int b = 0; b < 2; b++) {
            int i = tid + b * 512;
            int n = i >> 2, bseg = i & 3;
            size_t bo = (size_t)n * NFEAT + kc * 32 + bseg * 8;
            *(float4*)(Bh + n * G1_PAD + bseg * 8) = *(const float4*)(g_W1tH + bo);
        }
        __syncthreads();

        if (kc + 1 < NFEAT / 32) {
            pv0 = *(const float4*)(gX + (kc + 1) * 32);
            pv1 = *(const float4*)(gX + (kc + 1) * 32 + 4);
        }

        #pragma unroll
        for (int ks = 0; ks < 2; ks++) {
            int k0 = ks * 16;
            uint32_t afh[2][4], afl[2][4];
            #pragma unroll
            for (int i = 0; i < 2; i++) {
                const __nv_bfloat16* bh = Ah + (mBase + i * 16 + g) * G1_PAD + k0;
                const __nv_bfloat16* bl = Al + (mBase + i * 16 + g) * G1_PAD + k0;
                afh[i][0] = *(const uint32_t*)(bh + 2 * tg);
                afh[i][1] = *(const uint32_t*)(bh + 8 * G1_PAD + 2 * tg);
                afh[i][2] = *(const uint32_t*)(bh + 2 * tg + 8);
                afh[i][3] = *(const uint32_t*)(bh + 8 * G1_PAD + 2 * tg + 8);
                afl[i][0] = *(const uint32_t*)(bl + 2 * tg);
                afl[i][1] = *(const uint32_t*)(bl + 8 * G1_PAD + 2 * tg);
                afl[i][2] = *(const uint32_t*)(bl + 2 * tg + 8);
                afl[i][3] = *(const uint32_t*)(bl + 8 * G1_PAD + 2 * tg + 8);
            }
            #pragma unroll
            for (int j = 0; j < 8; j++) {
                const __nv_bfloat16* pbh = Bh + (nBase + j * 8 + g) * G1_PAD + k0;
                uint32_t bh0 = *(const uint32_t*)(pbh + 2 * tg);
                uint32_t bh1 = *(const uint32_t*)(pbh + 2 * tg + 8);
                #pragma unroll
                for (int i = 0; i < 2; i++) {
                    mma16816(acc[i][j], afh[i], bh0, bh1);
                    mma16816(acc[i][j], afl[i], bh0, bh1);
                }
            }
        }
        __syncthreads();
    }

    // epilogue: scale by disB[row], store as fp16
    #pragma unroll
    for (int i = 0; i < 2; i++) {
        int r0 = rowBase + mBase + i * 16 + g;
        int r1 = r0 + 8;
        float d0 = (r0 < NNODES) ? g_disB[r0] : 0.f;
        float d1 = (r1 < NNODES) ? g_disB[r1] : 0.f;
        #pragma unroll
        for (int j = 0; j < 8; j++) {
            int col = nBase + j * 8 + 2 * tg;
            if (r0 < NNODES) {
                __half2 v = __floats2half2_rn(acc[i][j][0] * d0, acc[i][j][1] * d0);
                *(__half2*)(g_G1h + (size_t)r0 * NHID + col) = v;
            }
            if (r1 < NNODES) {
                __half2 v = __floats2half2_rn(acc[i][j][2] * d1, acc[i][j][3] * d1);
                *(__half2*)(g_G1h + (size_t)r1 * NHID + col) = v;
            }
        }
    }
}

// --------------------- Aggregation 1: H1h = fp16(relu(dis*sum+b1)) ----------------
__device__ __forceinline__ void h8acc(float* a, float4 v) {
    const __half2* h = (const __half2*)&v;
    #pragma unroll
    for (int q = 0; q < 4; q++) {
        float2 f = __half22float2(h[q]);
        a[2 * q + 0] += f.x;
        a[2 * q + 1] += f.y;
    }
}

__global__ __launch_bounds__(256) void k_agg1(const float* __restrict__ b1) {
    int w = (blockIdx.x * blockDim.x + threadIdx.x) >> 5;
    int lane = threadIdx.x & 31;
    if (w >= NNODES) return;
    const float4* G = (const float4*)g_G1h;   // 32 float4 per row

    float a[8] = {0.f, 0.f, 0.f, 0.f, 0.f, 0.f, 0.f, 0.f};
    h8acc(a, G[(size_t)w * 32 + lane]);       // self

    int beg = g_off[w], end = g_off[w + 1];
    int j = beg;
    for (; j + 4 <= end; j += 4) {
        int s0 = g_csr[j], s1 = g_csr[j + 1], s2 = g_csr[j + 2], s3 = g_csr[j + 3];
        float4 v0 = G[(size_t)s0 * 32 + lane];
        float4 v1 = G[(size_t)s1 * 32 + lane];
        float4 v2 = G[(size_t)s2 * 32 + lane];
        float4 v3 = G[(size_t)s3 * 32 + lane];
        h8acc(a, v0); h8acc(a, v1); h8acc(a, v2); h8acc(a, v3);
    }
    for (; j < end; ++j)
        h8acc(a, G[(size_t)g_csr[j] * 32 + lane]);

    float d = g_dis[w];
    int c0 = lane << 3;
    float4 bb0 = *(const float4*)(b1 + c0);
    float4 bb1 = *(const float4*)(b1 + c0 + 4);
    __half2 o[4];
    o[0] = __floats2half2_rn(fmaxf(fmaf(a[0], d, bb0.x), 0.f),
                             fmaxf(fmaf(a[1], d, bb0.y), 0.f));
    o[1] = __floats2half2_rn(fmaxf(fmaf(a[2], d, bb0.z), 0.f),
                             fmaxf(fmaf(a[3], d, bb0.w), 0.f));
    o[2] = __floats2half2_rn(fmaxf(fmaf(a[4], d, bb1.x), 0.f),
                             fmaxf(fmaf(a[5], d, bb1.y), 0.f));
    o[3] = __floats2half2_rn(fmaxf(fmaf(a[6], d, bb1.z), 0.f),
                             fmaxf(fmaf(a[7], d, bb1.w), 0.f));
    *(uint4*)(g_H1h + (size_t)w * NHID + c0) = *(uint4*)o;
}

// ------------- GEMM2 (mma.sync bf16 split): Ph = fp16(dis * (H1 @ W2)) -----------
__global__ __launch_bounds__(256) void k_gemm2_mma() {
    int tid = threadIdx.x;
    int wid = tid >> 5, lane = tid & 31;
    int g = lane >> 2, tg = lane & 3;
    int wBase = blockIdx.x * 128 + wid * 16;

    int r0 = wBase + g, r1 = r0 + 8;
    int cr0 = (r0 < NNODES) ? r0 : NNODES - 1;
    int cr1 = (r1 < NNODES) ? r1 : NNODES - 1;
    const __half* A0 = g_H1h + (size_t)cr0 * NHID;
    const __half* A1 = g_H1h + (size_t)cr1 * NHID;

    float acc[5][4];
    #pragma unroll
    for (int n = 0; n < 5; n++)
        #pragma unroll
        for (int r = 0; r < 4; r++) acc[n][r] = 0.f;

    for (int kc = 0; kc < NHID / 16; kc++) {
        int kk = kc * 16 + tg * 2;
        float2 t0 = __half22float2(*(const __half2*)(A0 + kk));
        float2 t1 = __half22float2(*(const __half2*)(A1 + kk));
        float2 t2 = __half22float2(*(const __half2*)(A0 + kk + 8));
        float2 t3 = __half22float2(*(const __half2*)(A1 + kk + 8));
        float f[8] = {t0.x, t0.y, t1.x, t1.y, t2.x, t2.y, t3.x, t3.y};
        __nv_bfloat162 hp[4], lp[4];
        splitpack(f, hp, lp);
        uint32_t ah[4] = {*(uint32_t*)&hp[0], *(uint32_t*)&hp[1],
                          *(uint32_t*)&hp[2], *(uint32_t*)&hp[3]};
        uint32_t al[4] = {*(uint32_t*)&lp[0], *(uint32_t*)&lp[1],
                          *(uint32_t*)&lp[2], *(uint32_t*)&lp[3]};
        #pragma unroll
        for (int nt = 0; nt < 5; nt++) {
            const __nv_bfloat16* bh = g_W2tH + (size_t)(nt * 8 + g) * NHID + kc * 16;
            const __nv_bfloat16* bl = g_W2tL + (size_t)(nt * 8 + g) * NHID + kc * 16;
            uint32_t bh0 = *(const uint32_t*)(bh + 2 * tg);
            uint32_t bh1 = *(const uint32_t*)(bh + 2 * tg + 8);
            uint32_t bl0 = *(const uint32_t*)(bl + 2 * tg);
            uint32_t bl1 = *(const uint32_t*)(bl + 2 * tg + 8);
            mma16816(acc[nt], ah, bh0, bh1);
            mma16816(acc[nt], ah, bl0, bl1);
            mma16816(acc[nt], al, bh0, bh1);
        }
    }

    float d0 = (r0 < NNODES) ? g_dis[r0] : 0.f;
    float d1 = (r1 < NNODES) ? g_dis[r1] : 0.f;
    #pragma unroll
    for (int nt = 0; nt < 5; nt++) {
        int col = nt * 8 + 2 * tg;
        if (r0 < NNODES)
            *(__half2*)(g_Ph + (size_t)r0 * NCLASS + col) =
                __floats2half2_rn(acc[nt][0] * d0, acc[nt][1] * d0);
        if (r1 < NNODES)
            *(__half2*)(g_Ph + (size_t)r1 * NCLASS + col) =
                __floats2half2_rn(acc[nt][2] * d1, acc[nt][3] * d1);
    }
}

// ----------- Aggregation 2 + bias + log_softmax, fused, warp per node ------------
__global__ __launch_bounds__(256) void k_agg2(const float* __restrict__ b2,
                                              float* __restrict__ out) {
    int w = (blockIdx.x * blockDim.x + threadIdx.x) >> 5;
    int lane = threadIdx.x & 31;
    if (w >= NNODES) return;
    const uint2* Pv = (const uint2*)g_Ph;   // 10 uint2 per row
    bool act = lane < 10;
    int li = act ? lane : 0;

    float a0 = 0.f, a1 = 0.f, a2 = 0.f, a3 = 0.f;
    if (act) {
        uint2 v = Pv[(size_t)w * 10 + li];
        float2 x = __half22float2(*(__half2*)&v.x);
        float2 y = __half22float2(*(__half2*)&v.y);
        a0 = x.x; a1 = x.y; a2 = y.x; a3 = y.y;
    }

    int beg = g_off[w], end = g_off[w + 1];
    int j = beg;
    for (; j + 4 <= end; j += 4) {
        int s0 = g_csr[j], s1 = g_csr[j + 1], s2 = g_csr[j + 2], s3 = g_csr[j + 3];
        if (act) {
            uint2 u0 = Pv[(size_t)s0 * 10 + li];
            uint2 u1 = Pv[(size_t)s1 * 10 + li];
            uint2 u2 = Pv[(size_t)s2 * 10 + li];
            uint2 u3 = Pv[(size_t)s3 * 10 + li];
            #pragma unroll
            for (int q = 0; q < 4; q++) {
                uint2 u = (q == 0) ? u0 : (q == 1) ? u1 : (q == 2) ? u2 : u3;
                float2 x = __half22float2(*(__half2*)&u.x);
                float2 y = __half22float2(*(__half2*)&u.y);
                a0 += x.x; a1 += x.y; a2 += y.x; a3 += y.y;
            }
        }
    }
    for (; j < end; ++j) {
        if (act) {
            uint2 u = Pv[(size_t)g_csr[j] * 10 + li];
            float2 x = __half22float2(*(__half2*)&u.x);
            float2 y = __half22float2(*(__half2*)&u.y);
            a0 += x.x; a1 += x.y; a2 += y.x; a3 += y.y;
        }
    }

    float d = g_dis[w];
    float v0 = -1e30f, v1 = -1e30f, v2 = -1e30f, v3 = -1e30f;
    if (act) {
        float4 bb = *(const float4*)(b2 + li * 4);
        v0 = fmaf(a0, d, bb.x);
        v1 = fmaf(a1, d, bb.y);
        v2 = fmaf(a2, d, bb.z);
        v3 = fmaf(a3, d, bb.w);
    }
    float m = fmaxf(fmaxf(v0, v1), fmaxf(v2, v3));
    #pragma unroll
    for (int o = 16; o > 0; o >>= 1) m = fmaxf(m, __shfl_xor_sync(0xFFFFFFFFu, m, o));
    float e = act ? (expf(v0 - m) + expf(v1 - m) + expf(v2 - m) + expf(v3 - m)) : 0.f;
    #pragma unroll
    for (int o = 16; o > 0; o >>= 1) e += __shfl_xor_sync(0xFFFFFFFFu, e, o);
    float lz = m + logf(e);

    if (act) {
        float4 o4 = make_float4(v0 - lz, v1 - lz, v2 - lz, v3 - lz);
        *(float4*)(out + (size_t)w * NCLASS + li * 4) = o4;
    }
}

// ---------------------------------- launcher -------------------------------------
extern "C" void kernel_launch(void* const* d_in, const int* in_sizes, int n_in,
                              void* d_out, int out_size) {
    const float* x = nullptr;
    const float* W1 = nullptr;
    const float* b1 = nullptr;
    const float* W2 = nullptr;
    const float* b2 = nullptr;
    const void* edge = nullptr;
    int edgeElems = 0;
    for (int i = 0; i < n_in; i++) {
        int s = in_sizes[i];
        if      (s == 51200000) x  = (const float*)d_in[i];
        else if (s == 131072)   W1 = (const float*)d_in[i];
        else if (s == 256)      b1 = (const float*)d_in[i];
        else if (s == 10240)    W2 = (const float*)d_in[i];
        else if (s == 40)       b2 = (const float*)d_in[i];
        else if (s == 6400000) { edge = d_in[i]; edgeElems = s; }
    }
    if (!x || !W1 || !b1 || !W2 || !b2 || !edge) {
        x  = (const float*)d_in[0];
        W1 = (const float*)d_in[1];
        b1 = (const float*)d_in[2];
        W2 = (const float*)d_in[3];
        b2 = (const float*)d_in[4];
        edge = d_in[5];
        edgeElems = in_sizes[5];
    }
    float* out = (float*)d_out;

    int E = edgeElems / 2;
    if (E > NEDGE_MAX) E = NEDGE_MAX;

    static cudaStream_t sB = nullptr;
    static cudaEvent_t evFork = nullptr, evB = nullptr;
    if (!sB) {
        cudaStreamCreateWithFlags(&sB, cudaStreamNonBlocking);
        cudaEventCreateWithFlags(&evFork, cudaEventDisableTiming);
        cudaEventCreateWithFlags(&evB, cudaEventDisableTiming);
        cudaFuncSetAttribute(k_gemm1_mma, cudaFuncAttributeMaxDynamicSharedMemorySize,
                             G1_SMEM_BYTES);
    }

    k_detect<<<1, 256>>>((const unsigned*)edge, E);

    // ---- fork: stream B = weights conv + degB + GEMM1 ----
    cudaEventRecord(evFork, 0);
    cudaStreamWaitEvent(sB, evFork, 0);

    k_convW1t<<<(NFEAT * NHID + 255) / 256, 256, 0, sB>>>(W1);
    k_convW2t<<<(NHID * NCLASS + 255) / 256, 256, 0, sB>>>(W2);
    k_degB<<<(NNODES + 255) / 256, 256, 0, sB>>>(edge, E);
    k_histB<<<(E + 255) / 256, 256, 0, sB>>>(edge, E);
    k_finB<<<(NNODES + 255) / 256, 256, 0, sB>>>();
    k_gemm1_mma<<<(NNODES + 127) / 128, 512, G1_SMEM_BYTES, sB>>>(x);
    cudaEventRecord(evB, sB);

    // ---- stream A (default): CSR chain ----
    k_zero_deg<<<(NNODES + 255) / 256, 256>>>();
    k_hist<<<(E + 255) / 256, 256>>>(edge, E);
    k_scan1<<<SCAN_NB, 256>>>();
    k_scan2<<<1, 128>>>(SCAN_NB);
    k_scan3<<<SCAN_NB, 1024>>>();
    k_scatter<<<(E + 255) / 256, 256>>>(edge, E);

    // ---- join: agg1 needs CSR (stream A) + G1 (stream B) ----
    cudaStreamWaitEvent(0, evB, 0);
    k_agg1<<<(NNODES * 32 + 255) / 256, 256>>>(b1);

    // Layer 2
    k_gemm2_mma<<<(NNODES + 127) / 128, 256>>>();
    k_agg2<<<(NNODES * 32 + 255) / 256, 256>>>(b2, out);
}

// round 11
// speedup vs baseline: 2.3518x; 1.1213x over previous
#include <cuda_runtime.h>
#include <cuda_bf16.h>
#include <cuda_fp16.h>
#include <cstdint>

#define NNODES 100000
#define NFEAT  512
#define NHID   256
#define NCLASS 40
#define NEDGE_MAX 3200000
#define SCAN_NB ((NNODES + 1023) / 1024)

// ------------- scratch (static device allocations; no runtime alloc) -------------
__device__ int   g_deg[NNODES];
__device__ int   g_off[NNODES + 1];
__device__ int   g_cur[NNODES];
__device__ int   g_csr[NEDGE_MAX];
__device__ float g_dis[NNODES];
__device__ int   g_part[SCAN_NB + 8];
__device__ int   g_is64;
__device__ __align__(16) __half g_G1h[(size_t)NNODES * NHID];  // fp16: X@W1 (UNscaled)
__device__ __align__(16) __half g_H1h[(size_t)NNODES * NHID];  // fp16: relu(agg + b1)
__device__ __align__(16) __half g_Ph[(size_t)NNODES * NCLASS]; // fp16: dis[row]*(H1@W2)
// bf16 weights (transposed [n][k]); W1 hi only, W2 split hi/lo
__device__ __align__(16) __nv_bfloat16 g_W1tH[(size_t)NHID * NFEAT];
__device__ __align__(16) __nv_bfloat16 g_W2tH[(size_t)NCLASS * NHID];
__device__ __align__(16) __nv_bfloat16 g_W2tL[(size_t)NCLASS * NHID];

// --------------------------- edge dtype detection --------------------------------
__global__ void k_detect(const unsigned* __restrict__ w, int E) {
    __shared__ int any;
    if (threadIdx.x == 0) any = 0;
    __syncthreads();
    int n = (E < 1024) ? E : 1024;
    for (int i = threadIdx.x; i < n; i += blockDim.x)
        if (w[2 * i + 1] != 0u) any = 1;
    __syncthreads();
    if (threadIdx.x == 0) g_is64 = (any == 0) ? 1 : 0;
}

__device__ __forceinline__ int edge_at(const void* edge, int idx) {
    if (g_is64) return (int)((const long long*)edge)[idx];
    return ((const int*)edge)[idx];
}

// ------------------------------- CSR construction (stream A) ----------------------
__global__ void k_zero_deg() {
    int i = blockIdx.x * blockDim.x + threadIdx.x;
    if (i < NNODES) g_deg[i] = 0;
}

__global__ void k_hist(const void* __restrict__ edge, int E) {
    int e = blockIdx.x * blockDim.x + threadIdx.x;
    if (e < E) {
        int d = edge_at(edge, E + e);
        if ((unsigned)d < (unsigned)NNODES) atomicAdd(&g_deg[d], 1);
    }
}

__global__ void k_scan1() {
    __shared__ int s[256];
    int b = blockIdx.x, t = threadIdx.x;
    int base = b * 1024;
    int sum = 0;
    #pragma unroll
    for (int i = t; i < 1024; i += 256) {
        int gi = base + i;
        sum += (gi < NNODES) ? g_deg[gi] : 0;
    }
    s[t] = sum; __syncthreads();
    for (int o = 128; o > 0; o >>= 1) {
        if (t < o) s[t] += s[t + o];
        __syncthreads();
    }
    if (t == 0) g_part[b] = s[0];
}

__global__ void k_scan2(int nb) {
    __shared__ int s[128];
    int t = threadIdx.x;
    int v = (t < nb) ? g_part[t] : 0;
    s[t] = v; __syncthreads();
    #pragma unroll
    for (int o = 1; o < 128; o <<= 1) {
        int x = (t >= o) ? s[t - o] : 0;
        __syncthreads();
        s[t] += x;
        __syncthreads();
    }
    if (t < nb) g_part[t] = s[t] - v;
}

__global__ void k_scan3() {
    __shared__ int s[1024];
    int b = blockIdx.x, t = threadIdx.x;
    int i = b * 1024 + t;
    int v = (i < NNODES) ? g_deg[i] : 0;
    s[t] = v; __syncthreads();
    for (int o = 1; o < 1024; o <<= 1) {
        int x = (t >= o) ? s[t - o] : 0;
        __syncthreads();
        s[t] += x;
        __syncthreads();
    }
    int excl = s[t] - v;
    int off = g_part[b] + excl;
    if (i < NNODES) {
        g_off[i] = off;
        g_cur[i] = off;
        g_dis[i] = rsqrtf((float)(v + 1));
        if (i == NNODES - 1) g_off[NNODES] = off + v;
    }
}

__global__ void k_scatter(const void* __restrict__ edge, int E) {
    int e = blockIdx.x * blockDim.x + threadIdx.x;
    if (e < E) {
        int s = edge_at(edge, e);
        int d = edge_at(edge, E + e);
        if ((unsigned)d < (unsigned)NNODES && (unsigned)s < (unsigned)NNODES) {
            int p = atomicAdd(&g_cur[d], 1);
            g_csr[p] = s;
        }
    }
}

// ---------------------- bf16 weight conversions ------------------------------------
__global__ void k_convW1t(const float* __restrict__ W1) {
    int idx = blockIdx.x * 256 + threadIdx.x;
    if (idx < NFEAT * NHID) {
        int k = idx >> 8;      // / NHID
        int n = idx & 255;     // % NHID
        g_W1tH[(size_t)n * NFEAT + k] = __float2bfloat16_rn(W1[idx]);
    }
}

__global__ void k_convW2t(const float* __restrict__ W2) {
    int idx = blockIdx.x * 256 + threadIdx.x;
    if (idx < NHID * NCLASS) {
        int k = idx / NCLASS;
        int n = idx - k * NCLASS;
        float v = W2[idx];
        __nv_bfloat16 h = __float2bfloat16_rn(v);
        g_W2tH[(size_t)n * NHID + k] = h;
        g_W2tL[(size_t)n * NHID + k] = __float2bfloat16_rn(v - __bfloat162float(h));
    }
}

// ---------------- GEMM1 (mma.sync bf16): G1h = fp16(X @ W1), unscaled -------------
#define G1_PAD 40   // bf16 elems per smem row (32 data + 8 pad) -> 80B stride
#define G1_SMEM_BYTES ((128 * G1_PAD + 256 * G1_PAD) * 2)

__device__ __forceinline__ void mma16816(float* c, const uint32_t* a,
                                         uint32_t b0, uint32_t b1) {
    asm volatile(
        "mma.sync.aligned.m16n8k16.row.col.f32.bf16.bf16.f32 "
        "{%0,%1,%2,%3}, {%4,%5,%6,%7}, {%8,%9}, {%0,%1,%2,%3};"
        : "+f"(c[0]), "+f"(c[1]), "+f"(c[2]), "+f"(c[3])
        : "r"(a[0]), "r"(a[1]), "r"(a[2]), "r"(a[3]), "r"(b0), "r"(b1));
}

__device__ __forceinline__ void splitpack(const float* f, __nv_bfloat162* hp,
                                          __nv_bfloat162* lp) {
    #pragma unroll
    for (int q = 0; q < 4; q++) {
        __nv_bfloat16 h0 = __float2bfloat16_rn(f[2 * q]);
        __nv_bfloat16 h1 = __float2bfloat16_rn(f[2 * q + 1]);
        hp[q] = __nv_bfloat162(h0, h1);
        lp[q] = __nv_bfloat162(
            __float2bfloat16_rn(f[2 * q] - __bfloat162float(h0)),
            __float2bfloat16_rn(f[2 * q + 1] - __bfloat162float(h1)));
    }
}

__global__ __launch_bounds__(512) void k_gemm1_mma(const float* __restrict__ X) {
    extern __shared__ __nv_bfloat16 sm[];
    __nv_bfloat16* Ah = sm;                      // [128][40]
    __nv_bfloat16* Bh = Ah + 128 * G1_PAD;       // [256][40]

    int tid = threadIdx.x;
    int wid = tid >> 5, lane = tid & 31;
    int wm = wid >> 2, wn = wid & 3;
    int mBase = wm * 32, nBase = wn * 64;
    int rowBase = blockIdx.x * 128;
    int g = lane >> 2, tg = lane & 3;

    float acc[2][8][4];
    #pragma unroll
    for (int i = 0; i < 2; i++)
        #pragma unroll
        for (int j = 0; j < 8; j++)
            #pragma unroll
            for (int r = 0; r < 4; r++) acc[i][j][r] = 0.f;

    int ar = tid >> 2, aseg = tid & 3;
    int gr = rowBase + ar; if (gr >= NNODES) gr = NNODES - 1;
    const float* gX = X + (size_t)gr * NFEAT + aseg * 8;

    float4 pv0 = *(const float4*)(gX);
    float4 pv1 = *(const float4*)(gX + 4);

    for (int kc = 0; kc < NFEAT / 32; kc++) {
        // A: convert 8 fp32 -> plain bf16
        {
            float f[8] = {pv0.x, pv0.y, pv0.z, pv0.w, pv1.x, pv1.y, pv1.z, pv1.w};
            __nv_bfloat162 hp[4];
            #pragma unroll
            for (int q = 0; q < 4; q++)
                hp[q] = __nv_bfloat162(__float2bfloat16_rn(f[2 * q]),
                                       __float2bfloat16_rn(f[2 * q + 1]));
            *(uint4*)(Ah + ar * G1_PAD + aseg * 8) = *(uint4*)hp;
        }
        // B: 256 rows x 32 k, two float4 per thread
        #pragma unroll
        for (int b = 0; b < 2; b++) {
            int i = tid + b * 512;
            int n = i >> 2, bseg = i & 3;
            size_t bo = (size_t)n * NFEAT + kc * 32 + bseg * 8;
            *(float4*)(Bh + n * G1_PAD + bseg * 8) = *(const float4*)(g_W1tH + bo);
        }
        __syncthreads();

        if (kc + 1 < NFEAT / 32) {
            pv0 = *(const float4*)(gX + (kc + 1) * 32);
            pv1 = *(const float4*)(gX + (kc + 1) * 32 + 4);
        }

        #pragma unroll
        for (int ks = 0; ks < 2; ks++) {
            int k0 = ks * 16;
            uint32_t afh[2][4];
            #pragma unroll
            for (int i = 0; i < 2; i++) {
                const __nv_bfloat16* bh = Ah + (mBase + i * 16 + g) * G1_PAD + k0;
                afh[i][0] = *(const uint32_t*)(bh + 2 * tg);
                afh[i][1] = *(const uint32_t*)(bh + 8 * G1_PAD + 2 * tg);
                afh[i][2] = *(const uint32_t*)(bh + 2 * tg + 8);
                afh[i][3] = *(const uint32_t*)(bh + 8 * G1_PAD + 2 * tg + 8);
            }
            #pragma unroll
            for (int j = 0; j < 8; j++) {
                const __nv_bfloat16* pbh = Bh + (nBase + j * 8 + g) * G1_PAD + k0;
                uint32_t bh0 = *(const uint32_t*)(pbh + 2 * tg);
                uint32_t bh1 = *(const uint32_t*)(pbh + 2 * tg + 8);
                #pragma unroll
                for (int i = 0; i < 2; i++)
                    mma16816(acc[i][j], afh[i], bh0, bh1);
            }
        }
        __syncthreads();
    }

    // epilogue: store UNscaled as fp16 (dis applied in agg1)
    #pragma unroll
    for (int i = 0; i < 2; i++) {
        int r0 = rowBase + mBase + i * 16 + g;
        int r1 = r0 + 8;
        #pragma unroll
        for (int j = 0; j < 8; j++) {
            int col = nBase + j * 8 + 2 * tg;
            if (r0 < NNODES)
                *(__half2*)(g_G1h + (size_t)r0 * NHID + col) =
                    __floats2half2_rn(acc[i][j][0], acc[i][j][1]);
            if (r1 < NNODES)
                *(__half2*)(g_G1h + (size_t)r1 * NHID + col) =
                    __floats2half2_rn(acc[i][j][2], acc[i][j][3]);
        }
    }
}

// ------- Aggregation 1: H1h = fp16(relu(dis[w]*(Σ dis[s]*G[s] + dis[w]*G[w]) + b1))
__device__ __forceinline__ void h8accs(float* a, float4 v, float s) {
    const __half2* h = (const __half2*)&v;
    #pragma unroll
    for (int q = 0; q < 4; q++) {
        float2 f = __half22float2(h[q]);
        a[2 * q + 0] = fmaf(f.x, s, a[2 * q + 0]);
        a[2 * q + 1] = fmaf(f.y, s, a[2 * q + 1]);
    }
}

__global__ __launch_bounds__(256) void k_agg1(const float* __restrict__ b1) {
    int w = (blockIdx.x * blockDim.x + threadIdx.x) >> 5;
    int lane = threadIdx.x & 31;
    if (w >= NNODES) return;
    const float4* G = (const float4*)g_G1h;   // 32 float4 per row

    float dsw = g_dis[w];
    float a[8] = {0.f, 0.f, 0.f, 0.f, 0.f, 0.f, 0.f, 0.f};
    h8accs(a, G[(size_t)w * 32 + lane], dsw);   // self (dis[w])

    int beg = g_off[w], end = g_off[w + 1];
    int j = beg;
    for (; j + 4 <= end; j += 4) {
        int s0 = g_csr[j], s1 = g_csr[j + 1], s2 = g_csr[j + 2], s3 = g_csr[j + 3];
        float d0 = g_dis[s0], d1 = g_dis[s1], d2 = g_dis[s2], d3 = g_dis[s3];
        float4 v0 = G[(size_t)s0 * 32 + lane];
        float4 v1 = G[(size_t)s1 * 32 + lane];
        float4 v2 = G[(size_t)s2 * 32 + lane];
        float4 v3 = G[(size_t)s3 * 32 + lane];
        h8accs(a, v0, d0); h8accs(a, v1, d1); h8accs(a, v2, d2); h8accs(a, v3, d3);
    }
    for (; j < end; ++j) {
        int s = g_csr[j];
        h8accs(a, G[(size_t)s * 32 + lane], g_dis[s]);
    }

    int c0 = lane << 3;
    float4 bb0 = *(const float4*)(b1 + c0);
    float4 bb1 = *(const float4*)(b1 + c0 + 4);
    __half2 o[4];
    o[0] = __floats2half2_rn(fmaxf(fmaf(a[0], dsw, bb0.x), 0.f),
                             fmaxf(fmaf(a[1], dsw, bb0.y), 0.f));
    o[1] = __floats2half2_rn(fmaxf(fmaf(a[2], dsw, bb0.z), 0.f),
                             fmaxf(fmaf(a[3], dsw, bb0.w), 0.f));
    o[2] = __floats2half2_rn(fmaxf(fmaf(a[4], dsw, bb1.x), 0.f),
                             fmaxf(fmaf(a[5], dsw, bb1.y), 0.f));
    o[3] = __floats2half2_rn(fmaxf(fmaf(a[6], dsw, bb1.z), 0.f),
                             fmaxf(fmaf(a[7], dsw, bb1.w), 0.f));
    *(uint4*)(g_H1h + (size_t)w * NHID + c0) = *(uint4*)o;
}

// ------------- GEMM2 (mma.sync bf16 split): Ph = fp16(dis * (H1 @ W2)) -----------
__global__ __launch_bounds__(256) void k_gemm2_mma() {
    int tid = threadIdx.x;
    int wid = tid >> 5, lane = tid & 31;
    int g = lane >> 2, tg = lane & 3;
    int wBase = blockIdx.x * 128 + wid * 16;

    int r0 = wBase + g, r1 = r0 + 8;
    int cr0 = (r0 < NNODES) ? r0 : NNODES - 1;
    int cr1 = (r1 < NNODES) ? r1 : NNODES - 1;
    const __half* A0 = g_H1h + (size_t)cr0 * NHID;
    const __half* A1 = g_H1h + (size_t)cr1 * NHID;

    float acc[5][4];
    #pragma unroll
    for (int n = 0; n < 5; n++)
        #pragma unroll
        for (int r = 0; r < 4; r++) acc[n][r] = 0.f;

    for (int kc = 0; kc < NHID / 16; kc++) {
        int kk = kc * 16 + tg * 2;
        float2 t0 = __half22float2(*(const __half2*)(A0 + kk));
        float2 t1 = __half22float2(*(const __half2*)(A1 + kk));
        float2 t2 = __half22float2(*(const __half2*)(A0 + kk + 8));
        float2 t3 = __half22float2(*(const __half2*)(A1 + kk + 8));
        float f[8] = {t0.x, t0.y, t1.x, t1.y, t2.x, t2.y, t3.x, t3.y};
        __nv_bfloat162 hp[4], lp[4];
        splitpack(f, hp, lp);
        uint32_t ah[4] = {*(uint32_t*)&hp[0], *(uint32_t*)&hp[1],
                          *(uint32_t*)&hp[2], *(uint32_t*)&hp[3]};
        uint32_t al[4] = {*(uint32_t*)&lp[0], *(uint32_t*)&lp[1],
                          *(uint32_t*)&lp[2], *(uint32_t*)&lp[3]};
        #pragma unroll
        for (int nt = 0; nt < 5; nt++) {
            const __nv_bfloat16* bh = g_W2tH + (size_t)(nt * 8 + g) * NHID + kc * 16;
            const __nv_bfloat16* bl = g_W2tL + (size_t)(nt * 8 + g) * NHID + kc * 16;
            uint32_t bh0 = *(const uint32_t*)(bh + 2 * tg);
            uint32_t bh1 = *(const uint32_t*)(bh + 2 * tg + 8);
            uint32_t bl0 = *(const uint32_t*)(bl + 2 * tg);
            uint32_t bl1 = *(const uint32_t*)(bl + 2 * tg + 8);
            mma16816(acc[nt], ah, bh0, bh1);
            mma16816(acc[nt], ah, bl0, bl1);
            mma16816(acc[nt], al, bh0, bh1);
        }
    }

    float d0 = (r0 < NNODES) ? g_dis[r0] : 0.f;
    float d1 = (r1 < NNODES) ? g_dis[r1] : 0.f;
    #pragma unroll
    for (int nt = 0; nt < 5; nt++) {
        int col = nt * 8 + 2 * tg;
        if (r0 < NNODES)
            *(__half2*)(g_Ph + (size_t)r0 * NCLASS + col) =
                __floats2half2_rn(acc[nt][0] * d0, acc[nt][1] * d0);
        if (r1 < NNODES)
            *(__half2*)(g_Ph + (size_t)r1 * NCLASS + col) =
                __floats2half2_rn(acc[nt][2] * d1, acc[nt][3] * d1);
    }
}

// ----------- Aggregation 2 + bias + log_softmax, fused, warp per node ------------
__global__ __launch_bounds__(256) void k_agg2(const float* __restrict__ b2,
                                              float* __restrict__ out) {
    int w = (blockIdx.x * blockDim.x + threadIdx.x) >> 5;
    int lane = threadIdx.x & 31;
    if (w >= NNODES) return;
    const uint2* Pv = (const uint2*)g_Ph;   // 10 uint2 per row
    bool act = lane < 10;
    int li = act ? lane : 0;

    float a0 = 0.f, a1 = 0.f, a2 = 0.f, a3 = 0.f;
    if (act) {
        uint2 v = Pv[(size_t)w * 10 + li];
        float2 x = __half22float2(*(__half2*)&v.x);
        float2 y = __half22float2(*(__half2*)&v.y);
        a0 = x.x; a1 = x.y; a2 = y.x; a3 = y.y;
    }

    int beg = g_off[w], end = g_off[w + 1];
    int j = beg;
    for (; j + 4 <= end; j += 4) {
        int s0 = g_csr[j], s1 = g_csr[j + 1], s2 = g_csr[j + 2], s3 = g_csr[j + 3];
        if (act) {
            uint2 u0 = Pv[(size_t)s0 * 10 + li];
            uint2 u1 = Pv[(size_t)s1 * 10 + li];
            uint2 u2 = Pv[(size_t)s2 * 10 + li];
            uint2 u3 = Pv[(size_t)s3 * 10 + li];
            #pragma unroll
            for (int q = 0; q < 4; q++) {
                uint2 u = (q == 0) ? u0 : (q == 1) ? u1 : (q == 2) ? u2 : u3;
                float2 x = __half22float2(*(__half2*)&u.x);
                float2 y = __half22float2(*(__half2*)&u.y);
                a0 += x.x; a1 += x.y; a2 += y.x; a3 += y.y;
            }
        }
    }
    for (; j < end; ++j) {
        if (act) {
            uint2 u = Pv[(size_t)g_csr[j] * 10 + li];
            float2 x = __half22float2(*(__half2*)&u.x);
            float2 y = __half22float2(*(__half2*)&u.y);
            a0 += x.x; a1 += x.y; a2 += y.x; a3 += y.y;
        }
    }

    float d = g_dis[w];
    float v0 = -1e30f, v1 = -1e30f, v2 = -1e30f, v3 = -1e30f;
    if (act) {
        float4 bb = *(const float4*)(b2 + li * 4);
        v0 = fmaf(a0, d, bb.x);
        v1 = fmaf(a1, d, bb.y);
        v2 = fmaf(a2, d, bb.z);
        v3 = fmaf(a3, d, bb.w);
    }
    float m = fmaxf(fmaxf(v0, v1), fmaxf(v2, v3));
    #pragma unroll
    for (int o = 16; o > 0; o >>= 1) m = fmaxf(m, __shfl_xor_sync(0xFFFFFFFFu, m, o));
    float e = act ? (expf(v0 - m) + expf(v1 - m) + expf(v2 - m) + expf(v3 - m)) : 0.f;
    #pragma unroll
    for (int o = 16; o > 0; o >>= 1) e += __shfl_xor_sync(0xFFFFFFFFu, e, o);
    float lz = m + logf(e);

    if (act) {
        float4 o4 = make_float4(v0 - lz, v1 - lz, v2 - lz, v3 - lz);
        *(float4*)(out + (size_t)w * NCLASS + li * 4) = o4;
    }
}

// ---------------------------------- launcher -------------------------------------
extern "C" void kernel_launch(void* const* d_in, const int* in_sizes, int n_in,
                              void* d_out, int out_size) {
    const float* x = nullptr;
    const float* W1 = nullptr;
    const float* b1 = nullptr;
    const float* W2 = nullptr;
    const float* b2 = nullptr;
    const void* edge = nullptr;
    int edgeElems = 0;
    for (int i = 0; i < n_in; i++) {
        int s = in_sizes[i];
        if      (s == 51200000) x  = (const float*)d_in[i];
        else if (s == 131072)   W1 = (const float*)d_in[i];
        else if (s == 256)      b1 = (const float*)d_in[i];
        else if (s == 10240)    W2 = (const float*)d_in[i];
        else if (s == 40)       b2 = (const float*)d_in[i];
        else if (s == 6400000) { edge = d_in[i]; edgeElems = s; }
    }
    if (!x || !W1 || !b1 || !W2 || !b2 || !edge) {
        x  = (const float*)d_in[0];
        W1 = (const float*)d_in[1];
        b1 = (const float*)d_in[2];
        W2 = (const float*)d_in[3];
        b2 = (const float*)d_in[4];
        edge = d_in[5];
        edgeElems = in_sizes[5];
    }
    float* out = (float*)d_out;

    int E = edgeElems / 2;
    if (E > NEDGE_MAX) E = NEDGE_MAX;

    static cudaStream_t sB = nullptr;
    static cudaEvent_t evFork = nullptr, evB = nullptr;
    if (!sB) {
        cudaStreamCreateWithFlags(&sB, cudaStreamNonBlocking);
        cudaEventCreateWithFlags(&evFork, cudaEventDisableTiming);
        cudaEventCreateWithFlags(&evB, cudaEventDisableTiming);
        cudaFuncSetAttribute(k_gemm1_mma, cudaFuncAttributeMaxDynamicSharedMemorySize,
                             G1_SMEM_BYTES);
    }

    k_detect<<<1, 256>>>((const unsigned*)edge, E);

    // ---- fork: stream B = weight conversion + GEMM1 (no dis needed) ----
    cudaEventRecord(evFork, 0);
    cudaStreamWaitEvent(sB, evFork, 0);

    k_convW1t<<<(NFEAT * NHID + 255) / 256, 256, 0, sB>>>(W1);
    k_convW2t<<<(NHID * NCLASS + 255) / 256, 256, 0, sB>>>(W2);
    k_gemm1_mma<<<(NNODES + 127) / 128, 512, G1_SMEM_BYTES, sB>>>(x);
    cudaEventRecord(evB, sB);

    // ---- stream A (default): CSR chain ----
    k_zero_deg<<<(NNODES + 255) / 256, 256>>>();
    k_hist<<<(E + 255) / 256, 256>>>(edge, E);
    k_scan1<<<SCAN_NB, 256>>>();
    k_scan2<<<1, 128>>>(SCAN_NB);
    k_scan3<<<SCAN_NB, 1024>>>();
    k_scatter<<<(E + 255) / 256, 256>>>(edge, E);

    // ---- join: agg1 needs CSR+dis (stream A) + G1 (stream B) ----
    cudaStreamWaitEvent(0, evB, 0);
    k_agg1<<<(NNODES * 32 + 255) / 256, 256>>>(b1);

    // Layer 2
    k_gemm2_mma<<<(NNODES + 127) / 128, 256>>>();
    k_agg2<<<(NNODES * 32 + 255) / 256, 256>>>(b2, out);
}

// round 12
// speedup vs baseline: 2.4035x; 1.0219x over previous
#include <cuda_runtime.h>
#include <cuda_bf16.h>
#include <cuda_fp16.h>
#include <cstdint>

#define NNODES 100000
#define NFEAT  512
#define NHID   256
#define NCLASS 40
#define NEDGE_MAX 3200000
#define SCAN_NB ((NNODES + 1023) / 1024)

// ------------- scratch (static device allocations; no runtime alloc) -------------
__device__ int   g_deg[NNODES];
__device__ int   g_off[NNODES + 1];
__device__ int   g_cur[NNODES];
__device__ int   g_csr[NEDGE_MAX];
__device__ float g_dis[NNODES];
__device__ int   g_part[SCAN_NB + 8];
__device__ int   g_is64;
__device__ __align__(16) __half g_G1h[(size_t)NNODES * NHID];  // fp16: X@W1 (UNscaled)
__device__ __align__(16) __half g_H1h[(size_t)NNODES * NHID];  // fp16: relu(agg + b1)
__device__ __align__(16) __half g_Ph[(size_t)NNODES * NCLASS]; // fp16: dis[row]*(H1@W2)
// bf16 weights (transposed [n][k]); W1 hi only, W2 split hi/lo
__device__ __align__(16) __nv_bfloat16 g_W1tH[(size_t)NHID * NFEAT];
__device__ __align__(16) __nv_bfloat16 g_W2tH[(size_t)NCLASS * NHID];
__device__ __align__(16) __nv_bfloat16 g_W2tL[(size_t)NCLASS * NHID];

// --------------------------- edge dtype detection --------------------------------
__global__ void k_detect(const unsigned* __restrict__ w, int E) {
    __shared__ int any;
    if (threadIdx.x == 0) any = 0;
    __syncthreads();
    int n = (E < 1024) ? E : 1024;
    for (int i = threadIdx.x; i < n; i += blockDim.x)
        if (w[2 * i + 1] != 0u) any = 1;
    __syncthreads();
    if (threadIdx.x == 0) g_is64 = (any == 0) ? 1 : 0;
}

__device__ __forceinline__ int edge_at(const void* edge, int idx) {
    if (g_is64) return (int)((const long long*)edge)[idx];
    return ((const int*)edge)[idx];
}

// ------------------------------- CSR construction (stream A) ----------------------
__global__ void k_zero_deg() {
    int i = blockIdx.x * blockDim.x + threadIdx.x;
    if (i < NNODES) g_deg[i] = 0;
}

__global__ void k_hist(const void* __restrict__ edge, int E) {
    int e = blockIdx.x * blockDim.x + threadIdx.x;
    if (e < E) {
        int d = edge_at(edge, E + e);
        if ((unsigned)d < (unsigned)NNODES) atomicAdd(&g_deg[d], 1);
    }
}

__global__ void k_scan1() {
    __shared__ int s[256];
    int b = blockIdx.x, t = threadIdx.x;
    int base = b * 1024;
    int sum = 0;
    #pragma unroll
    for (int i = t; i < 1024; i += 256) {
        int gi = base + i;
        sum += (gi < NNODES) ? g_deg[gi] : 0;
    }
    s[t] = sum; __syncthreads();
    for (int o = 128; o > 0; o >>= 1) {
        if (t < o) s[t] += s[t + o];
        __syncthreads();
    }
    if (t == 0) g_part[b] = s[0];
}

__global__ void k_scan2(int nb) {
    __shared__ int s[128];
    int t = threadIdx.x;
    int v = (t < nb) ? g_part[t] : 0;
    s[t] = v; __syncthreads();
    #pragma unroll
    for (int o = 1; o < 128; o <<= 1) {
        int x = (t >= o) ? s[t - o] : 0;
        __syncthreads();
        s[t] += x;
        __syncthreads();
    }
    if (t < nb) g_part[t] = s[t] - v;
}

__global__ void k_scan3() {
    __shared__ int s[1024];
    int b = blockIdx.x, t = threadIdx.x;
    int i = b * 1024 + t;
    int v = (i < NNODES) ? g_deg[i] : 0;
    s[t] = v; __syncthreads();
    for (int o = 1; o < 1024; o <<= 1) {
        int x = (t >= o) ? s[t - o] : 0;
        __syncthreads();
        s[t] += x;
        __syncthreads();
    }
    int excl = s[t] - v;
    int off = g_part[b] + excl;
    if (i < NNODES) {
        g_off[i] = off;
        g_cur[i] = off;
        g_dis[i] = rsqrtf((float)(v + 1));
        if (i == NNODES - 1) g_off[NNODES] = off + v;
    }
}

__global__ void k_scatter(const void* __restrict__ edge, int E) {
    int e = blockIdx.x * blockDim.x + threadIdx.x;
    if (e < E) {
        int s = edge_at(edge, e);
        int d = edge_at(edge, E + e);
        if ((unsigned)d < (unsigned)NNODES && (unsigned)s < (unsigned)NNODES) {
            int p = atomicAdd(&g_cur[d], 1);
            g_csr[p] = s;
        }
    }
}

// ---------------------- bf16 weight conversions ------------------------------------
__global__ void k_convW1t(const float* __restrict__ W1) {
    int idx = blockIdx.x * 256 + threadIdx.x;
    if (idx < NFEAT * NHID) {
        int k = idx >> 8;      // / NHID
        int n = idx & 255;     // % NHID
        g_W1tH[(size_t)n * NFEAT + k] = __float2bfloat16_rn(W1[idx]);
    }
}

__global__ void k_convW2t(const float* __restrict__ W2) {
    int idx = blockIdx.x * 256 + threadIdx.x;
    if (idx < NHID * NCLASS) {
        int k = idx / NCLASS;
        int n = idx - k * NCLASS;
        float v = W2[idx];
        __nv_bfloat16 h = __float2bfloat16_rn(v);
        g_W2tH[(size_t)n * NHID + k] = h;
        g_W2tL[(size_t)n * NHID + k] = __float2bfloat16_rn(v - __bfloat162float(h));
    }
}

// ---------------- GEMM1 (mma.sync bf16 + ldmatrix): G1h = fp16(X @ W1) ------------
#define G1_PAD 40   // bf16 elems per smem row (32 data + 8 pad) -> 80B stride
#define G1_SMEM_BYTES ((128 * G1_PAD + 256 * G1_PAD) * 2)

__device__ __forceinline__ uint32_t smem_u32(const void* p) {
    return (uint32_t)__cvta_generic_to_shared(p);
}

__device__ __forceinline__ void ldm_x4(uint32_t* r, uint32_t addr) {
    asm volatile("ldmatrix.sync.aligned.m8n8.x4.shared.b16 {%0,%1,%2,%3}, [%4];"
                 : "=r"(r[0]), "=r"(r[1]), "=r"(r[2]), "=r"(r[3]) : "r"(addr));
}

__device__ __forceinline__ void mma16816(float* c, const uint32_t* a,
                                         uint32_t b0, uint32_t b1) {
    asm volatile(
        "mma.sync.aligned.m16n8k16.row.col.f32.bf16.bf16.f32 "
        "{%0,%1,%2,%3}, {%4,%5,%6,%7}, {%8,%9}, {%0,%1,%2,%3};"
        : "+f"(c[0]), "+f"(c[1]), "+f"(c[2]), "+f"(c[3])
        : "r"(a[0]), "r"(a[1]), "r"(a[2]), "r"(a[3]), "r"(b0), "r"(b1));
}

__device__ __forceinline__ void splitpack(const float* f, __nv_bfloat162* hp,
                                          __nv_bfloat162* lp) {
    #pragma unroll
    for (int q = 0; q < 4; q++) {
        __nv_bfloat16 h0 = __float2bfloat16_rn(f[2 * q]);
        __nv_bfloat16 h1 = __float2bfloat16_rn(f[2 * q + 1]);
        hp[q] = __nv_bfloat162(h0, h1);
        lp[q] = __nv_bfloat162(
            __float2bfloat16_rn(f[2 * q] - __bfloat162float(h0)),
            __float2bfloat16_rn(f[2 * q + 1] - __bfloat162float(h1)));
    }
}

__global__ __launch_bounds__(512) void k_gemm1_mma(const float* __restrict__ X) {
    extern __shared__ __nv_bfloat16 sm[];
    __nv_bfloat16* Ah = sm;                      // [128][40]
    __nv_bfloat16* Bh = Ah + 128 * G1_PAD;       // [256][40]

    int tid = threadIdx.x;
    int wid = tid >> 5, lane = tid & 31;
    int wm = wid >> 2, wn = wid & 3;
    int mBase = wm * 32, nBase = wn * 64;
    int rowBase = blockIdx.x * 128;
    int g = lane >> 2, tg = lane & 3;

    float acc[2][8][4];
    #pragma unroll
    for (int i = 0; i < 2; i++)
        #pragma unroll
        for (int j = 0; j < 8; j++)
            #pragma unroll
            for (int r = 0; r < 4; r++) acc[i][j][r] = 0.f;

    // ldmatrix lane addressing
    int lr = lane & 7, grp = lane >> 3;
    uint32_t aSm = smem_u32(Ah), bSm = smem_u32(Bh);
    // A m16k16 tile: groups {m0-7,k0-7},{m8-15,k0-7},{m0-7,k8-15},{m8-15,k8-15}
    uint32_t aAddr0 = aSm + (uint32_t)(((mBase + lr + (grp & 1) * 8) * G1_PAD
                                        + (grp >> 1) * 8) * 2);
    uint32_t aAddr1 = aAddr0 + 16 * G1_PAD * 2;
    // B pair of n8k16 tiles (j2): groups {n0-7,k0-7},{n0-7,k8-15},{n8-15,k0-7},{n8-15,k8-15}
    uint32_t bAddr[4];
    #pragma unroll
    for (int j2 = 0; j2 < 4; j2++)
        bAddr[j2] = bSm + (uint32_t)(((nBase + j2 * 16 + (grp >> 1) * 8 + lr) * G1_PAD
                                      + (grp & 1) * 8) * 2);

    int ar = tid >> 2, aseg = tid & 3;
    int gr = rowBase + ar; if (gr >= NNODES) gr = NNODES - 1;
    const float* gX = X + (size_t)gr * NFEAT + aseg * 8;

    float4 pv0 = *(const float4*)(gX);
    float4 pv1 = *(const float4*)(gX + 4);

    for (int kc = 0; kc < NFEAT / 32; kc++) {
        // A: convert 8 fp32 -> plain bf16
        {
            float f[8] = {pv0.x, pv0.y, pv0.z, pv0.w, pv1.x, pv1.y, pv1.z, pv1.w};
            __nv_bfloat162 hp[4];
            #pragma unroll
            for (int q = 0; q < 4; q++)
                hp[q] = __nv_bfloat162(__float2bfloat16_rn(f[2 * q]),
                                       __float2bfloat16_rn(f[2 * q + 1]));
            *(uint4*)(Ah + ar * G1_PAD + aseg * 8) = *(uint4*)hp;
        }
        // B: 256 rows x 32 k, two float4 per thread
        #pragma unroll
        for (int b = 0; b < 2; b++) {
            int i = tid + b * 512;
            int n = i >> 2, bseg = i & 3;
            size_t bo = (size_t)n * NFEAT + kc * 32 + bseg * 8;
            *(float4*)(Bh + n * G1_PAD + bseg * 8) = *(const float4*)(g_W1tH + bo);
        }
        __syncthreads();

        if (kc + 1 < NFEAT / 32) {
            pv0 = *(const float4*)(gX + (kc + 1) * 32);
            pv1 = *(const float4*)(gX + (kc + 1) * 32 + 4);
        }

        #pragma unroll
        for (int ks = 0; ks < 2; ks++) {
            uint32_t koff = ks * 32;   // 16 bf16 = 32 bytes
            uint32_t af0[4], af1[4];
            ldm_x4(af0, aAddr0 + koff);
            ldm_x4(af1, aAddr1 + koff);
            #pragma unroll
            for (int j2 = 0; j2 < 4; j2++) {
                uint32_t bb[4];
                ldm_x4(bb, bAddr[j2] + koff);
                mma16816(acc[0][2 * j2 + 0], af0, bb[0], bb[1]);
                mma16816(acc[1][2 * j2 + 0], af1, bb[0], bb[1]);
                mma16816(acc[0][2 * j2 + 1], af0, bb[2], bb[3]);
                mma16816(acc[1][2 * j2 + 1], af1, bb[2], bb[3]);
            }
        }
        __syncthreads();
    }

    // epilogue: store UNscaled as fp16 (dis applied in agg1)
    #pragma unroll
    for (int i = 0; i < 2; i++) {
        int r0 = rowBase + mBase + i * 16 + g;
        int r1 = r0 + 8;
        #pragma unroll
        for (int j = 0; j < 8; j++) {
            int col = nBase + j * 8 + 2 * tg;
            if (r0 < NNODES)
                *(__half2*)(g_G1h + (size_t)r0 * NHID + col) =
                    __floats2half2_rn(acc[i][j][0], acc[i][j][1]);
            if (r1 < NNODES)
                *(__half2*)(g_G1h + (size_t)r1 * NHID + col) =
                    __floats2half2_rn(acc[i][j][2], acc[i][j][3]);
        }
    }
}

// ------- Aggregation 1: H1h = fp16(relu(dis[w]*(Σ dis[s]*G[s] + dis[w]*G[w]) + b1))
__device__ __forceinline__ void h8accs(float* a, float4 v, float s) {
    const __half2* h = (const __half2*)&v;
    #pragma unroll
    for (int q = 0; q < 4; q++) {
        float2 f = __half22float2(h[q]);
        a[2 * q + 0] = fmaf(f.x, s, a[2 * q + 0]);
        a[2 * q + 1] = fmaf(f.y, s, a[2 * q + 1]);
    }
}

__global__ __launch_bounds__(256) void k_agg1(const float* __restrict__ b1) {
    int w = (blockIdx.x * blockDim.x + threadIdx.x) >> 5;
    int lane = threadIdx.x & 31;
    if (w >= NNODES) return;
    const float4* G = (const float4*)g_G1h;   // 32 float4 per row

    float dsw = g_dis[w];
    float a[8] = {0.f, 0.f, 0.f, 0.f, 0.f, 0.f, 0.f, 0.f};
    h8accs(a, G[(size_t)w * 32 + lane], dsw);   // self (dis[w])

    int beg = g_off[w], end = g_off[w + 1];
    int j = beg;
    for (; j + 4 <= end; j += 4) {
        int s0 = g_csr[j], s1 = g_csr[j + 1], s2 = g_csr[j + 2], s3 = g_csr[j + 3];
        float d0 = g_dis[s0], d1 = g_dis[s1], d2 = g_dis[s2], d3 = g_dis[s3];
        float4 v0 = G[(size_t)s0 * 32 + lane];
        float4 v1 = G[(size_t)s1 * 32 + lane];
        float4 v2 = G[(size_t)s2 * 32 + lane];
        float4 v3 = G[(size_t)s3 * 32 + lane];
        h8accs(a, v0, d0); h8accs(a, v1, d1); h8accs(a, v2, d2); h8accs(a, v3, d3);
    }
    for (; j < end; ++j) {
        int s = g_csr[j];
        h8accs(a, G[(size_t)s * 32 + lane], g_dis[s]);
    }

    int c0 = lane << 3;
    float4 bb0 = *(const float4*)(b1 + c0);
    float4 bb1 = *(const float4*)(b1 + c0 + 4);
    __half2 o[4];
    o[0] = __floats2half2_rn(fmaxf(fmaf(a[0], dsw, bb0.x), 0.f),
                             fmaxf(fmaf(a[1], dsw, bb0.y), 0.f));
    o[1] = __floats2half2_rn(fmaxf(fmaf(a[2], dsw, bb0.z), 0.f),
                             fmaxf(fmaf(a[3], dsw, bb0.w), 0.f));
    o[2] = __floats2half2_rn(fmaxf(fmaf(a[4], dsw, bb1.x), 0.f),
                             fmaxf(fmaf(a[5], dsw, bb1.y), 0.f));
    o[3] = __floats2half2_rn(fmaxf(fmaf(a[6], dsw, bb1.z), 0.f),
                             fmaxf(fmaf(a[7], dsw, bb1.w), 0.f));
    *(uint4*)(g_H1h + (size_t)w * NHID + c0) = *(uint4*)o;
}

// ------------- GEMM2 (mma.sync bf16 split): Ph = fp16(dis * (H1 @ W2)) -----------
__global__ __launch_bounds__(256) void k_gemm2_mma() {
    int tid = threadIdx.x;
    int wid = tid >> 5, lane = tid & 31;
    int g = lane >> 2, tg = lane & 3;
    int wBase = blockIdx.x * 128 + wid * 16;

    int r0 = wBase + g, r1 = r0 + 8;
    int cr0 = (r0 < NNODES) ? r0 : NNODES - 1;
    int cr1 = (r1 < NNODES) ? r1 : NNODES - 1;
    const __half* A0 = g_H1h + (size_t)cr0 * NHID;
    const __half* A1 = g_H1h + (size_t)cr1 * NHID;

    float acc[5][4];
    #pragma unroll
    for (int n = 0; n < 5; n++)
        #pragma unroll
        for (int r = 0; r < 4; r++) acc[n][r] = 0.f;

    for (int kc = 0; kc < NHID / 16; kc++) {
        int kk = kc * 16 + tg * 2;
        float2 t0 = __half22float2(*(const __half2*)(A0 + kk));
        float2 t1 = __half22float2(*(const __half2*)(A1 + kk));
        float2 t2 = __half22float2(*(const __half2*)(A0 + kk + 8));
        float2 t3 = __half22float2(*(const __half2*)(A1 + kk + 8));
        float f[8] = {t0.x, t0.y, t1.x, t1.y, t2.x, t2.y, t3.x, t3.y};
        __nv_bfloat162 hp[4], lp[4];
        splitpack(f, hp, lp);
        uint32_t ah[4] = {*(uint32_t*)&hp[0], *(uint32_t*)&hp[1],
                          *(uint32_t*)&hp[2], *(uint32_t*)&hp[3]};
        uint32_t al[4] = {*(uint32_t*)&lp[0], *(uint32_t*)&lp[1],
                          *(uint32_t*)&lp[2], *(uint32_t*)&lp[3]};
        #pragma unroll
        for (int nt = 0; nt < 5; nt++) {
            const __nv_bfloat16* bh = g_W2tH + (size_t)(nt * 8 + g) * NHID + kc * 16;
            const __nv_bfloat16* bl = g_W2tL + (size_t)(nt * 8 + g) * NHID + kc * 16;
            uint32_t bh0 = *(const uint32_t*)(bh + 2 * tg);
            uint32_t bh1 = *(const uint32_t*)(bh + 2 * tg + 8);
            uint32_t bl0 = *(const uint32_t*)(bl + 2 * tg);
            uint32_t bl1 = *(const uint32_t*)(bl + 2 * tg + 8);
            mma16816(acc[nt], ah, bh0, bh1);
            mma16816(acc[nt], ah, bl0, bl1);
            mma16816(acc[nt], al, bh0, bh1);
        }
    }

    float d0 = (r0 < NNODES) ? g_dis[r0] : 0.f;
    float d1 = (r1 < NNODES) ? g_dis[r1] : 0.f;
    #pragma unroll
    for (int nt = 0; nt < 5; nt++) {
        int col = nt * 8 + 2 * tg;
        if (r0 < NNODES)
            *(__half2*)(g_Ph + (size_t)r0 * NCLASS + col) =
                __floats2half2_rn(acc[nt][0] * d0, acc[nt][1] * d0);
        if (r1 < NNODES)
            *(__half2*)(g_Ph + (size_t)r1 * NCLASS + col) =
                __floats2half2_rn(acc[nt][2] * d1, acc[nt][3] * d1);
    }
}

// ----------- Aggregation 2 + bias + log_softmax, fused, warp per node ------------
__global__ __launch_bounds__(256) void k_agg2(const float* __restrict__ b2,
                                              float* __restrict__ out) {
    int w = (blockIdx.x * blockDim.x + threadIdx.x) >> 5;
    int lane = threadIdx.x & 31;
    if (w >= NNODES) return;
    const uint2* Pv = (const uint2*)g_Ph;   // 10 uint2 per row
    bool act = lane < 10;
    int li = act ? lane : 0;

    float a0 = 0.f, a1 = 0.f, a2 = 0.f, a3 = 0.f;
    if (act) {
        uint2 v = Pv[(size_t)w * 10 + li];
        float2 x = __half22float2(*(__half2*)&v.x);
        float2 y = __half22float2(*(__half2*)&v.y);
        a0 = x.x; a1 = x.y; a2 = y.x; a3 = y.y;
    }

    int beg = g_off[w], end = g_off[w + 1];
    int j = beg;
    for (; j + 4 <= end; j += 4) {
        int s0 = g_csr[j], s1 = g_csr[j + 1], s2 = g_csr[j + 2], s3 = g_csr[j + 3];
        if (act) {
            uint2 u0 = Pv[(size_t)s0 * 10 + li];
            uint2 u1 = Pv[(size_t)s1 * 10 + li];
            uint2 u2 = Pv[(size_t)s2 * 10 + li];
            uint2 u3 = Pv[(size_t)s3 * 10 + li];
            #pragma unroll
            for (int q = 0; q < 4; q++) {
                uint2 u = (q == 0) ? u0 : (q == 1) ? u1 : (q == 2) ? u2 : u3;
                float2 x = __half22float2(*(__half2*)&u.x);
                float2 y = __half22float2(*(__half2*)&u.y);
                a0 += x.x; a1 += x.y; a2 += y.x; a3 += y.y;
            }
        }
    }
    for (; j < end; ++j) {
        if (act) {
            uint2 u = Pv[(size_t)g_csr[j] * 10 + li];
            float2 x = __half22float2(*(__half2*)&u.x);
            float2 y = __half22float2(*(__half2*)&u.y);
            a0 += x.x; a1 += x.y; a2 += y.x; a3 += y.y;
        }
    }

    float d = g_dis[w];
    float v0 = -1e30f, v1 = -1e30f, v2 = -1e30f, v3 = -1e30f;
    if (act) {
        float4 bb = *(const float4*)(b2 + li * 4);
        v0 = fmaf(a0, d, bb.x);
        v1 = fmaf(a1, d, bb.y);
        v2 = fmaf(a2, d, bb.z);
        v3 = fmaf(a3, d, bb.w);
    }
    float m = fmaxf(fmaxf(v0, v1), fmaxf(v2, v3));
    #pragma unroll
    for (int o = 16; o > 0; o >>= 1) m = fmaxf(m, __shfl_xor_sync(0xFFFFFFFFu, m, o));
    float e = act ? (expf(v0 - m) + expf(v1 - m) + expf(v2 - m) + expf(v3 - m)) : 0.f;
    #pragma unroll
    for (int o = 16; o > 0; o >>= 1) e += __shfl_xor_sync(0xFFFFFFFFu, e, o);
    float lz = m + logf(e);

    if (act) {
        float4 o4 = make_float4(v0 - lz, v1 - lz, v2 - lz, v3 - lz);
        *(float4*)(out + (size_t)w * NCLASS + li * 4) = o4;
    }
}

// ---------------------------------- launcher -------------------------------------
extern "C" void kernel_launch(void* const* d_in, const int* in_sizes, int n_in,
                              void* d_out, int out_size) {
    const float* x = nullptr;
    const float* W1 = nullptr;
    const float* b1 = nullptr;
    const float* W2 = nullptr;
    const float* b2 = nullptr;
    const void* edge = nullptr;
    int edgeElems = 0;
    for (int i = 0; i < n_in; i++) {
        int s = in_sizes[i];
        if      (s == 51200000) x  = (const float*)d_in[i];
        else if (s == 131072)   W1 = (const float*)d_in[i];
        else if (s == 256)      b1 = (const float*)d_in[i];
        else if (s == 10240)    W2 = (const float*)d_in[i];
        else if (s == 40)       b2 = (const float*)d_in[i];
        else if (s == 6400000) { edge = d_in[i]; edgeElems = s; }
    }
    if (!x || !W1 || !b1 || !W2 || !b2 || !edge) {
        x  = (const float*)d_in[0];
        W1 = (const float*)d_in[1];
        b1 = (const float*)d_in[2];
        W2 = (const float*)d_in[3];
        b2 = (const float*)d_in[4];
        edge = d_in[5];
        edgeElems = in_sizes[5];
    }
    float* out = (float*)d_out;

    int E = edgeElems / 2;
    if (E > NEDGE_MAX) E = NEDGE_MAX;

    static cudaStream_t sB = nullptr;
    static cudaEvent_t evFork = nullptr, evB = nullptr;
    if (!sB) {
        cudaStreamCreateWithFlags(&sB, cudaStreamNonBlocking);
        cudaEventCreateWithFlags(&evFork, cudaEventDisableTiming);
        cudaEventCreateWithFlags(&evB, cudaEventDisableTiming);
        cudaFuncSetAttribute(k_gemm1_mma, cudaFuncAttributeMaxDynamicSharedMemorySize,
                             G1_SMEM_BYTES);
    }

    k_detect<<<1, 256>>>((const unsigned*)edge, E);

    // ---- fork: stream B = weight conversion + GEMM1 ----
    cudaEventRecord(evFork, 0);
    cudaStreamWaitEvent(sB, evFork, 0);

    k_convW1t<<<(NFEAT * NHID + 255) / 256, 256, 0, sB>>>(W1);
    k_convW2t<<<(NHID * NCLASS + 255) / 256, 256, 0, sB>>>(W2);
    k_gemm1_mma<<<(NNODES + 127) / 128, 512, G1_SMEM_BYTES, sB>>>(x);
    cudaEventRecord(evB, sB);

    // ---- stream A (default): CSR chain ----
    k_zero_deg<<<(NNODES + 255) / 256, 256>>>();
    k_hist<<<(E + 255) / 256, 256>>>(edge, E);
    k_scan1<<<SCAN_NB, 256>>>();
    k_scan2<<<1, 128>>>(SCAN_NB);
    k_scan3<<<SCAN_NB, 1024>>>();
    k_scatter<<<(E + 255) / 256, 256>>>(edge, E);

    // ---- join: agg1 needs CSR+dis (stream A) + G1 (stream B) ----
    cudaStreamWaitEvent(0, evB, 0);
    k_agg1<<<(NNODES * 32 + 255) / 256, 256>>>(b1);

    // Layer 2
    k_gemm2_mma<<<(NNODES + 127) / 128, 256>>>();
    k_agg2<<<(NNODES * 32 + 255) / 256, 256>>>(b2, out);
}